// round 1
// baseline (speedup 1.0000x reference)
#include <cuda_runtime.h>
#include <math.h>

#define NN   50000
#define EE   400000
#define ET   (EE + NN)
#define F    256
#define HH   4
#define CC   64
#define GG   64
#define NCLS 10

// ---------------- scratch (static device globals; no allocations) -----------
__device__ float    g_h[NN * F];        // GEMM output h = x @ W
__device__ float    g_out[NN * F];      // attention aggregation accumulator
__device__ float    g_y1[NN * F];       // layer-1 output (post BN)
__device__ float    g_y2[NN * F];       // layer-2 output (post BN)
__device__ float    g_asrc[NN * HH];
__device__ float    g_adst[NN * HH];
__device__ unsigned g_m[NN * HH];       // encoded segment max
__device__ float    g_s[NN * HH];       // segment softmax denom
__device__ float    g_ex[ET * HH];      // exp(e - m) per (edge, head)
__device__ float    g_sum[F], g_sumsq[F], g_scale[F], g_shift[F];
__device__ float    g_pool[GG * F];
__device__ float    g_cnt[GG];

// ------------- ordered-float encoding for atomicMax on float ----------------
__device__ __forceinline__ unsigned fenc(float f) {
    unsigned u = __float_as_uint(f);
    return (u & 0x80000000u) ? ~u : (u | 0x80000000u);
}
__device__ __forceinline__ float fdec(unsigned u) {
    return (u & 0x80000000u) ? __uint_as_float(u & 0x7FFFFFFFu)
                             : __uint_as_float(~u);
}

// ---------------- GEMM: C[M x 256] = A[M x 256] @ B[256 x 256] --------------
__global__ void gemm256(const float* __restrict__ A, const float* __restrict__ B,
                        float* __restrict__ C, int M) {
    __shared__ float sA[16][65];   // [k][m], padded
    __shared__ float sB[16][64];   // [k][n]
    const int row0 = blockIdx.x * 64;
    const int col0 = blockIdx.y * 64;
    const int t  = threadIdx.x;      // 0..255
    const int tx = t & 15, ty = t >> 4;

    float acc[4][4];
#pragma unroll
    for (int i = 0; i < 4; i++)
#pragma unroll
        for (int j = 0; j < 4; j++) acc[i][j] = 0.f;

    for (int k0 = 0; k0 < 256; k0 += 16) {
        {   // A tile: 64 rows x 16 k
            int r  = t >> 2;
            int kq = (t & 3) << 2;
            int gr = row0 + r;
            float4 v = make_float4(0.f, 0.f, 0.f, 0.f);
            if (gr < M) v = *(const float4*)(A + (long long)gr * 256 + k0 + kq);
            sA[kq + 0][r] = v.x; sA[kq + 1][r] = v.y;
            sA[kq + 2][r] = v.z; sA[kq + 3][r] = v.w;
        }
        {   // B tile: 16 k x 64 n
            int kr = t >> 4;
            int nq = (t & 15) << 2;
            float4 v = *(const float4*)(B + (long long)(k0 + kr) * 256 + col0 + nq);
            sB[kr][nq + 0] = v.x; sB[kr][nq + 1] = v.y;
            sB[kr][nq + 2] = v.z; sB[kr][nq + 3] = v.w;
        }
        __syncthreads();
#pragma unroll
        for (int k = 0; k < 16; k++) {
            float a[4], b[4];
#pragma unroll
            for (int i = 0; i < 4; i++) a[i] = sA[k][ty * 4 + i];
#pragma unroll
            for (int j = 0; j < 4; j++) b[j] = sB[k][tx * 4 + j];
#pragma unroll
            for (int i = 0; i < 4; i++)
#pragma unroll
                for (int j = 0; j < 4; j++) acc[i][j] += a[i] * b[j];
        }
        __syncthreads();
    }
#pragma unroll
    for (int i = 0; i < 4; i++) {
        int gr = row0 + ty * 4 + i;
        if (gr < M)
            *(float4*)(C + (long long)gr * 256 + col0 + tx * 4) =
                make_float4(acc[i][0], acc[i][1], acc[i][2], acc[i][3]);
    }
}

// ------------- per-node per-head attention scores (a_src, a_dst) ------------
__global__ void attn_scores(const float* __restrict__ atts,
                            const float* __restrict__ attd) {
    int n = blockIdx.x;
    int w = threadIdx.x >> 5;      // head
    int lane = threadIdx.x & 31;
    const float* hp = g_h + (long long)n * F + w * CC;
    float a1 = hp[lane] * atts[w * CC + lane] + hp[lane + 32] * atts[w * CC + lane + 32];
    float a2 = hp[lane] * attd[w * CC + lane] + hp[lane + 32] * attd[w * CC + lane + 32];
#pragma unroll
    for (int o = 16; o; o >>= 1) {
        a1 += __shfl_xor_sync(0xFFFFFFFFu, a1, o);
        a2 += __shfl_xor_sync(0xFFFFFFFFu, a2, o);
    }
    if (lane == 0) { g_asrc[n * HH + w] = a1; g_adst[n * HH + w] = a2; }
}

// ---------------------------- per-layer init --------------------------------
__global__ void init_layer() {
    int i = blockIdx.x * blockDim.x + threadIdx.x;
    if (i >= NN * F) return;
    g_out[i] = 0.f;
    if (i < NN * HH) { g_m[i] = fenc(-INFINITY); g_s[i] = 0.f; }
}

__device__ __forceinline__ void edge_sd(const int* __restrict__ ei, int e,
                                        int& s, int& d) {
    if (e < EE) { s = ei[e]; d = ei[EE + e]; }
    else        { s = d = e - EE; }    // self loops appended
}

// ------------------------------ edge pass A: max ----------------------------
__global__ void edge_max(const int* __restrict__ ei) {
    int t = blockIdx.x * blockDim.x + threadIdx.x;
    if (t >= ET * HH) return;
    int e = t >> 2, h = t & 3;
    int s, d; edge_sd(ei, e, s, d);
    float v = g_asrc[s * HH + h] + g_adst[d * HH + h];
    v = v > 0.f ? v : 0.2f * v;      // leaky relu, slope 0.2
    atomicMax(&g_m[d * HH + h], fenc(v));
}

// -------------------------- edge pass B: exp + sum --------------------------
__global__ void edge_exp(const int* __restrict__ ei) {
    int t = blockIdx.x * blockDim.x + threadIdx.x;
    if (t >= ET * HH) return;
    int e = t >> 2, h = t & 3;
    int s, d; edge_sd(ei, e, s, d);
    float v = g_asrc[s * HH + h] + g_adst[d * HH + h];
    v = v > 0.f ? v : 0.2f * v;
    float mm = fdec(g_m[d * HH + h]);
    float ex = expf(v - mm);
    g_ex[t] = ex;
    atomicAdd(&g_s[d * HH + h], ex);
}

// -------------------- edge pass C: weighted scatter aggregate ---------------
__global__ void edge_agg(const int* __restrict__ ei) {
    long long wid = (long long)blockIdx.x * (blockDim.x >> 5) + (threadIdx.x >> 5);
    if (wid >= (long long)ET * HH) return;
    int lane = threadIdx.x & 31;
    int e = (int)(wid >> 2), h = (int)(wid & 3);
    int s, d; edge_sd(ei, e, s, d);
    float alpha = g_ex[e * HH + h] / g_s[d * HH + h];
    const float* hp = g_h + (long long)s * F + h * CC;
    float* op = g_out + (long long)d * F + h * CC;
    atomicAdd(op + lane,        alpha * hp[lane]);
    atomicAdd(op + lane + 32,   alpha * hp[lane + 32]);
}

// ---------------- post-aggregation: +bias, ELU, residual --------------------
__global__ void post_elu_res(const float* __restrict__ b,
                             const float* __restrict__ xin,
                             float* __restrict__ y) {
    int i = blockIdx.x * blockDim.x + threadIdx.x;
    if (i >= NN * F) return;
    int f = i & 255;
    float v = g_out[i] + b[f];
    v = v > 0.f ? v : expm1f(v);     // ELU
    y[i] = v + xin[i];               // residual
}

// ------------------------------- batch norm ---------------------------------
__global__ void bn_zero() {
    int f = threadIdx.x;
    g_sum[f] = 0.f; g_sumsq[f] = 0.f;
}
__global__ void bn_stats(const float* __restrict__ y) {
    int f  = threadIdx.x;
    int r0 = blockIdx.x * 256;
    int r1 = min(r0 + 256, NN);
    float s = 0.f, s2 = 0.f;
    for (int r = r0; r < r1; r++) {
        float v = y[(long long)r * F + f];
        s += v; s2 += v * v;
    }
    atomicAdd(&g_sum[f], s);
    atomicAdd(&g_sumsq[f], s2);
}
__global__ void bn_final(const float* __restrict__ gm, const float* __restrict__ bt) {
    int f = threadIdx.x;
    float mu  = g_sum[f] / (float)NN;
    float var = g_sumsq[f] / (float)NN - mu * mu;
    float sc  = gm[f] * rsqrtf(var + 1e-5f);
    g_scale[f] = sc;
    g_shift[f] = bt[f] - mu * sc;
}
__global__ void bn_apply(float* __restrict__ y) {
    int i = blockIdx.x * blockDim.x + threadIdx.x;
    if (i >= NN * F) return;
    int f = i & 255;
    y[i] = y[i] * g_scale[f] + g_shift[f];
}

// ------------------------------- pooling ------------------------------------
__global__ void pool_zero() {
    int i = blockIdx.x * blockDim.x + threadIdx.x;
    if (i < GG * F) g_pool[i] = 0.f;
    if (i < GG)     g_cnt[i]  = 0.f;
}
__global__ void pool_acc(const int* __restrict__ bt, const float* __restrict__ y) {
    int i = blockIdx.x * blockDim.x + threadIdx.x;
    if (i >= NN * F) return;
    int n = i >> 8, f = i & 255;
    int g = bt[n];
    atomicAdd(&g_pool[g * F + f], y[i]);
    if (f == 0) atomicAdd(&g_cnt[g], 1.0f);
}

// --------------------------- MLP head + log softmax -------------------------
__global__ void mlp_head(const float* __restrict__ fc1w, const float* __restrict__ fc1b,
                         const float* __restrict__ fc2w, const float* __restrict__ fc2b,
                         float* __restrict__ out) {
    __shared__ float p[F];
    __shared__ float z[CC];
    __shared__ float l[NCLS];
    __shared__ float red[2];
    int g = blockIdx.x;
    int t = threadIdx.x;   // 64 threads
    float inv = 1.f / fmaxf(g_cnt[g], 1.f);
    for (int k = t; k < F; k += 64) p[k] = g_pool[g * F + k] * inv;
    __syncthreads();
    float acc = fc1b[t];
    for (int k = 0; k < F; k++) acc += p[k] * fc1w[k * CC + t];
    z[t] = fmaxf(acc, 0.f);
    __syncthreads();
    if (t < NCLS) {
        float a = fc2b[t];
        for (int k = 0; k < CC; k++) a += z[k] * fc2w[k * NCLS + t];
        l[t] = a;
    }
    __syncthreads();
    if (t == 0) {
        float m = l[0];
        for (int i = 1; i < NCLS; i++) m = fmaxf(m, l[i]);
        float s = 0.f;
        for (int i = 0; i < NCLS; i++) s += expf(l[i] - m);
        red[0] = m; red[1] = logf(s);
    }
    __syncthreads();
    if (t < NCLS) out[g * NCLS + t] = l[t] - red[0] - red[1];
}

// ---------------------------------- launch ----------------------------------
extern "C" void kernel_launch(void* const* d_in, const int* in_sizes, int n_in,
                              void* d_out, int out_size) {
    const float* x    = (const float*)d_in[0];
    const int*   ei   = (const int*)  d_in[1];
    const int*   bat  = (const int*)  d_in[2];
    const float* W1   = (const float*)d_in[3];
    const float* as1  = (const float*)d_in[4];
    const float* ad1  = (const float*)d_in[5];
    const float* b1   = (const float*)d_in[6];
    const float* gm1  = (const float*)d_in[7];
    const float* be1  = (const float*)d_in[8];
    const float* W2   = (const float*)d_in[9];
    const float* as2  = (const float*)d_in[10];
    const float* ad2  = (const float*)d_in[11];
    const float* b2   = (const float*)d_in[12];
    const float* gm2  = (const float*)d_in[13];
    const float* be2  = (const float*)d_in[14];
    const float* fc1w = (const float*)d_in[15];
    const float* fc1b = (const float*)d_in[16];
    const float* fc2w = (const float*)d_in[17];
    const float* fc2b = (const float*)d_in[18];
    float* out = (float*)d_out;

    float *ph, *py1, *py2;
    cudaGetSymbolAddress((void**)&ph,  g_h);
    cudaGetSymbolAddress((void**)&py1, g_y1);
    cudaGetSymbolAddress((void**)&py2, g_y2);

    const int TPB = 256;
    const int nNF  = (NN * F + TPB - 1) / TPB;
    const int nEH  = (ET * HH + TPB - 1) / TPB;
    const long long aggThreads = (long long)ET * HH * 32;
    const int nAGG = (int)((aggThreads + TPB - 1) / TPB);
    dim3 gemmGrid((NN + 63) / 64, 4);

    // ---------------- layer 1 ----------------
    gemm256<<<gemmGrid, 256>>>(x, W1, ph, NN);
    attn_scores<<<NN, 128>>>(as1, ad1);
    init_layer<<<nNF, TPB>>>();
    edge_max<<<nEH, TPB>>>(ei);
    edge_exp<<<nEH, TPB>>>(ei);
    edge_agg<<<nAGG, TPB>>>(ei);
    post_elu_res<<<nNF, TPB>>>(b1, x, py1);
    bn_zero<<<1, F>>>();
    bn_stats<<<(NN + 255) / 256, F>>>(py1);
    bn_final<<<1, F>>>(gm1, be1);
    bn_apply<<<nNF, TPB>>>(py1);

    // ---------------- layer 2 ----------------
    gemm256<<<gemmGrid, 256>>>(py1, W2, ph, NN);
    attn_scores<<<NN, 128>>>(as2, ad2);
    init_layer<<<nNF, TPB>>>();
    edge_max<<<nEH, TPB>>>(ei);
    edge_exp<<<nEH, TPB>>>(ei);
    edge_agg<<<nAGG, TPB>>>(ei);
    post_elu_res<<<nNF, TPB>>>(b2, py1, py2);
    bn_zero<<<1, F>>>();
    bn_stats<<<(NN + 255) / 256, F>>>(py2);
    bn_final<<<1, F>>>(gm2, be2);
    bn_apply<<<nNF, TPB>>>(py2);

    // ---------------- pool + head ----------------
    pool_zero<<<(GG * F + TPB - 1) / TPB, TPB>>>();
    pool_acc<<<nNF, TPB>>>(bat, py2);
    mlp_head<<<GG, 64>>>(fc1w, fc1b, fc2w, fc2b, out);
}

// round 2
// speedup vs baseline: 1.3472x; 1.3472x over previous
#include <cuda_runtime.h>
#include <math.h>

#define NN   50000
#define EE   400000
#define ET   (EE + NN)
#define F    256
#define HH   4
#define CC   64
#define GG   64
#define NCLS 10

// ---------------- scratch (static device globals; no allocations) -----------
__device__ float    g_h[NN * F];        // GEMM output h = x @ W (per layer)
__device__ float    g_out[NN * F];      // attention aggregation accumulator
__device__ float    g_y1[NN * F];       // layer-1 output, PRE-BN (raw)
__device__ float    g_y2[NN * F];       // layer-2 output, PRE-BN (raw)
__device__ float    g_asrc[NN * HH];
__device__ float    g_adst[NN * HH];
__device__ float    g_s[NN * HH];       // segment softmax denom
__device__ float    g_ex[ET * HH];      // exp(e) per (edge, head)
__device__ float    g_sum[F], g_sumsq[F];
__device__ float    g_sc1[F], g_sh1[F]; // BN1 scale/shift
__device__ float    g_sc2[F], g_sh2[F]; // BN2 scale/shift
__device__ float    g_pool[GG * F];
__device__ float    g_cnt[GG];

// ---------------- packed f32x2 helpers ---------------------------------------
__device__ __forceinline__ void ffma2(unsigned long long& d,
                                      unsigned long long a,
                                      unsigned long long b) {
    asm("fma.rn.f32x2 %0, %1, %2, %0;" : "+l"(d) : "l"(a), "l"(b));
}
__device__ __forceinline__ float2 unpk(unsigned long long v) {
    float2 r;
    asm("mov.b64 {%0, %1}, %2;" : "=f"(r.x), "=f"(r.y) : "l"(v));
    return r;
}

// ---------------- GEMM: C[M x 256] = A'[M x 256] @ B[256 x 256] --------------
// A' = A * scale[col] + shift[col] when scale != NULL (fused BN apply).
// 128x128 tile, 256 threads, 8x8 per thread via packed FFMA2.
#define BM 128
#define BN 128
#define BK 16
#define SA_STRIDE (2 * BM + 4)   // 260 floats (1040B, 16B-aligned rows)
#define SB_STRIDE (BN + 4)       // 132 floats (528B, 16B-aligned rows)

__global__ __launch_bounds__(256, 2)
void gemm_f32x2(const float* __restrict__ A, const float* __restrict__ B,
                float* __restrict__ C, int M,
                const float* __restrict__ scale, const float* __restrict__ shift) {
    __shared__ float sA[BK * SA_STRIDE];   // duplicated: sA[k][2m]=sA[k][2m+1]=a
    __shared__ float sB[BK * SB_STRIDE];
    const int row0 = blockIdx.x * BM;
    const int col0 = blockIdx.y * BN;
    const int t  = threadIdx.x;
    const int tx = t & 15, ty = t >> 4;

    unsigned long long acc[8][4];
#pragma unroll
    for (int i = 0; i < 8; i++)
#pragma unroll
        for (int j = 0; j < 4; j++) acc[i][j] = 0ULL;

    for (int k0 = 0; k0 < 256; k0 += BK) {
        // ---- A tile: 128 rows x 16 k, stored duplicated ----
#pragma unroll
        for (int q = t; q < 512; q += 256) {
            int m  = q >> 2;
            int kq = (q & 3) << 2;
            int gr = row0 + m;
            float4 v = make_float4(0.f, 0.f, 0.f, 0.f);
            if (gr < M) v = *(const float4*)(A + (size_t)gr * 256 + k0 + kq);
            if (scale) {
                v.x = v.x * scale[k0 + kq + 0] + shift[k0 + kq + 0];
                v.y = v.y * scale[k0 + kq + 1] + shift[k0 + kq + 1];
                v.z = v.z * scale[k0 + kq + 2] + shift[k0 + kq + 2];
                v.w = v.w * scale[k0 + kq + 3] + shift[k0 + kq + 3];
            }
            *(float2*)&sA[(kq + 0) * SA_STRIDE + 2 * m] = make_float2(v.x, v.x);
            *(float2*)&sA[(kq + 1) * SA_STRIDE + 2 * m] = make_float2(v.y, v.y);
            *(float2*)&sA[(kq + 2) * SA_STRIDE + 2 * m] = make_float2(v.z, v.z);
            *(float2*)&sA[(kq + 3) * SA_STRIDE + 2 * m] = make_float2(v.w, v.w);
        }
        // ---- B tile: 16 k x 128 n ----
#pragma unroll
        for (int q = t; q < 512; q += 256) {
            int r  = q >> 5;
            int c4 = (q & 31) << 2;
            *(float4*)&sB[r * SB_STRIDE + c4] =
                *(const float4*)(B + (size_t)(k0 + r) * 256 + col0 + c4);
        }
        __syncthreads();
#pragma unroll
        for (int k = 0; k < BK; k++) {
            const float* ap = &sA[k * SA_STRIDE + ty * 16];
            const float* bp = &sB[k * SB_STRIDE + tx * 8];
            ulonglong2 a01 = *(const ulonglong2*)(ap + 0);
            ulonglong2 a23 = *(const ulonglong2*)(ap + 4);
            ulonglong2 a45 = *(const ulonglong2*)(ap + 8);
            ulonglong2 a67 = *(const ulonglong2*)(ap + 12);
            ulonglong2 b01 = *(const ulonglong2*)(bp + 0);
            ulonglong2 b23 = *(const ulonglong2*)(bp + 4);
            unsigned long long av[8] = {a01.x, a01.y, a23.x, a23.y,
                                        a45.x, a45.y, a67.x, a67.y};
            unsigned long long bv[4] = {b01.x, b01.y, b23.x, b23.y};
#pragma unroll
            for (int i = 0; i < 8; i++)
#pragma unroll
                for (int j = 0; j < 4; j++) ffma2(acc[i][j], av[i], bv[j]);
        }
        __syncthreads();
    }
#pragma unroll
    for (int i = 0; i < 8; i++) {
        int gr = row0 + ty * 8 + i;
        if (gr < M) {
            float2 p0 = unpk(acc[i][0]), p1 = unpk(acc[i][1]);
            float2 p2 = unpk(acc[i][2]), p3 = unpk(acc[i][3]);
            float4* cp = (float4*)(C + (size_t)gr * 256 + col0 + tx * 8);
            cp[0] = make_float4(p0.x, p0.y, p1.x, p1.y);
            cp[1] = make_float4(p2.x, p2.y, p3.x, p3.y);
        }
    }
}

// ------------- per-node per-head attention scores (a_src, a_dst) ------------
__global__ void attn_scores(const float* __restrict__ atts,
                            const float* __restrict__ attd) {
    int n = blockIdx.x;
    int w = threadIdx.x >> 5;      // head
    int lane = threadIdx.x & 31;
    const float* hp = g_h + (size_t)n * F + w * CC;
    float a1 = hp[lane] * atts[w * CC + lane] + hp[lane + 32] * atts[w * CC + lane + 32];
    float a2 = hp[lane] * attd[w * CC + lane] + hp[lane + 32] * attd[w * CC + lane + 32];
#pragma unroll
    for (int o = 16; o; o >>= 1) {
        a1 += __shfl_xor_sync(0xFFFFFFFFu, a1, o);
        a2 += __shfl_xor_sync(0xFFFFFFFFu, a2, o);
    }
    if (lane == 0) { g_asrc[n * HH + w] = a1; g_adst[n * HH + w] = a2; }
}

// ---------------------------- per-layer init --------------------------------
__global__ void init_layer() {
    int i = blockIdx.x * blockDim.x + threadIdx.x;
    if (i >= NN * F) return;
    g_out[i] = 0.f;
    if (i < NN * HH) g_s[i] = 0.f;
    if (i < F)       { g_sum[i] = 0.f; g_sumsq[i] = 0.f; }
    if (i < GG * F)  g_pool[i] = 0.f;
    if (i < GG)      g_cnt[i] = 0.f;
}

__device__ __forceinline__ void edge_sd(const int* __restrict__ ei, int e,
                                        int& s, int& d) {
    if (e < EE) { s = ei[e]; d = ei[EE + e]; }
    else        { s = d = e - EE; }    // self loops appended
}

// -------------------- edge pass A: exp + segment sum -------------------------
// Scores are O(1); exp without max-shift is mathematically identical alpha.
__global__ void edge_expsum(const int* __restrict__ ei) {
    int t = blockIdx.x * blockDim.x + threadIdx.x;
    if (t >= ET * HH) return;
    int e = t >> 2, h = t & 3;
    int s, d; edge_sd(ei, e, s, d);
    float v = g_asrc[s * HH + h] + g_adst[d * HH + h];
    v = v > 0.f ? v : 0.2f * v;      // leaky relu
    float ex = expf(v);
    g_ex[t] = ex;
    atomicAdd(&g_s[d * HH + h], ex);
}

// -------------------- edge pass B: weighted scatter (vectored red) -----------
__device__ __forceinline__ void red4(float* p, float a, float b, float c, float d) {
    asm volatile("red.global.add.v4.f32 [%0], {%1,%2,%3,%4};"
                 :: "l"(p), "f"(a), "f"(b), "f"(c), "f"(d) : "memory");
}
__global__ void edge_agg(const int* __restrict__ ei) {
    int wid = blockIdx.x * (blockDim.x >> 5) + (threadIdx.x >> 5);
    if (wid >= ET) return;
    int lane = threadIdx.x & 31;
    int s, d; edge_sd(ei, wid, s, d);
    int c1 = lane << 2, c2 = 128 + (lane << 2);
    int h1 = lane >> 4, h2 = 2 + (lane >> 4);
    float a1 = __fdividef(g_ex[wid * 4 + h1], g_s[d * 4 + h1]);
    float a2 = __fdividef(g_ex[wid * 4 + h2], g_s[d * 4 + h2]);
    const float* hp = g_h + (size_t)s * F;
    float* op = g_out + (size_t)d * F;
    float4 v1 = *(const float4*)(hp + c1);
    float4 v2 = *(const float4*)(hp + c2);
    red4(op + c1, v1.x * a1, v1.y * a1, v1.z * a1, v1.w * a1);
    red4(op + c2, v2.x * a2, v2.y * a2, v2.z * a2, v2.w * a2);
}

// -------- fused: +bias, ELU, residual (opt. BN on residual), BN stats --------
#define ROWS_PB 128
__global__ void post_res_stats(const float* __restrict__ b,
                               const float* __restrict__ xin,
                               const float* __restrict__ rscale,
                               const float* __restrict__ rshift,
                               float* __restrict__ y) {
    int f  = threadIdx.x;            // 256
    int r0 = blockIdx.x * ROWS_PB;
    int r1 = min(r0 + ROWS_PB, NN);
    float bias = b[f];
    float sc = rscale ? rscale[f] : 1.f;
    float sh = rshift ? rshift[f] : 0.f;
    float s = 0.f, s2 = 0.f;
    for (int r = r0; r < r1; r++) {
        size_t idx = (size_t)r * F + f;
        float v = g_out[idx] + bias;
        v = v > 0.f ? v : expm1f(v);     // ELU
        v += xin[idx] * sc + sh;         // residual (post-BN of previous layer)
        y[idx] = v;
        s += v; s2 += v * v;
    }
    atomicAdd(&g_sum[f], s);
    atomicAdd(&g_sumsq[f], s2);
}

__global__ void bn_final(const float* __restrict__ gm, const float* __restrict__ bt,
                         float* __restrict__ sc_out, float* __restrict__ sh_out) {
    int f = threadIdx.x;
    float mu  = g_sum[f] / (float)NN;
    float var = g_sumsq[f] / (float)NN - mu * mu;
    float sc  = gm[f] * rsqrtf(var + 1e-5f);
    sc_out[f] = sc;
    sh_out[f] = bt[f] - mu * sc;
}

// -------------- fused: BN2 apply + global mean pool (sorted batch) -----------
#define POOL_ROWS 512
__global__ void bn_pool(const int* __restrict__ bt, const float* __restrict__ y) {
    int f  = threadIdx.x;            // 256
    int r0 = blockIdx.x * POOL_ROWS;
    int r1 = min(r0 + POOL_ROWS, NN);
    if (r0 >= NN) return;
    float sc = g_sc2[f], sh = g_sh2[f];
    int g = bt[r0];
    float acc = 0.f, cnt = 0.f;
    for (int r = r0; r < r1; r++) {
        int gr = bt[r];
        if (gr != g) {
            atomicAdd(&g_pool[g * F + f], acc);
            if (f == 0) atomicAdd(&g_cnt[g], cnt);
            acc = 0.f; cnt = 0.f; g = gr;
        }
        acc += y[(size_t)r * F + f] * sc + sh;
        cnt += 1.f;
    }
    atomicAdd(&g_pool[g * F + f], acc);
    if (f == 0) atomicAdd(&g_cnt[g], cnt);
}

// --------------------------- MLP head + log softmax -------------------------
__global__ void mlp_head(const float* __restrict__ fc1w, const float* __restrict__ fc1b,
                         const float* __restrict__ fc2w, const float* __restrict__ fc2b,
                         float* __restrict__ out) {
    __shared__ float p[F];
    __shared__ float z[CC];
    __shared__ float l[NCLS];
    __shared__ float red[2];
    int g = blockIdx.x;
    int t = threadIdx.x;   // 64 threads
    float inv = 1.f / fmaxf(g_cnt[g], 1.f);
    for (int k = t; k < F; k += 64) p[k] = g_pool[g * F + k] * inv;
    __syncthreads();
    float acc = fc1b[t];
    for (int k = 0; k < F; k++) acc += p[k] * fc1w[k * CC + t];
    z[t] = fmaxf(acc, 0.f);
    __syncthreads();
    if (t < NCLS) {
        float a = fc2b[t];
        for (int k = 0; k < CC; k++) a += z[k] * fc2w[k * NCLS + t];
        l[t] = a;
    }
    __syncthreads();
    if (t == 0) {
        float m = l[0];
        for (int i = 1; i < NCLS; i++) m = fmaxf(m, l[i]);
        float s = 0.f;
        for (int i = 0; i < NCLS; i++) s += expf(l[i] - m);
        red[0] = m; red[1] = logf(s);
    }
    __syncthreads();
    if (t < NCLS) out[g * NCLS + t] = l[t] - red[0] - red[1];
}

// ---------------------------------- launch ----------------------------------
extern "C" void kernel_launch(void* const* d_in, const int* in_sizes, int n_in,
                              void* d_out, int out_size) {
    const float* x    = (const float*)d_in[0];
    const int*   ei   = (const int*)  d_in[1];
    const int*   bat  = (const int*)  d_in[2];
    const float* W1   = (const float*)d_in[3];
    const float* as1  = (const float*)d_in[4];
    const float* ad1  = (const float*)d_in[5];
    const float* b1   = (const float*)d_in[6];
    const float* gm1  = (const float*)d_in[7];
    const float* be1  = (const float*)d_in[8];
    const float* W2   = (const float*)d_in[9];
    const float* as2  = (const float*)d_in[10];
    const float* ad2  = (const float*)d_in[11];
    const float* b2   = (const float*)d_in[12];
    const float* gm2  = (const float*)d_in[13];
    const float* be2  = (const float*)d_in[14];
    const float* fc1w = (const float*)d_in[15];
    const float* fc1b = (const float*)d_in[16];
    const float* fc2w = (const float*)d_in[17];
    const float* fc2b = (const float*)d_in[18];
    float* out = (float*)d_out;

    float *ph, *py1, *py2, *psc1, *psh1, *psc2, *psh2;
    cudaGetSymbolAddress((void**)&ph,   g_h);
    cudaGetSymbolAddress((void**)&py1,  g_y1);
    cudaGetSymbolAddress((void**)&py2,  g_y2);
    cudaGetSymbolAddress((void**)&psc1, g_sc1);
    cudaGetSymbolAddress((void**)&psh1, g_sh1);
    cudaGetSymbolAddress((void**)&psc2, g_sc2);
    cudaGetSymbolAddress((void**)&psh2, g_sh2);

    const int TPB = 256;
    const int nNF = (NN * F + TPB - 1) / TPB;
    const int nEH = (ET * HH + TPB - 1) / TPB;
    const int nAGG = (ET + 7) / 8;                 // 8 warps/block
    dim3 gemmGrid((NN + BM - 1) / BM, 2);
    const int nPOST = (NN + ROWS_PB - 1) / ROWS_PB;
    const int nPOOL = (NN + POOL_ROWS - 1) / POOL_ROWS;

    // ---------------- layer 1 ----------------
    gemm_f32x2<<<gemmGrid, 256>>>(x, W1, ph, NN, NULL, NULL);
    attn_scores<<<NN, 128>>>(as1, ad1);
    init_layer<<<nNF, TPB>>>();
    edge_expsum<<<nEH, TPB>>>(ei);
    edge_agg<<<nAGG, TPB>>>(ei);
    post_res_stats<<<nPOST, 256>>>(b1, x, NULL, NULL, py1);
    bn_final<<<1, F>>>(gm1, be1, psc1, psh1);

    // ---------------- layer 2 ----------------
    gemm_f32x2<<<gemmGrid, 256>>>(py1, W2, ph, NN, psc1, psh1);  // fused BN1 apply
    attn_scores<<<NN, 128>>>(as2, ad2);
    init_layer<<<nNF, TPB>>>();
    edge_expsum<<<nEH, TPB>>>(ei);
    edge_agg<<<nAGG, TPB>>>(ei);
    post_res_stats<<<nPOST, 256>>>(b2, py1, psc1, psh1, py2);    // BN1 on residual
    bn_final<<<1, F>>>(gm2, be2, psc2, psh2);

    // ---------------- pool + head ----------------
    bn_pool<<<nPOOL, 256>>>(bat, py2);                            // fused BN2 + pool
    mlp_head<<<GG, 64>>>(fc1w, fc1b, fc2w, fc2b, out);
}

// round 3
// speedup vs baseline: 1.6393x; 1.2169x over previous
#include <cuda_runtime.h>
#include <math.h>

#define NN   50000
#define EE   400000
#define ET   (EE + NN)
#define F    256
#define HH   4
#define CC   64
#define GG   64
#define NCLS 10

// ---------------- scratch (static device globals; no allocations) -----------
__device__ float g_h[NN * F];        // GEMM output h = x @ W (per layer)
__device__ float g_y1[NN * F];       // layer-1 output, PRE-BN (raw)
__device__ float g_y2[NN * F];       // layer-2 output, PRE-BN (raw)
__device__ float g_asrc[NN * HH];
__device__ float g_adst[NN * HH];
__device__ float g_sum[F], g_sumsq[F];
__device__ float g_sc1[F], g_sh1[F]; // BN1 scale/shift
__device__ float g_sc2[F], g_sh2[F]; // BN2 scale/shift
__device__ float g_pool[GG * F];
__device__ float g_cnt[GG];
// CSR (built per call from edge_index; reused by both layers)
__device__ int   g_cnt_n[NN];        // histogram, then write-cursor
__device__ int   g_rp[NN + 1];       // row pointers (by dst)
__device__ int   g_col[ET];          // src indices grouped by dst

// ---------------- packed f32x2 helpers ---------------------------------------
__device__ __forceinline__ void ffma2(unsigned long long& d,
                                      unsigned long long a,
                                      unsigned long long b) {
    asm("fma.rn.f32x2 %0, %1, %2, %0;" : "+l"(d) : "l"(a), "l"(b));
}
__device__ __forceinline__ float2 unpk(unsigned long long v) {
    float2 r;
    asm("mov.b64 {%0, %1}, %2;" : "=f"(r.x), "=f"(r.y) : "l"(v));
    return r;
}

// ---------------- GEMM: C[M x 256] = A'[M x 256] @ B[256 x 256] --------------
#define BM 128
#define BN 128
#define BK 16
#define SA_STRIDE (2 * BM + 4)
#define SB_STRIDE (BN + 4)

__global__ __launch_bounds__(256, 2)
void gemm_f32x2(const float* __restrict__ A, const float* __restrict__ B,
                float* __restrict__ C, int M,
                const float* __restrict__ scale, const float* __restrict__ shift) {
    __shared__ float sA[BK * SA_STRIDE];
    __shared__ float sB[BK * SB_STRIDE];
    const int row0 = blockIdx.x * BM;
    const int col0 = blockIdx.y * BN;
    const int t  = threadIdx.x;
    const int tx = t & 15, ty = t >> 4;

    unsigned long long acc[8][4];
#pragma unroll
    for (int i = 0; i < 8; i++)
#pragma unroll
        for (int j = 0; j < 4; j++) acc[i][j] = 0ULL;

    for (int k0 = 0; k0 < 256; k0 += BK) {
#pragma unroll
        for (int q = t; q < 512; q += 256) {
            int m  = q >> 2;
            int kq = (q & 3) << 2;
            int gr = row0 + m;
            float4 v = make_float4(0.f, 0.f, 0.f, 0.f);
            if (gr < M) v = *(const float4*)(A + (size_t)gr * 256 + k0 + kq);
            if (scale) {
                v.x = v.x * scale[k0 + kq + 0] + shift[k0 + kq + 0];
                v.y = v.y * scale[k0 + kq + 1] + shift[k0 + kq + 1];
                v.z = v.z * scale[k0 + kq + 2] + shift[k0 + kq + 2];
                v.w = v.w * scale[k0 + kq + 3] + shift[k0 + kq + 3];
            }
            *(float2*)&sA[(kq + 0) * SA_STRIDE + 2 * m] = make_float2(v.x, v.x);
            *(float2*)&sA[(kq + 1) * SA_STRIDE + 2 * m] = make_float2(v.y, v.y);
            *(float2*)&sA[(kq + 2) * SA_STRIDE + 2 * m] = make_float2(v.z, v.z);
            *(float2*)&sA[(kq + 3) * SA_STRIDE + 2 * m] = make_float2(v.w, v.w);
        }
#pragma unroll
        for (int q = t; q < 512; q += 256) {
            int r  = q >> 5;
            int c4 = (q & 31) << 2;
            *(float4*)&sB[r * SB_STRIDE + c4] =
                *(const float4*)(B + (size_t)(k0 + r) * 256 + col0 + c4);
        }
        __syncthreads();
#pragma unroll
        for (int k = 0; k < BK; k++) {
            const float* ap = &sA[k * SA_STRIDE + ty * 16];
            const float* bp = &sB[k * SB_STRIDE + tx * 8];
            ulonglong2 a01 = *(const ulonglong2*)(ap + 0);
            ulonglong2 a23 = *(const ulonglong2*)(ap + 4);
            ulonglong2 a45 = *(const ulonglong2*)(ap + 8);
            ulonglong2 a67 = *(const ulonglong2*)(ap + 12);
            ulonglong2 b01 = *(const ulonglong2*)(bp + 0);
            ulonglong2 b23 = *(const ulonglong2*)(bp + 4);
            unsigned long long av[8] = {a01.x, a01.y, a23.x, a23.y,
                                        a45.x, a45.y, a67.x, a67.y};
            unsigned long long bv[4] = {b01.x, b01.y, b23.x, b23.y};
#pragma unroll
            for (int i = 0; i < 8; i++)
#pragma unroll
                for (int j = 0; j < 4; j++) ffma2(acc[i][j], av[i], bv[j]);
        }
        __syncthreads();
    }
#pragma unroll
    for (int i = 0; i < 8; i++) {
        int gr = row0 + ty * 8 + i;
        if (gr < M) {
            float2 p0 = unpk(acc[i][0]), p1 = unpk(acc[i][1]);
            float2 p2 = unpk(acc[i][2]), p3 = unpk(acc[i][3]);
            float4* cp = (float4*)(C + (size_t)gr * 256 + col0 + tx * 8);
            cp[0] = make_float4(p0.x, p0.y, p1.x, p1.y);
            cp[1] = make_float4(p2.x, p2.y, p3.x, p3.y);
        }
    }
}

// ------------- per-node per-head attention scores (a_src, a_dst) ------------
__global__ void attn_scores(const float* __restrict__ atts,
                            const float* __restrict__ attd) {
    int n = blockIdx.x;
    int w = threadIdx.x >> 5;
    int lane = threadIdx.x & 31;
    const float* hp = g_h + (size_t)n * F + w * CC;
    float a1 = hp[lane] * atts[w * CC + lane] + hp[lane + 32] * atts[w * CC + lane + 32];
    float a2 = hp[lane] * attd[w * CC + lane] + hp[lane + 32] * attd[w * CC + lane + 32];
#pragma unroll
    for (int o = 16; o; o >>= 1) {
        a1 += __shfl_xor_sync(0xFFFFFFFFu, a1, o);
        a2 += __shfl_xor_sync(0xFFFFFFFFu, a2, o);
    }
    if (lane == 0) { g_asrc[n * HH + w] = a1; g_adst[n * HH + w] = a2; }
}

// ------------------------------ CSR build -----------------------------------
__global__ void csr_zero() {
    int i = blockIdx.x * blockDim.x + threadIdx.x;
    if (i < NN) g_cnt_n[i] = 0;
    if (i < F)  { g_sum[i] = 0.f; g_sumsq[i] = 0.f; }
    if (i < GG * F) g_pool[i] = 0.f;
    if (i < GG) g_cnt[i] = 0.f;
}
__global__ void csr_hist(const int* __restrict__ ei) {
    int e = blockIdx.x * blockDim.x + threadIdx.x;
    if (e >= ET) return;
    int d = (e < EE) ? ei[EE + e] : e - EE;
    atomicAdd(&g_cnt_n[d], 1);
}
#define SCAN_T 1024
#define CHUNK  ((NN + SCAN_T - 1) / SCAN_T)   // 49
__global__ void csr_scan() {
    __shared__ int ps[SCAN_T];
    int t = threadIdx.x;
    int lo = t * CHUNK, hi = min(lo + CHUNK, NN);
    int s = 0;
    for (int i = lo; i < hi; i++) s += g_cnt_n[i];
    ps[t] = s;
    __syncthreads();
    for (int off = 1; off < SCAN_T; off <<= 1) {
        int v = (t >= off) ? ps[t - off] : 0;
        __syncthreads();
        ps[t] += v;
        __syncthreads();
    }
    int run = t ? ps[t - 1] : 0;   // exclusive base for this chunk
    for (int i = lo; i < hi; i++) {
        int c = g_cnt_n[i];
        g_rp[i] = run;
        g_cnt_n[i] = run;          // becomes write-cursor
        run += c;
    }
    if (hi == NN) g_rp[NN] = run;
}
__global__ void csr_scatter(const int* __restrict__ ei) {
    int e = blockIdx.x * blockDim.x + threadIdx.x;
    if (e >= ET) return;
    int s, d;
    if (e < EE) { s = ei[e]; d = ei[EE + e]; }
    else        { s = d = e - EE; }
    int pos = atomicAdd(&g_cnt_n[d], 1);
    g_col[pos] = s;
}

// ----- fused GAT aggregate: softmax + weighted sum + bias + ELU + residual
// ----- (+ optional BN of prev layer on residual) + BN stats, per dst row -----
#define RPW 4
__global__ __launch_bounds__(256)
void gat_agg(const float* __restrict__ b,
             const float* __restrict__ xin,
             const float* __restrict__ rscale,
             const float* __restrict__ rshift,
             float* __restrict__ y) {
    __shared__ float bsum[F], bsq[F];
    int t = threadIdx.x;
    bsum[t] = 0.f; bsq[t] = 0.f;
    __syncthreads();

    int lane = t & 31;
    int gwarp = blockIdx.x * 8 + (t >> 5);
    int c1 = lane << 2, c2 = 128 + (lane << 2);
    int h1 = lane >> 4, h2 = 2 + (lane >> 4);

    float4 bias1 = *(const float4*)(b + c1);
    float4 bias2 = *(const float4*)(b + c2);
    float sc1v = rscale ? rscale[c1] : 1.f, sh1v = rshift ? rshift[c1] : 0.f;
    float sc1y = rscale ? rscale[c1 + 1] : 1.f, sh1y = rshift ? rshift[c1 + 1] : 0.f;
    float sc1z = rscale ? rscale[c1 + 2] : 1.f, sh1z = rshift ? rshift[c1 + 2] : 0.f;
    float sc1w = rscale ? rscale[c1 + 3] : 1.f, sh1w = rshift ? rshift[c1 + 3] : 0.f;
    float sc2v = rscale ? rscale[c2] : 1.f, sh2v = rshift ? rshift[c2] : 0.f;
    float sc2y = rscale ? rscale[c2 + 1] : 1.f, sh2y = rshift ? rshift[c2 + 1] : 0.f;
    float sc2z = rscale ? rscale[c2 + 2] : 1.f, sh2z = rshift ? rshift[c2 + 2] : 0.f;
    float sc2w = rscale ? rscale[c2 + 3] : 1.f, sh2w = rshift ? rshift[c2 + 3] : 0.f;

    float ss[8] = {0.f, 0.f, 0.f, 0.f, 0.f, 0.f, 0.f, 0.f};
    float sq[8] = {0.f, 0.f, 0.f, 0.f, 0.f, 0.f, 0.f, 0.f};

#pragma unroll
    for (int rr = 0; rr < RPW; rr++) {
        int d = gwarp * RPW + rr;
        if (d >= NN) break;
        float ad1 = g_adst[d * HH + h1];
        float ad2 = g_adst[d * HH + h2];
        float acc1x = 0.f, acc1y = 0.f, acc1z = 0.f, acc1w = 0.f;
        float acc2x = 0.f, acc2y = 0.f, acc2z = 0.f, acc2w = 0.f;
        float den1 = 0.f, den2 = 0.f;
        int e0 = g_rp[d], e1 = g_rp[d + 1];
        for (int e = e0; e < e1; e++) {
            int s = g_col[e];
            float v1 = g_asrc[s * HH + h1] + ad1;
            float v2 = g_asrc[s * HH + h2] + ad2;
            v1 = v1 > 0.f ? v1 : 0.2f * v1;
            v2 = v2 > 0.f ? v2 : 0.2f * v2;
            float ex1 = __expf(v1);
            float ex2 = __expf(v2);
            den1 += ex1; den2 += ex2;
            const float* hp = g_h + (size_t)s * F;
            float4 w1 = *(const float4*)(hp + c1);
            float4 w2 = *(const float4*)(hp + c2);
            acc1x += ex1 * w1.x; acc1y += ex1 * w1.y;
            acc1z += ex1 * w1.z; acc1w += ex1 * w1.w;
            acc2x += ex2 * w2.x; acc2y += ex2 * w2.y;
            acc2z += ex2 * w2.z; acc2w += ex2 * w2.w;
        }
        float i1 = __fdividef(1.f, den1);
        float i2 = __fdividef(1.f, den2);
        const float* xp = xin + (size_t)d * F;
        float4 x1 = *(const float4*)(xp + c1);
        float4 x2 = *(const float4*)(xp + c2);
        float o[8];
        o[0] = acc1x * i1 + bias1.x; o[1] = acc1y * i1 + bias1.y;
        o[2] = acc1z * i1 + bias1.z; o[3] = acc1w * i1 + bias1.w;
        o[4] = acc2x * i2 + bias2.x; o[5] = acc2y * i2 + bias2.y;
        o[6] = acc2z * i2 + bias2.z; o[7] = acc2w * i2 + bias2.w;
#pragma unroll
        for (int j = 0; j < 8; j++) o[j] = o[j] > 0.f ? o[j] : expm1f(o[j]);
        o[0] += x1.x * sc1v + sh1v; o[1] += x1.y * sc1y + sh1y;
        o[2] += x1.z * sc1z + sh1z; o[3] += x1.w * sc1w + sh1w;
        o[4] += x2.x * sc2v + sh2v; o[5] += x2.y * sc2y + sh2y;
        o[6] += x2.z * sc2z + sh2z; o[7] += x2.w * sc2w + sh2w;
        float* yp = y + (size_t)d * F;
        *(float4*)(yp + c1) = make_float4(o[0], o[1], o[2], o[3]);
        *(float4*)(yp + c2) = make_float4(o[4], o[5], o[6], o[7]);
#pragma unroll
        for (int j = 0; j < 8; j++) { ss[j] += o[j]; sq[j] += o[j] * o[j]; }
    }
    // warp-private stats -> smem (features distinct within a warp) -> global
#pragma unroll
    for (int j = 0; j < 4; j++) {
        atomicAdd(&bsum[c1 + j], ss[j]);
        atomicAdd(&bsq[c1 + j],  sq[j]);
        atomicAdd(&bsum[c2 + j], ss[4 + j]);
        atomicAdd(&bsq[c2 + j],  sq[4 + j]);
    }
    __syncthreads();
    atomicAdd(&g_sum[t],   bsum[t]);
    atomicAdd(&g_sumsq[t], bsq[t]);
}

__global__ void bn_final(const float* __restrict__ gm, const float* __restrict__ bt,
                         float* __restrict__ sc_out, float* __restrict__ sh_out) {
    int f = threadIdx.x;
    float mu  = g_sum[f] / (float)NN;
    float var = g_sumsq[f] / (float)NN - mu * mu;
    float sc  = gm[f] * rsqrtf(var + 1e-5f);
    sc_out[f] = sc;
    sh_out[f] = bt[f] - mu * sc;
    g_sum[f] = 0.f; g_sumsq[f] = 0.f;   // ready for next layer
}

// -------------- fused: BN2 apply + global mean pool (sorted batch) -----------
#define POOL_ROWS 512
__global__ void bn_pool(const int* __restrict__ bt, const float* __restrict__ y) {
    int f  = threadIdx.x;
    int r0 = blockIdx.x * POOL_ROWS;
    int r1 = min(r0 + POOL_ROWS, NN);
    if (r0 >= NN) return;
    float sc = g_sc2[f], sh = g_sh2[f];
    int g = bt[r0];
    float acc = 0.f, cnt = 0.f;
    for (int r = r0; r < r1; r++) {
        int gr = bt[r];
        if (gr != g) {
            atomicAdd(&g_pool[g * F + f], acc);
            if (f == 0) atomicAdd(&g_cnt[g], cnt);
            acc = 0.f; cnt = 0.f; g = gr;
        }
        acc += y[(size_t)r * F + f] * sc + sh;
        cnt += 1.f;
    }
    atomicAdd(&g_pool[g * F + f], acc);
    if (f == 0) atomicAdd(&g_cnt[g], cnt);
}

// --------------------------- MLP head + log softmax -------------------------
__global__ void mlp_head(const float* __restrict__ fc1w, const float* __restrict__ fc1b,
                         const float* __restrict__ fc2w, const float* __restrict__ fc2b,
                         float* __restrict__ out) {
    __shared__ float p[F];
    __shared__ float z[CC];
    __shared__ float l[NCLS];
    __shared__ float red[2];
    int g = blockIdx.x;
    int t = threadIdx.x;   // 64
    float inv = 1.f / fmaxf(g_cnt[g], 1.f);
    for (int k = t; k < F; k += 64) p[k] = g_pool[g * F + k] * inv;
    __syncthreads();
    float acc = fc1b[t];
    for (int k = 0; k < F; k++) acc += p[k] * fc1w[k * CC + t];
    z[t] = fmaxf(acc, 0.f);
    __syncthreads();
    if (t < NCLS) {
        float a = fc2b[t];
        for (int k = 0; k < CC; k++) a += z[k] * fc2w[k * NCLS + t];
        l[t] = a;
    }
    __syncthreads();
    if (t == 0) {
        float m = l[0];
        for (int i = 1; i < NCLS; i++) m = fmaxf(m, l[i]);
        float s = 0.f;
        for (int i = 0; i < NCLS; i++) s += expf(l[i] - m);
        red[0] = m; red[1] = logf(s);
    }
    __syncthreads();
    if (t < NCLS) out[g * NCLS + t] = l[t] - red[0] - red[1];
}

// ---------------------------------- launch ----------------------------------
extern "C" void kernel_launch(void* const* d_in, const int* in_sizes, int n_in,
                              void* d_out, int out_size) {
    const float* x    = (const float*)d_in[0];
    const int*   ei   = (const int*)  d_in[1];
    const int*   bat  = (const int*)  d_in[2];
    const float* W1   = (const float*)d_in[3];
    const float* as1  = (const float*)d_in[4];
    const float* ad1  = (const float*)d_in[5];
    const float* b1   = (const float*)d_in[6];
    const float* gm1  = (const float*)d_in[7];
    const float* be1  = (const float*)d_in[8];
    const float* W2   = (const float*)d_in[9];
    const float* as2  = (const float*)d_in[10];
    const float* ad2  = (const float*)d_in[11];
    const float* b2   = (const float*)d_in[12];
    const float* gm2  = (const float*)d_in[13];
    const float* be2  = (const float*)d_in[14];
    const float* fc1w = (const float*)d_in[15];
    const float* fc1b = (const float*)d_in[16];
    const float* fc2w = (const float*)d_in[17];
    const float* fc2b = (const float*)d_in[18];
    float* out = (float*)d_out;

    float *ph, *py1, *py2, *psc1, *psh1, *psc2, *psh2;
    cudaGetSymbolAddress((void**)&ph,   g_h);
    cudaGetSymbolAddress((void**)&py1,  g_y1);
    cudaGetSymbolAddress((void**)&py2,  g_y2);
    cudaGetSymbolAddress((void**)&psc1, g_sc1);
    cudaGetSymbolAddress((void**)&psh1, g_sh1);
    cudaGetSymbolAddress((void**)&psc2, g_sc2);
    cudaGetSymbolAddress((void**)&psh2, g_sh2);

    const int TPB = 256;
    const int nET = (ET + TPB - 1) / TPB;
    dim3 gemmGrid((NN + BM - 1) / BM, 2);
    const int nAGG  = (NN + 8 * RPW - 1) / (8 * RPW);
    const int nPOOL = (NN + POOL_ROWS - 1) / POOL_ROWS;
    const int nZERO = (GG * F + TPB - 1) / TPB > (NN + TPB - 1) / TPB
                      ? (GG * F + TPB - 1) / TPB : (NN + TPB - 1) / TPB;

    // ---------------- CSR build (reused by both layers) ----------------
    csr_zero<<<nZERO, TPB>>>();
    csr_hist<<<nET, TPB>>>(ei);
    csr_scan<<<1, SCAN_T>>>();
    csr_scatter<<<nET, TPB>>>(ei);

    // ---------------- layer 1 ----------------
    gemm_f32x2<<<gemmGrid, 256>>>(x, W1, ph, NN, NULL, NULL);
    attn_scores<<<NN, 128>>>(as1, ad1);
    gat_agg<<<nAGG, 256>>>(b1, x, NULL, NULL, py1);
    bn_final<<<1, F>>>(gm1, be1, psc1, psh1);

    // ---------------- layer 2 ----------------
    gemm_f32x2<<<gemmGrid, 256>>>(py1, W2, ph, NN, psc1, psh1);  // fused BN1 apply
    attn_scores<<<NN, 128>>>(as2, ad2);
    gat_agg<<<nAGG, 256>>>(b2, py1, psc1, psh1, py2);            // BN1 on residual
    bn_final<<<1, F>>>(gm2, be2, psc2, psh2);

    // ---------------- pool + head ----------------
    bn_pool<<<nPOOL, 256>>>(bat, py2);
    mlp_head<<<GG, 64>>>(fc1w, fc1b, fc2w, fc2b, out);
}

// round 5
// speedup vs baseline: 2.2028x; 1.3437x over previous
#include <cuda_runtime.h>
#include <cuda_bf16.h>
#include <math.h>
#include <stdint.h>

#define NN   50000
#define EE   400000
#define ET   (EE + NN)
#define F    256
#define HH   4
#define CC   64
#define GG   64
#define NCLS 10
#define KP   768

// ---------------- scratch (static device globals; no allocations) -----------
__device__ float g_h[NN * F];
__device__ float g_y1[NN * F];
__device__ float g_y2[NN * F];
__device__ float g_asrc[NN * HH];
__device__ float g_adst[NN * HH];
__device__ float g_sum[F], g_sumsq[F];
__device__ float g_sc1[F], g_sh1[F];
__device__ float g_sc2[F], g_sh2[F];
__device__ float g_pool[GG * F];
__device__ float g_cnt[GG];
__device__ __align__(16) __nv_bfloat16 g_Ap[(size_t)NN * KP];  // split A
__device__ __align__(16) __nv_bfloat16 g_Bp[KP * 256];         // split W
// CSR
__device__ int   g_cnt_n[NN];
__device__ int   g_rp[NN + 1];
__device__ int   g_col[ET];

// ---------------- bf16 pack helpers ------------------------------------------
__device__ __forceinline__ uint32_t pack_hi(float a, float b) {
    __nv_bfloat162 h = __floats2bfloat162_rn(a, b);
    return *(uint32_t*)&h;
}
__device__ __forceinline__ uint32_t pack_lo(float a, float b, uint32_t hi) {
    __nv_bfloat162 h = *(__nv_bfloat162*)&hi;
    __nv_bfloat162 l = __floats2bfloat162_rn(a - __bfloat162float(h.x),
                                             b - __bfloat162float(h.y));
    return *(uint32_t*)&l;
}

// ---------- conv_B: W[256][256] -> B'[768][256] bf16 (hi, hi, lo per 64-blk) --
__global__ void conv_B(const float* __restrict__ W) {
    int k = blockIdx.x, n = threadIdx.x;
    float v = W[k * 256 + n];
    __nv_bfloat16 hi = __float2bfloat16_rn(v);
    __nv_bfloat16 lo = __float2bfloat16_rn(v - __bfloat162float(hi));
    int j = k >> 6, c = k & 63;
    g_Bp[(j * 192 + c) * 256 + n]       = hi;   // pairs A_hi
    g_Bp[(j * 192 + 64 + c) * 256 + n]  = hi;   // pairs A_lo
    g_Bp[(j * 192 + 128 + c) * 256 + n] = lo;   // pairs A_hi
}

// ---------- conv_A: A[N][256] fp32 (opt *scale+shift) -> A'[N][768] bf16 -----
// Per 64-col block j: cols [0,64)=hi, [64,128)=lo, [128,192)=hi.
// Also zeroes g_asrc / g_adst for the GEMM epilogue atomics.
__global__ __launch_bounds__(256)
void conv_A(const float* __restrict__ A,
            const float* __restrict__ scale, const float* __restrict__ shift) {
    int t = threadIdx.x;
    int gid = blockIdx.x * 256 + t;
    if (gid < NN * HH) { g_asrc[gid] = 0.f; g_adst[gid] = 0.f; }
    int r  = blockIdx.x * 8 + (t >> 5);
    int c0 = (t & 31) * 8;                 // 8 fp32 cols, within one 64-block
    float e[8];
    const float4* ap = (const float4*)(A + (size_t)r * 256 + c0);
    float4 v0 = ap[0], v1 = ap[1];
    e[0] = v0.x; e[1] = v0.y; e[2] = v0.z; e[3] = v0.w;
    e[4] = v1.x; e[5] = v1.y; e[6] = v1.z; e[7] = v1.w;
    if (scale) {
#pragma unroll
        for (int i = 0; i < 8; i++) e[i] = e[i] * scale[c0 + i] + shift[c0 + i];
    }
    uint4 hi, lo;
    hi.x = pack_hi(e[0], e[1]); hi.y = pack_hi(e[2], e[3]);
    hi.z = pack_hi(e[4], e[5]); hi.w = pack_hi(e[6], e[7]);
    lo.x = pack_lo(e[0], e[1], hi.x); lo.y = pack_lo(e[2], e[3], hi.y);
    lo.z = pack_lo(e[4], e[5], hi.z); lo.w = pack_lo(e[6], e[7], hi.w);
    int j = c0 >> 6, q = c0 & 63;
    __nv_bfloat16* base = g_Ap + (size_t)r * KP + j * 192 + q;
    *(uint4*)(base)       = hi;
    *(uint4*)(base + 64)  = lo;
    *(uint4*)(base + 128) = hi;
}

// =================== bf16 mma.sync GEMM, K=768, fused attn dots ==============
// C[M x 256] = A' @ B'.  Block 128x128, 8 warps (2x4), warp tile 64x32.
#define PA 80     // A smem pitch bytes (40 bf16)
#define PB 272    // B smem pitch bytes (136 bf16)
#define ABUF (128 * PA)            // 10240
#define BBUF (32 * PB)             // 8704
#define STG  (ABUF + BBUF)         // 18944

__device__ __forceinline__ uint32_t smem_u32(const void* p) {
    uint32_t a;
    asm("{ .reg .u64 t; cvta.to.shared.u64 t, %1; cvt.u32.u64 %0, t; }"
        : "=r"(a) : "l"(p));
    return a;
}
__device__ __forceinline__ void ldsm_x4(uint32_t* a, uint32_t addr) {
    asm volatile("ldmatrix.sync.aligned.m8n8.x4.shared.b16 {%0,%1,%2,%3}, [%4];"
                 : "=r"(a[0]), "=r"(a[1]), "=r"(a[2]), "=r"(a[3]) : "r"(addr));
}
__device__ __forceinline__ void ldsm_x2t(uint32_t* b, uint32_t addr) {
    asm volatile("ldmatrix.sync.aligned.m8n8.x2.trans.shared.b16 {%0,%1}, [%2];"
                 : "=r"(b[0]), "=r"(b[1]) : "r"(addr));
}
__device__ __forceinline__ void mma16816(float* d, const uint32_t* a,
                                         const uint32_t* b) {
    asm volatile(
        "mma.sync.aligned.m16n8k16.row.col.f32.bf16.bf16.f32 "
        "{%0,%1,%2,%3}, {%4,%5,%6,%7}, {%8,%9}, {%0,%1,%2,%3};"
        : "+f"(d[0]), "+f"(d[1]), "+f"(d[2]), "+f"(d[3])
        : "r"(a[0]), "r"(a[1]), "r"(a[2]), "r"(a[3]), "r"(b[0]), "r"(b[1]));
}

__global__ __launch_bounds__(256)
void gemm_bf16(float* __restrict__ C, int M,
               const float* __restrict__ atts, const float* __restrict__ attd) {
    __shared__ __align__(16) char sm[2 * STG];
    const int t = threadIdx.x, lane = t & 31, w = t >> 5;
    const int wm = w & 1, wn = w >> 1;
    const int row0 = blockIdx.x * 128, col0 = blockIdx.y * 128;
    const uint32_t sb = smem_u32(sm);

    float acc[4][4][4];
#pragma unroll
    for (int i = 0; i < 4; i++)
#pragma unroll
        for (int j = 0; j < 4; j++)
#pragma unroll
            for (int k = 0; k < 4; k++) acc[i][j][k] = 0.f;

    // gmem load roles
    const int ar = t >> 1, apart = t & 1;      // A: row, 32B chunk
    const int br = t >> 3, bseg = t & 7;       // B: row, 32B chunk
    const bool a_ok = (row0 + ar) < M;
    const __nv_bfloat16* agp = g_Ap + (size_t)(row0 + ar) * KP + apart * 16;
    const __nv_bfloat16* bgp = g_Bp + (size_t)br * 256 + col0 + bseg * 16;

    uint4 la0, la1, lb0, lb1;
    la0 = la1 = make_uint4(0, 0, 0, 0);
    // prologue: load stage 0
    if (a_ok) { la0 = *(const uint4*)(agp); la1 = *(const uint4*)(agp + 8); }
    lb0 = *(const uint4*)(bgp);
    lb1 = *(const uint4*)(bgp + 8);
    {
        char* pa = sm + ar * PA + apart * 32;
        *(uint4*)pa = la0; *(uint4*)(pa + 16) = la1;
        char* pb = sm + ABUF + br * PB + bseg * 32;
        *(uint4*)pb = lb0; *(uint4*)(pb + 16) = lb1;
    }
    __syncthreads();

    for (int s = 0; s < 24; s++) {
        const int buf = s & 1;
        const uint32_t sba = sb + buf * STG;
        if (s < 23) {
            int k0 = (s + 1) * 32;
            la0 = la1 = make_uint4(0, 0, 0, 0);
            if (a_ok) {
                la0 = *(const uint4*)(agp + k0);
                la1 = *(const uint4*)(agp + k0 + 8);
            }
            lb0 = *(const uint4*)(bgp + (size_t)k0 * 256);
            lb1 = *(const uint4*)(bgp + (size_t)k0 * 256 + 8);
        }
#pragma unroll
        for (int kh = 0; kh < 2; kh++) {
            uint32_t afr[4][4], bfr[4][2];
#pragma unroll
            for (int mi = 0; mi < 4; mi++) {
                uint32_t addr = sba + (uint32_t)(wm * 64 + mi * 16 + (lane & 15)) * PA
                              + kh * 32 + (lane >> 4) * 16;
                ldsm_x4(afr[mi], addr);
            }
#pragma unroll
            for (int nf = 0; nf < 4; nf++) {
                uint32_t addr = sba + ABUF + (uint32_t)(kh * 16 + (lane & 15)) * PB
                              + (wn * 32 + nf * 8) * 2;
                ldsm_x2t(bfr[nf], addr);
            }
#pragma unroll
            for (int mi = 0; mi < 4; mi++)
#pragma unroll
                for (int nf = 0; nf < 4; nf++)
                    mma16816(acc[mi][nf], afr[mi], bfr[nf]);
        }
        if (s < 23) {
            char* pa = sm + (buf ^ 1) * STG + ar * PA + apart * 32;
            *(uint4*)pa = la0; *(uint4*)(pa + 16) = la1;
            char* pb = sm + (buf ^ 1) * STG + ABUF + br * PB + bseg * 32;
            *(uint4*)pb = lb0; *(uint4*)(pb + 16) = lb1;
        }
        __syncthreads();
    }

    // ---- epilogue: store C + fused att dots (quad reduce + atomic) ----
    const int head = (col0 + wn * 32) >> 6;
#pragma unroll
    for (int mi = 0; mi < 4; mi++) {
        int r_lo = row0 + wm * 64 + mi * 16 + (lane >> 2);
        int r_hi = r_lo + 8;
        float ds0 = 0.f, dd0 = 0.f, ds1 = 0.f, dd1 = 0.f;
#pragma unroll
        for (int nf = 0; nf < 4; nf++) {
            int c = col0 + wn * 32 + nf * 8 + (lane & 3) * 2;
            float v0 = acc[mi][nf][0], v1 = acc[mi][nf][1];
            float v2 = acc[mi][nf][2], v3 = acc[mi][nf][3];
            if (r_lo < M) *(float2*)(C + (size_t)r_lo * 256 + c) = make_float2(v0, v1);
            if (r_hi < M) *(float2*)(C + (size_t)r_hi * 256 + c) = make_float2(v2, v3);
            float s0 = atts[c], s1 = atts[c + 1];
            float d0 = attd[c], d1 = attd[c + 1];
            ds0 += v0 * s0 + v1 * s1; dd0 += v0 * d0 + v1 * d1;
            ds1 += v2 * s0 + v3 * s1; dd1 += v2 * d0 + v3 * d1;
        }
#pragma unroll
        for (int o = 1; o <= 2; o <<= 1) {
            ds0 += __shfl_xor_sync(0xFFFFFFFFu, ds0, o);
            dd0 += __shfl_xor_sync(0xFFFFFFFFu, dd0, o);
            ds1 += __shfl_xor_sync(0xFFFFFFFFu, ds1, o);
            dd1 += __shfl_xor_sync(0xFFFFFFFFu, dd1, o);
        }
        if ((lane & 3) == 0) {
            if (r_lo < M) {
                atomicAdd(&g_asrc[r_lo * HH + head], ds0);
                atomicAdd(&g_adst[r_lo * HH + head], dd0);
            }
            if (r_hi < M) {
                atomicAdd(&g_asrc[r_hi * HH + head], ds1);
                atomicAdd(&g_adst[r_hi * HH + head], dd1);
            }
        }
    }
}

// ------------------------------ CSR build -----------------------------------
__global__ void csr_zero() {
    int i = blockIdx.x * blockDim.x + threadIdx.x;
    if (i < NN) g_cnt_n[i] = 0;
    if (i < F)  { g_sum[i] = 0.f; g_sumsq[i] = 0.f; }
    if (i < GG * F) g_pool[i] = 0.f;
    if (i < GG) g_cnt[i] = 0.f;
}
__global__ void csr_hist(const int* __restrict__ ei) {
    int e = blockIdx.x * blockDim.x + threadIdx.x;
    if (e >= ET) return;
    int d = (e < EE) ? ei[EE + e] : e - EE;
    atomicAdd(&g_cnt_n[d], 1);
}
#define SCAN_T 1024
#define CHUNK  ((NN + SCAN_T - 1) / SCAN_T)
__global__ void csr_scan() {
    __shared__ int ps[SCAN_T];
    int t = threadIdx.x;
    int lo = t * CHUNK, hi = min(lo + CHUNK, NN);
    int s = 0;
    for (int i = lo; i < hi; i++) s += g_cnt_n[i];
    ps[t] = s;
    __syncthreads();
    for (int off = 1; off < SCAN_T; off <<= 1) {
        int v = (t >= off) ? ps[t - off] : 0;
        __syncthreads();
        ps[t] += v;
        __syncthreads();
    }
    int run = t ? ps[t - 1] : 0;
    for (int i = lo; i < hi; i++) {
        int c = g_cnt_n[i];
        g_rp[i] = run;
        g_cnt_n[i] = run;
        run += c;
    }
    if (hi == NN) g_rp[NN] = run;
}
__global__ void csr_scatter(const int* __restrict__ ei) {
    int e = blockIdx.x * blockDim.x + threadIdx.x;
    if (e >= ET) return;
    int s, d;
    if (e < EE) { s = ei[e]; d = ei[EE + e]; }
    else        { s = d = e - EE; }
    int pos = atomicAdd(&g_cnt_n[d], 1);
    g_col[pos] = s;
}

// ----- fused GAT aggregate + bias + ELU + residual(+BN) + BN stats -----------
#define RPW 4
__global__ __launch_bounds__(256)
void gat_agg(const float* __restrict__ b,
             const float* __restrict__ xin,
             const float* __restrict__ rscale,
             const float* __restrict__ rshift,
             float* __restrict__ y) {
    __shared__ float bsum[F], bsq[F];
    int t = threadIdx.x;
    bsum[t] = 0.f; bsq[t] = 0.f;
    __syncthreads();

    int lane = t & 31;
    int gwarp = blockIdx.x * 8 + (t >> 5);
    int c1 = lane << 2, c2 = 128 + (lane << 2);
    int h1 = lane >> 4, h2 = 2 + (lane >> 4);

    float4 bias1 = *(const float4*)(b + c1);
    float4 bias2 = *(const float4*)(b + c2);
    float sc1v = rscale ? rscale[c1] : 1.f, sh1v = rshift ? rshift[c1] : 0.f;
    float sc1y = rscale ? rscale[c1 + 1] : 1.f, sh1y = rshift ? rshift[c1 + 1] : 0.f;
    float sc1z = rscale ? rscale[c1 + 2] : 1.f, sh1z = rshift ? rshift[c1 + 2] : 0.f;
    float sc1w = rscale ? rscale[c1 + 3] : 1.f, sh1w = rshift ? rshift[c1 + 3] : 0.f;
    float sc2v = rscale ? rscale[c2] : 1.f, sh2v = rshift ? rshift[c2] : 0.f;
    float sc2y = rscale ? rscale[c2 + 1] : 1.f, sh2y = rshift ? rshift[c2 + 1] : 0.f;
    float sc2z = rscale ? rscale[c2 + 2] : 1.f, sh2z = rshift ? rshift[c2 + 2] : 0.f;
    float sc2w = rscale ? rscale[c2 + 3] : 1.f, sh2w = rshift ? rshift[c2 + 3] : 0.f;

    float ss[8] = {0,0,0,0,0,0,0,0};
    float sq[8] = {0,0,0,0,0,0,0,0};

#pragma unroll
    for (int rr = 0; rr < RPW; rr++) {
        int d = gwarp * RPW + rr;
        if (d >= NN) break;
        float ad1 = g_adst[d * HH + h1];
        float ad2 = g_adst[d * HH + h2];
        float acc1x = 0.f, acc1y = 0.f, acc1z = 0.f, acc1w = 0.f;
        float acc2x = 0.f, acc2y = 0.f, acc2z = 0.f, acc2w = 0.f;
        float den1 = 0.f, den2 = 0.f;
        int e0 = g_rp[d], e1 = g_rp[d + 1];
        for (int e = e0; e < e1; e++) {
            int s = g_col[e];
            float v1 = g_asrc[s * HH + h1] + ad1;
            float v2 = g_asrc[s * HH + h2] + ad2;
            v1 = v1 > 0.f ? v1 : 0.2f * v1;
            v2 = v2 > 0.f ? v2 : 0.2f * v2;
            float ex1 = __expf(v1);
            float ex2 = __expf(v2);
            den1 += ex1; den2 += ex2;
            const float* hp = g_h + (size_t)s * F;
            float4 w1 = *(const float4*)(hp + c1);
            float4 w2 = *(const float4*)(hp + c2);
            acc1x += ex1 * w1.x; acc1y += ex1 * w1.y;
            acc1z += ex1 * w1.z; acc1w += ex1 * w1.w;
            acc2x += ex2 * w2.x; acc2y += ex2 * w2.y;
            acc2z += ex2 * w2.z; acc2w += ex2 * w2.w;
        }
        float i1 = __fdividef(1.f, den1);
        float i2 = __fdividef(1.f, den2);
        const float* xp = xin + (size_t)d * F;
        float4 x1 = *(const float4*)(xp + c1);
        float4 x2 = *(const float4*)(xp + c2);
        float o[8];
        o[0] = acc1x * i1 + bias1.x; o[1] = acc1y * i1 + bias1.y;
        o[2] = acc1z * i1 + bias1.z; o[3] = acc1w * i1 + bias1.w;
        o[4] = acc2x * i2 + bias2.x; o[5] = acc2y * i2 + bias2.y;
        o[6] = acc2z * i2 + bias2.z; o[7] = acc2w * i2 + bias2.w;
#pragma unroll
        for (int jj = 0; jj < 8; jj++) o[jj] = o[jj] > 0.f ? o[jj] : expm1f(o[jj]);
        o[0] += x1.x * sc1v + sh1v; o[1] += x1.y * sc1y + sh1y;
        o[2] += x1.z * sc1z + sh1z; o[3] += x1.w * sc1w + sh1w;
        o[4] += x2.x * sc2v + sh2v; o[5] += x2.y * sc2y + sh2y;
        o[6] += x2.z * sc2z + sh2z; o[7] += x2.w * sc2w + sh2w;
        float* yp = y + (size_t)d * F;
        *(float4*)(yp + c1) = make_float4(o[0], o[1], o[2], o[3]);
        *(float4*)(yp + c2) = make_float4(o[4], o[5], o[6], o[7]);
#pragma unroll
        for (int jj = 0; jj < 8; jj++) { ss[jj] += o[jj]; sq[jj] += o[jj] * o[jj]; }
    }
#pragma unroll
    for (int jj = 0; jj < 4; jj++) {
        atomicAdd(&bsum[c1 + jj], ss[jj]);
        atomicAdd(&bsq[c1 + jj],  sq[jj]);
        atomicAdd(&bsum[c2 + jj], ss[4 + jj]);
        atomicAdd(&bsq[c2 + jj],  sq[4 + jj]);
    }
    __syncthreads();
    atomicAdd(&g_sum[t],   bsum[t]);
    atomicAdd(&g_sumsq[t], bsq[t]);
}

__global__ void bn_final(const float* __restrict__ gm, const float* __restrict__ bt,
                         float* __restrict__ sc_out, float* __restrict__ sh_out) {
    int f = threadIdx.x;
    float mu  = g_sum[f] / (float)NN;
    float var = g_sumsq[f] / (float)NN - mu * mu;
    float sc  = gm[f] * rsqrtf(var + 1e-5f);
    sc_out[f] = sc;
    sh_out[f] = bt[f] - mu * sc;
    g_sum[f] = 0.f; g_sumsq[f] = 0.f;
}

// -------------- fused: BN2 apply + global mean pool (sorted batch) -----------
#define POOL_ROWS 512
__global__ void bn_pool(const int* __restrict__ bt, const float* __restrict__ y) {
    int f  = threadIdx.x;
    int r0 = blockIdx.x * POOL_ROWS;
    int r1 = min(r0 + POOL_ROWS, NN);
    if (r0 >= NN) return;
    float sc = g_sc2[f], sh = g_sh2[f];
    int g = bt[r0];
    float acc = 0.f, cnt = 0.f;
    for (int r = r0; r < r1; r++) {
        int gr = bt[r];
        if (gr != g) {
            atomicAdd(&g_pool[g * F + f], acc);
            if (f == 0) atomicAdd(&g_cnt[g], cnt);
            acc = 0.f; cnt = 0.f; g = gr;
        }
        acc += y[(size_t)r * F + f] * sc + sh;
        cnt += 1.f;
    }
    atomicAdd(&g_pool[g * F + f], acc);
    if (f == 0) atomicAdd(&g_cnt[g], cnt);
}

// --------------------------- MLP head + log softmax -------------------------
__global__ void mlp_head(const float* __restrict__ fc1w, const float* __restrict__ fc1b,
                         const float* __restrict__ fc2w, const float* __restrict__ fc2b,
                         float* __restrict__ out) {
    __shared__ float p[F];
    __shared__ float z[CC];
    __shared__ float l[NCLS];
    __shared__ float red[2];
    int g = blockIdx.x;
    int t = threadIdx.x;
    float inv = 1.f / fmaxf(g_cnt[g], 1.f);
    for (int k = t; k < F; k += 64) p[k] = g_pool[g * F + k] * inv;
    __syncthreads();
    float acc = fc1b[t];
    for (int k = 0; k < F; k++) acc += p[k] * fc1w[k * CC + t];
    z[t] = fmaxf(acc, 0.f);
    __syncthreads();
    if (t < NCLS) {
        float a = fc2b[t];
        for (int k = 0; k < CC; k++) a += z[k] * fc2w[k * NCLS + t];
        l[t] = a;
    }
    __syncthreads();
    if (t == 0) {
        float m = l[0];
        for (int i = 1; i < NCLS; i++) m = fmaxf(m, l[i]);
        float s = 0.f;
        for (int i = 0; i < NCLS; i++) s += expf(l[i] - m);
        red[0] = m; red[1] = logf(s);
    }
    __syncthreads();
    if (t < NCLS) out[g * NCLS + t] = l[t] - red[0] - red[1];
}

// ---------------------------------- launch ----------------------------------
extern "C" void kernel_launch(void* const* d_in, const int* in_sizes, int n_in,
                              void* d_out, int out_size) {
    const float* x    = (const float*)d_in[0];
    const int*   ei   = (const int*)  d_in[1];
    const int*   bat  = (const int*)  d_in[2];
    const float* W1   = (const float*)d_in[3];
    const float* as1  = (const float*)d_in[4];
    const float* ad1  = (const float*)d_in[5];
    const float* b1   = (const float*)d_in[6];
    const float* gm1  = (const float*)d_in[7];
    const float* be1  = (const float*)d_in[8];
    const float* W2   = (const float*)d_in[9];
    const float* as2  = (const float*)d_in[10];
    const float* ad2  = (const float*)d_in[11];
    const float* b2   = (const float*)d_in[12];
    const float* gm2  = (const float*)d_in[13];
    const float* be2  = (const float*)d_in[14];
    const float* fc1w = (const float*)d_in[15];
    const float* fc1b = (const float*)d_in[16];
    const float* fc2w = (const float*)d_in[17];
    const float* fc2b = (const float*)d_in[18];
    float* out = (float*)d_out;

    float *ph, *py1, *py2, *psc1, *psh1, *psc2, *psh2;
    cudaGetSymbolAddress((void**)&ph,   g_h);
    cudaGetSymbolAddress((void**)&py1,  g_y1);
    cudaGetSymbolAddress((void**)&py2,  g_y2);
    cudaGetSymbolAddress((void**)&psc1, g_sc1);
    cudaGetSymbolAddress((void**)&psh1, g_sh1);
    cudaGetSymbolAddress((void**)&psc2, g_sc2);
    cudaGetSymbolAddress((void**)&psh2, g_sh2);

    const int TPB = 256;
    const int nET = (ET + TPB - 1) / TPB;
    const int nCONV = NN / 8;                     // 6250
    dim3 mmGrid((NN + 127) / 128, 2);
    const int nAGG  = (NN + 8 * RPW - 1) / (8 * RPW);
    const int nPOOL = (NN + POOL_ROWS - 1) / POOL_ROWS;
    const int nZERO = (GG * F + TPB - 1) / TPB > (NN + TPB - 1) / TPB
                      ? (GG * F + TPB - 1) / TPB : (NN + TPB - 1) / TPB;

    // ---------------- CSR build ----------------
    csr_zero<<<nZERO, TPB>>>();
    csr_hist<<<nET, TPB>>>(ei);
    csr_scan<<<1, SCAN_T>>>();
    csr_scatter<<<nET, TPB>>>(ei);

    // ---------------- layer 1 ----------------
    conv_B<<<256, 256>>>(W1);
    conv_A<<<nCONV, 256>>>(x, NULL, NULL);
    gemm_bf16<<<mmGrid, 256>>>(ph, NN, as1, ad1);
    gat_agg<<<nAGG, 256>>>(b1, x, NULL, NULL, py1);
    bn_final<<<1, F>>>(gm1, be1, psc1, psh1);

    // ---------------- layer 2 ----------------
    conv_B<<<256, 256>>>(W2);
    conv_A<<<nCONV, 256>>>(py1, psc1, psh1);      // fused BN1 apply
    gemm_bf16<<<mmGrid, 256>>>(ph, NN, as2, ad2);
    gat_agg<<<nAGG, 256>>>(b2, py1, psc1, psh1, py2);
    bn_final<<<1, F>>>(gm2, be2, psc2, psh2);

    // ---------------- pool + head ----------------
    bn_pool<<<nPOOL, 256>>>(bat, py2);
    mlp_head<<<GG, 64>>>(fc1w, fc1b, fc2w, fc2b, out);
}

// round 6
// speedup vs baseline: 2.3602x; 1.0715x over previous
#include <cuda_runtime.h>
#include <cuda_bf16.h>
#include <math.h>
#include <stdint.h>

#define NN   50000
#define EE   400000
#define ET   (EE + NN)
#define F    256
#define HH   4
#define CC   64
#define GG   64
#define NCLS 10

// ---------------- scratch (static device globals; no allocations) -----------
__device__ float g_h[NN * F];
__device__ float g_y1[NN * F];
__device__ float g_y2[NN * F];
__device__ float g_asrc[NN * HH];
__device__ float g_adst[NN * HH];
__device__ float g_sum[F], g_sumsq[F];
__device__ float g_sc1[F], g_sh1[F];
__device__ float g_sc2[F], g_sh2[F];
__device__ float g_pool[GG * F];
__device__ float g_cnt[GG];
__device__ __align__(16) __nv_bfloat16 g_Bp[768 * 256];   // split W, stage-ordered
// CSR
__device__ int   g_cnt_n[NN];
__device__ int   g_rp[NN + 1];
__device__ int   g_col[ET];

// ---------------- bf16 pack helpers ------------------------------------------
__device__ __forceinline__ uint32_t pack_hi(float a, float b) {
    __nv_bfloat162 h = __floats2bfloat162_rn(a, b);
    return *(uint32_t*)&h;
}
__device__ __forceinline__ uint32_t pack_lo(float a, float b, uint32_t hi) {
    __nv_bfloat162 h = *(__nv_bfloat162*)&hi;
    __nv_bfloat162 l = __floats2bfloat162_rn(a - __bfloat162float(h.x),
                                             b - __bfloat162float(h.y));
    return *(uint32_t*)&l;
}

// ---- conv_B: W[256][256] -> B'[768][256], per 64-block j, per 32-half:
// rows [hi, hi, lo] so stages pair (A_hi*Bh, A_lo*Bh, A_hi*Bl) ------------------
__global__ void conv_B(const float* __restrict__ W) {
    int k = blockIdx.x, n = threadIdx.x;
    float v = W[k * 256 + n];
    __nv_bfloat16 hi = __float2bfloat16_rn(v);
    __nv_bfloat16 lo = __float2bfloat16_rn(v - __bfloat162float(hi));
    int j = k >> 6, kl = k & 63, half = kl >> 5, i = kl & 31;
    int base = j * 192 + half * 96 + i;
    g_Bp[(size_t)(base)      * 256 + n] = hi;
    g_Bp[(size_t)(base + 32) * 256 + n] = hi;
    g_Bp[(size_t)(base + 64) * 256 + n] = lo;
}

// ============ bf16 mma.sync GEMM, K'=768, inline A split, fused attn =========
#define PA 80
#define PB 272
#define ABUF (128 * PA)
#define BBUF (32 * PB)
#define STG  (ABUF + BBUF)

__device__ __forceinline__ uint32_t smem_u32(const void* p) {
    uint32_t a;
    asm("{ .reg .u64 t; cvta.to.shared.u64 t, %1; cvt.u32.u64 %0, t; }"
        : "=r"(a) : "l"(p));
    return a;
}
__device__ __forceinline__ void ldsm_x4(uint32_t* a, uint32_t addr) {
    asm volatile("ldmatrix.sync.aligned.m8n8.x4.shared.b16 {%0,%1,%2,%3}, [%4];"
                 : "=r"(a[0]), "=r"(a[1]), "=r"(a[2]), "=r"(a[3]) : "r"(addr));
}
__device__ __forceinline__ void ldsm_x2t(uint32_t* b, uint32_t addr) {
    asm volatile("ldmatrix.sync.aligned.m8n8.x2.trans.shared.b16 {%0,%1}, [%2];"
                 : "=r"(b[0]), "=r"(b[1]) : "r"(addr));
}
__device__ __forceinline__ void mma16816(float* d, const uint32_t* a,
                                         const uint32_t* b) {
    asm volatile(
        "mma.sync.aligned.m16n8k16.row.col.f32.bf16.bf16.f32 "
        "{%0,%1,%2,%3}, {%4,%5,%6,%7}, {%8,%9}, {%0,%1,%2,%3};"
        : "+f"(d[0]), "+f"(d[1]), "+f"(d[2]), "+f"(d[3])
        : "r"(a[0]), "r"(a[1]), "r"(a[2]), "r"(a[3]), "r"(b[0]), "r"(b[1]));
}
// load 16 fp32 A elements (opt. BN apply) and pre-pack hi
__device__ __forceinline__ void load_split(const float* agp32, int kbase, int sidx,
                                           const float* scale, const float* shift,
                                           bool ok, float* e, uint32_t* hp) {
    if (ok) {
#pragma unroll
        for (int i = 0; i < 4; i++) {
            float4 v = *(const float4*)(agp32 + kbase + i * 4);
            e[i * 4 + 0] = v.x; e[i * 4 + 1] = v.y;
            e[i * 4 + 2] = v.z; e[i * 4 + 3] = v.w;
        }
        if (scale) {
#pragma unroll
            for (int i = 0; i < 16; i++)
                e[i] = e[i] * scale[sidx + i] + shift[sidx + i];
        }
    } else {
#pragma unroll
        for (int i = 0; i < 16; i++) e[i] = 0.f;
    }
#pragma unroll
    for (int p = 0; p < 8; p++) hp[p] = pack_hi(e[2 * p], e[2 * p + 1]);
}

__global__ __launch_bounds__(256)
void gemm_bf16(const float* __restrict__ A, float* __restrict__ C, int M,
               const float* __restrict__ scale, const float* __restrict__ shift,
               const float* __restrict__ atts, const float* __restrict__ attd) {
    __shared__ __align__(16) char sm[2 * STG];
    const int t = threadIdx.x, lane = t & 31, w = t >> 5;
    const int wm = w & 1, wn = w >> 1;
    const int row0 = blockIdx.x * 128, col0 = blockIdx.y * 128;
    const uint32_t sb = smem_u32(sm);

    float acc[4][4][4];
#pragma unroll
    for (int i = 0; i < 4; i++)
#pragma unroll
        for (int j = 0; j < 4; j++)
#pragma unroll
            for (int k = 0; k < 4; k++) acc[i][j][k] = 0.f;

    // A roles: 128 rows x 32 fp32 cols per fresh load; thread -> (row, 16-col half)
    const int ar = t >> 1, apart = t & 1;
    const bool a_ok = (row0 + ar) < M;
    const float* agp32 = A + (size_t)(row0 + ar) * 256 + apart * 16;
    // B roles: 32 rows x 256 cols per stage (take 128 cols)
    const int br = t >> 3, bseg = t & 7;
    const __nv_bfloat16* bgp = g_Bp + (size_t)br * 256 + col0 + bseg * 16;

    float e[16];
    uint32_t hp[8];

    // prologue: stage 0 = hi of block0 cols [0,32)
    load_split(agp32, 0, apart * 16, scale, shift, a_ok, e, hp);
    {
        char* pa = sm + ar * PA + apart * 32;
        *(uint4*)pa = *(uint4*)&hp[0];
        *(uint4*)(pa + 16) = *(uint4*)&hp[4];
        uint4 lb0 = *(const uint4*)(bgp);
        uint4 lb1 = *(const uint4*)(bgp + 8);
        char* pb = sm + ABUF + br * PB + bseg * 32;
        *(uint4*)pb = lb0; *(uint4*)(pb + 16) = lb1;
    }
    __syncthreads();

    for (int s = 0; s < 24; s++) {
        const int buf = s & 1;
        const uint32_t sba = sb + buf * STG;
        const int sn = s + 1;
        const int rn = sn % 6;      // next stage type within its 64-block
        uint4 lb0, lb1;
        if (s < 23) {
            lb0 = *(const uint4*)(bgp + (size_t)(sn * 32) * 256);
            lb1 = *(const uint4*)(bgp + (size_t)(sn * 32) * 256 + 8);
            if (rn == 0 || rn == 3) {
                int kbase = (sn / 6) * 64 + (rn == 3 ? 32 : 0);
                load_split(agp32, kbase, kbase + apart * 16, scale, shift,
                           a_ok, e, hp);
            }
        }
#pragma unroll
        for (int kh = 0; kh < 2; kh++) {
            uint32_t afr[4][4], bfr[4][2];
#pragma unroll
            for (int mi = 0; mi < 4; mi++) {
                uint32_t addr = sba + (uint32_t)(wm * 64 + mi * 16 + (lane & 15)) * PA
                              + kh * 32 + (lane >> 4) * 16;
                ldsm_x4(afr[mi], addr);
            }
#pragma unroll
            for (int nf = 0; nf < 4; nf++) {
                uint32_t addr = sba + ABUF + (uint32_t)(kh * 16 + (lane & 15)) * PB
                              + (wn * 32 + nf * 8) * 2;
                ldsm_x2t(bfr[nf], addr);
            }
#pragma unroll
            for (int mi = 0; mi < 4; mi++)
#pragma unroll
                for (int nf = 0; nf < 4; nf++)
                    mma16816(acc[mi][nf], afr[mi], bfr[nf]);
        }
        if (s < 23) {
            char* base = sm + (buf ^ 1) * STG;
            char* pb = base + ABUF + br * PB + bseg * 32;
            *(uint4*)pb = lb0; *(uint4*)(pb + 16) = lb1;
            if (rn == 0 || rn == 3) {            // fresh hi
                char* pa = base + ar * PA + apart * 32;
                *(uint4*)pa = *(uint4*)&hp[0];
                *(uint4*)(pa + 16) = *(uint4*)&hp[4];
            } else if (rn == 1 || rn == 4) {     // lo from kept fp32
                uint32_t lp[8];
#pragma unroll
                for (int p = 0; p < 8; p++)
                    lp[p] = pack_lo(e[2 * p], e[2 * p + 1], hp[p]);
                char* pa = base + ar * PA + apart * 32;
                *(uint4*)pa = *(uint4*)&lp[0];
                *(uint4*)(pa + 16) = *(uint4*)&lp[4];
            }
            // rn == 2 || rn == 5: buffer already holds the right hi tile
        }
        __syncthreads();
    }

    // ---- epilogue: store C, per-warp att partials -> smem, combine ----------
    float* part = (float*)sm;   // [128 rows][4 wn][2 {src,dst}] = 4KB
#pragma unroll
    for (int mi = 0; mi < 4; mi++) {
        int lr_lo = wm * 64 + mi * 16 + (lane >> 2);
        int lr_hi = lr_lo + 8;
        int r_lo = row0 + lr_lo, r_hi = row0 + lr_hi;
        float ds0 = 0.f, dd0 = 0.f, ds1 = 0.f, dd1 = 0.f;
#pragma unroll
        for (int nf = 0; nf < 4; nf++) {
            int c = col0 + wn * 32 + nf * 8 + (lane & 3) * 2;
            float v0 = acc[mi][nf][0], v1 = acc[mi][nf][1];
            float v2 = acc[mi][nf][2], v3 = acc[mi][nf][3];
            if (r_lo < M) *(float2*)(C + (size_t)r_lo * 256 + c) = make_float2(v0, v1);
            if (r_hi < M) *(float2*)(C + (size_t)r_hi * 256 + c) = make_float2(v2, v3);
            float s0 = atts[c], s1 = atts[c + 1];
            float d0 = attd[c], d1 = attd[c + 1];
            ds0 += v0 * s0 + v1 * s1; dd0 += v0 * d0 + v1 * d1;
            ds1 += v2 * s0 + v3 * s1; dd1 += v2 * d0 + v3 * d1;
        }
#pragma unroll
        for (int o = 1; o <= 2; o <<= 1) {
            ds0 += __shfl_xor_sync(0xFFFFFFFFu, ds0, o);
            dd0 += __shfl_xor_sync(0xFFFFFFFFu, dd0, o);
            ds1 += __shfl_xor_sync(0xFFFFFFFFu, ds1, o);
            dd1 += __shfl_xor_sync(0xFFFFFFFFu, dd1, o);
        }
        if ((lane & 3) == 0) {
            part[(lr_lo * 4 + wn) * 2 + 0] = ds0;
            part[(lr_lo * 4 + wn) * 2 + 1] = dd0;
            part[(lr_hi * 4 + wn) * 2 + 0] = ds1;
            part[(lr_hi * 4 + wn) * 2 + 1] = dd1;
        }
    }
    __syncthreads();
    {
        int lr = t & 127, sd = t >> 7;
        int gr = row0 + lr;
        if (gr < M) {
            float* dst = sd ? g_adst : g_asrc;
#pragma unroll
            for (int hl = 0; hl < 2; hl++) {
                float v = part[(lr * 4 + 2 * hl) * 2 + sd]
                        + part[(lr * 4 + 2 * hl + 1) * 2 + sd];
                dst[gr * HH + (col0 >> 6) + hl] = v;
            }
        }
    }
}

// ------------------------------ CSR build -----------------------------------
__global__ void csr_zero() {
    int i = blockIdx.x * blockDim.x + threadIdx.x;
    if (i < NN) g_cnt_n[i] = 0;
    if (i < F)  { g_sum[i] = 0.f; g_sumsq[i] = 0.f; }
    if (i < GG * F) g_pool[i] = 0.f;
    if (i < GG) g_cnt[i] = 0.f;
}
__global__ void csr_hist(const int* __restrict__ ei) {
    int e = blockIdx.x * blockDim.x + threadIdx.x;
    if (e >= ET) return;
    int d = (e < EE) ? ei[EE + e] : e - EE;
    atomicAdd(&g_cnt_n[d], 1);
}
#define SCAN_T 1024
#define CHUNK  ((NN + SCAN_T - 1) / SCAN_T)
__global__ void csr_scan() {
    __shared__ int ps[SCAN_T];
    int t = threadIdx.x;
    int lo = t * CHUNK, hi = min(lo + CHUNK, NN);
    int s = 0;
    for (int i = lo; i < hi; i++) s += g_cnt_n[i];
    ps[t] = s;
    __syncthreads();
    for (int off = 1; off < SCAN_T; off <<= 1) {
        int v = (t >= off) ? ps[t - off] : 0;
        __syncthreads();
        ps[t] += v;
        __syncthreads();
    }
    int run = t ? ps[t - 1] : 0;
    for (int i = lo; i < hi; i++) {
        int c = g_cnt_n[i];
        g_rp[i] = run;
        g_cnt_n[i] = run;
        run += c;
    }
    if (hi == NN) g_rp[NN] = run;
}
__global__ void csr_scatter(const int* __restrict__ ei) {
    int e = blockIdx.x * blockDim.x + threadIdx.x;
    if (e >= ET) return;
    int s, d;
    if (e < EE) { s = ei[e]; d = ei[EE + e]; }
    else        { s = d = e - EE; }
    int pos = atomicAdd(&g_cnt_n[d], 1);
    g_col[pos] = s;
}

// ----- fused GAT aggregate + bias + ELU + residual(+BN) + BN stats -----------
#define RPW 4
__global__ __launch_bounds__(256)
void gat_agg(const float* __restrict__ b,
             const float* __restrict__ xin,
             const float* __restrict__ rscale,
             const float* __restrict__ rshift,
             float* __restrict__ y) {
    __shared__ float bsum[F], bsq[F];
    int t = threadIdx.x;
    bsum[t] = 0.f; bsq[t] = 0.f;
    __syncthreads();

    int lane = t & 31;
    int gwarp = blockIdx.x * 8 + (t >> 5);
    int c1 = lane << 2, c2 = 128 + (lane << 2);
    int h1 = lane >> 4, h2 = 2 + (lane >> 4);

    float4 bias1 = *(const float4*)(b + c1);
    float4 bias2 = *(const float4*)(b + c2);
    float sc1v = rscale ? rscale[c1] : 1.f, sh1v = rshift ? rshift[c1] : 0.f;
    float sc1y = rscale ? rscale[c1 + 1] : 1.f, sh1y = rshift ? rshift[c1 + 1] : 0.f;
    float sc1z = rscale ? rscale[c1 + 2] : 1.f, sh1z = rshift ? rshift[c1 + 2] : 0.f;
    float sc1w = rscale ? rscale[c1 + 3] : 1.f, sh1w = rshift ? rshift[c1 + 3] : 0.f;
    float sc2v = rscale ? rscale[c2] : 1.f, sh2v = rshift ? rshift[c2] : 0.f;
    float sc2y = rscale ? rscale[c2 + 1] : 1.f, sh2y = rshift ? rshift[c2 + 1] : 0.f;
    float sc2z = rscale ? rscale[c2 + 2] : 1.f, sh2z = rshift ? rshift[c2 + 2] : 0.f;
    float sc2w = rscale ? rscale[c2 + 3] : 1.f, sh2w = rshift ? rshift[c2 + 3] : 0.f;

    float ss[8] = {0,0,0,0,0,0,0,0};
    float sq[8] = {0,0,0,0,0,0,0,0};

#pragma unroll
    for (int rr = 0; rr < RPW; rr++) {
        int d = gwarp * RPW + rr;
        if (d >= NN) break;
        float ad1 = g_adst[d * HH + h1];
        float ad2 = g_adst[d * HH + h2];
        float acc1x = 0.f, acc1y = 0.f, acc1z = 0.f, acc1w = 0.f;
        float acc2x = 0.f, acc2y = 0.f, acc2z = 0.f, acc2w = 0.f;
        float den1 = 0.f, den2 = 0.f;
        int e0 = g_rp[d], e1 = g_rp[d + 1];
        for (int e = e0; e < e1; e++) {
            int s = g_col[e];
            float v1 = g_asrc[s * HH + h1] + ad1;
            float v2 = g_asrc[s * HH + h2] + ad2;
            v1 = v1 > 0.f ? v1 : 0.2f * v1;
            v2 = v2 > 0.f ? v2 : 0.2f * v2;
            float ex1 = __expf(v1);
            float ex2 = __expf(v2);
            den1 += ex1; den2 += ex2;
            const float* hp售 = g_h + (size_t)s * F;
            const float* hp = hp售;
            float4 w1 = *(const float4*)(hp + c1);
            float4 w2 = *(const float4*)(hp + c2);
            acc1x += ex1 * w1.x; acc1y += ex1 * w1.y;
            acc1z += ex1 * w1.z; acc1w += ex1 * w1.w;
            acc2x += ex2 * w2.x; acc2y += ex2 * w2.y;
            acc2z += ex2 * w2.z; acc2w += ex2 * w2.w;
        }
        float i1 = __fdividef(1.f, den1);
        float i2 = __fdividef(1.f, den2);
        const float* xp = xin + (size_t)d * F;
        float4 x1 = *(const float4*)(xp + c1);
        float4 x2 = *(const float4*)(xp + c2);
        float o[8];
        o[0] = acc1x * i1 + bias1.x; o[1] = acc1y * i1 + bias1.y;
        o[2] = acc1z * i1 + bias1.z; o[3] = acc1w * i1 + bias1.w;
        o[4] = acc2x * i2 + bias2.x; o[5] = acc2y * i2 + bias2.y;
        o[6] = acc2z * i2 + bias2.z; o[7] = acc2w * i2 + bias2.w;
#pragma unroll
        for (int jj = 0; jj < 8; jj++) o[jj] = o[jj] > 0.f ? o[jj] : expm1f(o[jj]);
        o[0] += x1.x * sc1v + sh1v; o[1] += x1.y * sc1y + sh1y;
        o[2] += x1.z * sc1z + sh1z; o[3] += x1.w * sc1w + sh1w;
        o[4] += x2.x * sc2v + sh2v; o[5] += x2.y * sc2y + sh2y;
        o[6] += x2.z * sc2z + sh2z; o[7] += x2.w * sc2w + sh2w;
        float* yp = y + (size_t)d * F;
        *(float4*)(yp + c1) = make_float4(o[0], o[1], o[2], o[3]);
        *(float4*)(yp + c2) = make_float4(o[4], o[5], o[6], o[7]);
#pragma unroll
        for (int jj = 0; jj < 8; jj++) { ss[jj] += o[jj]; sq[jj] += o[jj] * o[jj]; }
    }
#pragma unroll
    for (int jj = 0; jj < 4; jj++) {
        atomicAdd(&bsum[c1 + jj], ss[jj]);
        atomicAdd(&bsq[c1 + jj],  sq[jj]);
        atomicAdd(&bsum[c2 + jj], ss[4 + jj]);
        atomicAdd(&bsq[c2 + jj],  sq[4 + jj]);
    }
    __syncthreads();
    atomicAdd(&g_sum[t],   bsum[t]);
    atomicAdd(&g_sumsq[t], bsq[t]);
}

__global__ void bn_final(const float* __restrict__ gm, const float* __restrict__ bt,
                         float* __restrict__ sc_out, float* __restrict__ sh_out) {
    int f = threadIdx.x;
    float mu  = g_sum[f] / (float)NN;
    float var = g_sumsq[f] / (float)NN - mu * mu;
    float sc  = gm[f] * rsqrtf(var + 1e-5f);
    sc_out[f] = sc;
    sh_out[f] = bt[f] - mu * sc;
    g_sum[f] = 0.f; g_sumsq[f] = 0.f;
}

// -------------- fused: BN2 apply + global mean pool (sorted batch) -----------
#define POOL_ROWS 512
__global__ void bn_pool(const int* __restrict__ bt, const float* __restrict__ y) {
    int f  = threadIdx.x;
    int r0 = blockIdx.x * POOL_ROWS;
    int r1 = min(r0 + POOL_ROWS, NN);
    if (r0 >= NN) return;
    float sc = g_sc2[f], sh = g_sh2[f];
    int g = bt[r0];
    float acc = 0.f, cnt = 0.f;
    for (int r = r0; r < r1; r++) {
        int gr = bt[r];
        if (gr != g) {
            atomicAdd(&g_pool[g * F + f], acc);
            if (f == 0) atomicAdd(&g_cnt[g], cnt);
            acc = 0.f; cnt = 0.f; g = gr;
        }
        acc += y[(size_t)r * F + f] * sc + sh;
        cnt += 1.f;
    }
    atomicAdd(&g_pool[g * F + f], acc);
    if (f == 0) atomicAdd(&g_cnt[g], cnt);
}

// --------------------------- MLP head + log softmax -------------------------
__global__ void mlp_head(const float* __restrict__ fc1w, const float* __restrict__ fc1b,
                         const float* __restrict__ fc2w, const float* __restrict__ fc2b,
                         float* __restrict__ out) {
    __shared__ float p[F];
    __shared__ float z[CC];
    __shared__ float l[NCLS];
    __shared__ float red[2];
    int g = blockIdx.x;
    int t = threadIdx.x;
    float inv = 1.f / fmaxf(g_cnt[g], 1.f);
    for (int k = t; k < F; k += 64) p[k] = g_pool[g * F + k] * inv;
    __syncthreads();
    float acc = fc1b[t];
    for (int k = 0; k < F; k++) acc += p[k] * fc1w[k * CC + t];
    z[t] = fmaxf(acc, 0.f);
    __syncthreads();
    if (t < NCLS) {
        float a = fc2b[t];
        for (int k = 0; k < CC; k++) a += z[k] * fc2w[k * NCLS + t];
        l[t] = a;
    }
    __syncthreads();
    if (t == 0) {
        float m = l[0];
        for (int i = 1; i < NCLS; i++) m = fmaxf(m, l[i]);
        float s = 0.f;
        for (int i = 0; i < NCLS; i++) s += expf(l[i] - m);
        red[0] = m; red[1] = logf(s);
    }
    __syncthreads();
    if (t < NCLS) out[g * NCLS + t] = l[t] - red[0] - red[1];
}

// ---------------------------------- launch ----------------------------------
extern "C" void kernel_launch(void* const* d_in, const int* in_sizes, int n_in,
                              void* d_out, int out_size) {
    const float* x    = (const float*)d_in[0];
    const int*   ei   = (const int*)  d_in[1];
    const int*   bat  = (const int*)  d_in[2];
    const float* W1   = (const float*)d_in[3];
    const float* as1  = (const float*)d_in[4];
    const float* ad1  = (const float*)d_in[5];
    const float* b1   = (const float*)d_in[6];
    const float* gm1  = (const float*)d_in[7];
    const float* be1  = (const float*)d_in[8];
    const float* W2   = (const float*)d_in[9];
    const float* as2  = (const float*)d_in[10];
    const float* ad2  = (const float*)d_in[11];
    const float* b2   = (const float*)d_in[12];
    const float* gm2  = (const float*)d_in[13];
    const float* be2  = (const float*)d_in[14];
    const float* fc1w = (const float*)d_in[15];
    const float* fc1b = (const float*)d_in[16];
    const float* fc2w = (const float*)d_in[17];
    const float* fc2b = (const float*)d_in[18];
    float* out = (float*)d_out;

    float *ph, *py1, *py2, *psc1, *psh1, *psc2, *psh2;
    cudaGetSymbolAddress((void**)&ph,   g_h);
    cudaGetSymbolAddress((void**)&py1,  g_y1);
    cudaGetSymbolAddress((void**)&py2,  g_y2);
    cudaGetSymbolAddress((void**)&psc1, g_sc1);
    cudaGetSymbolAddress((void**)&psh1, g_sh1);
    cudaGetSymbolAddress((void**)&psc2, g_sc2);
    cudaGetSymbolAddress((void**)&psh2, g_sh2);

    const int TPB = 256;
    const int nET = (ET + TPB - 1) / TPB;
    dim3 mmGrid((NN + 127) / 128, 2);
    const int nAGG  = (NN + 8 * RPW - 1) / (8 * RPW);
    const int nPOOL = (NN + POOL_ROWS - 1) / POOL_ROWS;
    const int nZERO = (GG * F + TPB - 1) / TPB > (NN + TPB - 1) / TPB
                      ? (GG * F + TPB - 1) / TPB : (NN + TPB - 1) / TPB;

    // ---------------- CSR build ----------------
    csr_zero<<<nZERO, TPB>>>();
    csr_hist<<<nET, TPB>>>(ei);
    csr_scan<<<1, SCAN_T>>>();
    csr_scatter<<<nET, TPB>>>(ei);

    // ---------------- layer 1 ----------------
    conv_B<<<256, 256>>>(W1);
    gemm_bf16<<<mmGrid, 256>>>(x, ph, NN, NULL, NULL, as1, ad1);
    gat_agg<<<nAGG, 256>>>(b1, x, NULL, NULL, py1);
    bn_final<<<1, F>>>(gm1, be1, psc1, psh1);

    // ---------------- layer 2 ----------------
    conv_B<<<256, 256>>>(W2);
    gemm_bf16<<<mmGrid, 256>>>(py1, ph, NN, psc1, psh1, as2, ad2);
    gat_agg<<<nAGG, 256>>>(b2, py1, psc1, psh1, py2);
    bn_final<<<1, F>>>(gm2, be2, psc2, psh2);

    // ---------------- pool + head ----------------
    bn_pool<<<nPOOL, 256>>>(bat, py2);
    mlp_head<<<GG, 64>>>(fc1w, fc1b, fc2w, fc2b, out);
}

// round 7
// speedup vs baseline: 2.3967x; 1.0155x over previous
#include <cuda_runtime.h>
#include <cuda_bf16.h>
#include <cuda_fp16.h>
#include <math.h>
#include <stdint.h>

#define NN   50000
#define EE   400000
#define ET   (EE + NN)
#define F    256
#define HH   4
#define CC   64
#define GG   64
#define NCLS 10

// ---------------- scratch (static device globals; no allocations) -----------
__device__ __align__(16) __half g_hh[(size_t)NN * F];   // h = A' @ W, fp16
__device__ float g_y1[NN * F];
__device__ float g_y2[NN * F];
__device__ float g_asrc[NN * HH];
__device__ float g_adst[NN * HH];
__device__ float g_sum[F], g_sumsq[F];
__device__ float g_sc1[F], g_sh1[F];
__device__ float g_sc2[F], g_sh2[F];
__device__ float g_pool[GG * F];
__device__ float g_cnt[GG];
__device__ __align__(16) __nv_bfloat16 g_Bp[768 * 256];   // split W, stage-ordered
// CSR
__device__ int   g_cnt_n[NN];
__device__ int   g_rp[NN + 1];
__device__ int   g_col[ET];

// ---------------- bf16 pack helpers ------------------------------------------
__device__ __forceinline__ uint32_t pack_hi(float a, float b) {
    __nv_bfloat162 h = __floats2bfloat162_rn(a, b);
    return *(uint32_t*)&h;
}
__device__ __forceinline__ uint32_t pack_lo(float a, float b, uint32_t hi) {
    __nv_bfloat162 h = *(__nv_bfloat162*)&hi;
    __nv_bfloat162 l = __floats2bfloat162_rn(a - __bfloat162float(h.x),
                                             b - __bfloat162float(h.y));
    return *(uint32_t*)&l;
}

// ---- conv_B: W[256][256] -> B'[768][256], per 64-block j, per 32-half:
// rows [hi, hi, lo] so stages pair (A_hi*Bh, A_lo*Bh, A_hi*Bl) ------------------
__global__ void conv_B(const float* __restrict__ W) {
    int k = blockIdx.x, n = threadIdx.x;
    float v = W[k * 256 + n];
    __nv_bfloat16 hi = __float2bfloat16_rn(v);
    __nv_bfloat16 lo = __float2bfloat16_rn(v - __bfloat162float(hi));
    int j = k >> 6, kl = k & 63, half = kl >> 5, i = kl & 31;
    int base = j * 192 + half * 96 + i;
    g_Bp[(size_t)(base)      * 256 + n] = hi;
    g_Bp[(size_t)(base + 32) * 256 + n] = hi;
    g_Bp[(size_t)(base + 64) * 256 + n] = lo;
}

// ============ bf16 mma.sync GEMM, K'=768, inline A split, fused attn =========
#define PA 80
#define PB 272
#define ABUF (128 * PA)
#define BBUF (32 * PB)
#define STG  (ABUF + BBUF)

__device__ __forceinline__ uint32_t smem_u32(const void* p) {
    uint32_t a;
    asm("{ .reg .u64 t; cvta.to.shared.u64 t, %1; cvt.u32.u64 %0, t; }"
        : "=r"(a) : "l"(p));
    return a;
}
__device__ __forceinline__ void ldsm_x4(uint32_t* a, uint32_t addr) {
    asm volatile("ldmatrix.sync.aligned.m8n8.x4.shared.b16 {%0,%1,%2,%3}, [%4];"
                 : "=r"(a[0]), "=r"(a[1]), "=r"(a[2]), "=r"(a[3]) : "r"(addr));
}
__device__ __forceinline__ void ldsm_x2t(uint32_t* b, uint32_t addr) {
    asm volatile("ldmatrix.sync.aligned.m8n8.x2.trans.shared.b16 {%0,%1}, [%2];"
                 : "=r"(b[0]), "=r"(b[1]) : "r"(addr));
}
__device__ __forceinline__ void mma16816(float* d, const uint32_t* a,
                                         const uint32_t* b) {
    asm volatile(
        "mma.sync.aligned.m16n8k16.row.col.f32.bf16.bf16.f32 "
        "{%0,%1,%2,%3}, {%4,%5,%6,%7}, {%8,%9}, {%0,%1,%2,%3};"
        : "+f"(d[0]), "+f"(d[1]), "+f"(d[2]), "+f"(d[3])
        : "r"(a[0]), "r"(a[1]), "r"(a[2]), "r"(a[3]), "r"(b[0]), "r"(b[1]));
}
__device__ __forceinline__ void load_split(const float* agp32, int kbase, int sidx,
                                           const float* scale, const float* shift,
                                           bool ok, float* e, uint32_t* hp) {
    if (ok) {
#pragma unroll
        for (int i = 0; i < 4; i++) {
            float4 v = *(const float4*)(agp32 + kbase + i * 4);
            e[i * 4 + 0] = v.x; e[i * 4 + 1] = v.y;
            e[i * 4 + 2] = v.z; e[i * 4 + 3] = v.w;
        }
        if (scale) {
#pragma unroll
            for (int i = 0; i < 16; i++)
                e[i] = e[i] * scale[sidx + i] + shift[sidx + i];
        }
    } else {
#pragma unroll
        for (int i = 0; i < 16; i++) e[i] = 0.f;
    }
#pragma unroll
    for (int p = 0; p < 8; p++) hp[p] = pack_hi(e[2 * p], e[2 * p + 1]);
}

__global__ __launch_bounds__(256)
void gemm_bf16(const float* __restrict__ A, __half* __restrict__ C, int M,
               const float* __restrict__ scale, const float* __restrict__ shift,
               const float* __restrict__ atts, const float* __restrict__ attd) {
    __shared__ __align__(16) char sm[2 * STG];
    const int t = threadIdx.x, lane = t & 31, w = t >> 5;
    const int wm = w & 1, wn = w >> 1;
    const int row0 = blockIdx.x * 128, col0 = blockIdx.y * 128;
    const uint32_t sb = smem_u32(sm);

    float acc[4][4][4];
#pragma unroll
    for (int i = 0; i < 4; i++)
#pragma unroll
        for (int j = 0; j < 4; j++)
#pragma unroll
            for (int k = 0; k < 4; k++) acc[i][j][k] = 0.f;

    const int ar = t >> 1, apart = t & 1;
    const bool a_ok = (row0 + ar) < M;
    const float* agp32 = A + (size_t)(row0 + ar) * 256 + apart * 16;
    const int br = t >> 3, bseg = t & 7;
    const __nv_bfloat16* bgp = g_Bp + (size_t)br * 256 + col0 + bseg * 16;

    float e[16];
    uint32_t hp[8];

    load_split(agp32, 0, apart * 16, scale, shift, a_ok, e, hp);
    {
        char* pa = sm + ar * PA + apart * 32;
        *(uint4*)pa = *(uint4*)&hp[0];
        *(uint4*)(pa + 16) = *(uint4*)&hp[4];
        uint4 lb0 = *(const uint4*)(bgp);
        uint4 lb1 = *(const uint4*)(bgp + 8);
        char* pb = sm + ABUF + br * PB + bseg * 32;
        *(uint4*)pb = lb0; *(uint4*)(pb + 16) = lb1;
    }
    __syncthreads();

    for (int s = 0; s < 24; s++) {
        const int buf = s & 1;
        const uint32_t sba = sb + buf * STG;
        const int sn = s + 1;
        const int rn = sn % 6;
        uint4 lb0, lb1;
        if (s < 23) {
            lb0 = *(const uint4*)(bgp + (size_t)(sn * 32) * 256);
            lb1 = *(const uint4*)(bgp + (size_t)(sn * 32) * 256 + 8);
            if (rn == 0 || rn == 3) {
                int kbase = (sn / 6) * 64 + (rn == 3 ? 32 : 0);
                load_split(agp32, kbase, kbase + apart * 16, scale, shift,
                           a_ok, e, hp);
            }
        }
#pragma unroll
        for (int kh = 0; kh < 2; kh++) {
            uint32_t afr[4][4], bfr[4][2];
#pragma unroll
            for (int mi = 0; mi < 4; mi++) {
                uint32_t addr = sba + (uint32_t)(wm * 64 + mi * 16 + (lane & 15)) * PA
                              + kh * 32 + (lane >> 4) * 16;
                ldsm_x4(afr[mi], addr);
            }
#pragma unroll
            for (int nf = 0; nf < 4; nf++) {
                uint32_t addr = sba + ABUF + (uint32_t)(kh * 16 + (lane & 15)) * PB
                              + (wn * 32 + nf * 8) * 2;
                ldsm_x2t(bfr[nf], addr);
            }
#pragma unroll
            for (int mi = 0; mi < 4; mi++)
#pragma unroll
                for (int nf = 0; nf < 4; nf++)
                    mma16816(acc[mi][nf], afr[mi], bfr[nf]);
        }
        if (s < 23) {
            char* base = sm + (buf ^ 1) * STG;
            char* pb = base + ABUF + br * PB + bseg * 32;
            *(uint4*)pb = lb0; *(uint4*)(pb + 16) = lb1;
            if (rn == 0 || rn == 3) {
                char* pa = base + ar * PA + apart * 32;
                *(uint4*)pa = *(uint4*)&hp[0];
                *(uint4*)(pa + 16) = *(uint4*)&hp[4];
            } else if (rn == 1 || rn == 4) {
                uint32_t lp[8];
#pragma unroll
                for (int p = 0; p < 8; p++)
                    lp[p] = pack_lo(e[2 * p], e[2 * p + 1], hp[p]);
                char* pa = base + ar * PA + apart * 32;
                *(uint4*)pa = *(uint4*)&lp[0];
                *(uint4*)(pa + 16) = *(uint4*)&lp[4];
            }
        }
        __syncthreads();
    }

    // ---- epilogue: store C (fp16), per-warp att partials -> smem, combine ---
    float* part = (float*)sm;
#pragma unroll
    for (int mi = 0; mi < 4; mi++) {
        int lr_lo = wm * 64 + mi * 16 + (lane >> 2);
        int lr_hi = lr_lo + 8;
        int r_lo = row0 + lr_lo, r_hi = row0 + lr_hi;
        float ds0 = 0.f, dd0 = 0.f, ds1 = 0.f, dd1 = 0.f;
#pragma unroll
        for (int nf = 0; nf < 4; nf++) {
            int c = col0 + wn * 32 + nf * 8 + (lane & 3) * 2;
            float v0 = acc[mi][nf][0], v1 = acc[mi][nf][1];
            float v2 = acc[mi][nf][2], v3 = acc[mi][nf][3];
            if (r_lo < M) *(__half2*)(C + (size_t)r_lo * 256 + c) = __floats2half2_rn(v0, v1);
            if (r_hi < M) *(__half2*)(C + (size_t)r_hi * 256 + c) = __floats2half2_rn(v2, v3);
            float s0 = atts[c], s1 = atts[c + 1];
            float d0 = attd[c], d1 = attd[c + 1];
            ds0 += v0 * s0 + v1 * s1; dd0 += v0 * d0 + v1 * d1;
            ds1 += v2 * s0 + v3 * s1; dd1 += v2 * d0 + v3 * d1;
        }
#pragma unroll
        for (int o = 1; o <= 2; o <<= 1) {
            ds0 += __shfl_xor_sync(0xFFFFFFFFu, ds0, o);
            dd0 += __shfl_xor_sync(0xFFFFFFFFu, dd0, o);
            ds1 += __shfl_xor_sync(0xFFFFFFFFu, ds1, o);
            dd1 += __shfl_xor_sync(0xFFFFFFFFu, dd1, o);
        }
        if ((lane & 3) == 0) {
            part[(lr_lo * 4 + wn) * 2 + 0] = ds0;
            part[(lr_lo * 4 + wn) * 2 + 1] = dd0;
            part[(lr_hi * 4 + wn) * 2 + 0] = ds1;
            part[(lr_hi * 4 + wn) * 2 + 1] = dd1;
        }
    }
    __syncthreads();
    {
        int lr = t & 127, sd = t >> 7;
        int gr = row0 + lr;
        if (gr < M) {
            float* dst = sd ? g_adst : g_asrc;
#pragma unroll
            for (int hl = 0; hl < 2; hl++) {
                float v = part[(lr * 4 + 2 * hl) * 2 + sd]
                        + part[(lr * 4 + 2 * hl + 1) * 2 + sd];
                dst[gr * HH + (col0 >> 6) + hl] = v;
            }
        }
    }
}

// ------------------------------ CSR build -----------------------------------
__global__ void csr_zero() {
    int i = blockIdx.x * blockDim.x + threadIdx.x;
    if (i < NN) g_cnt_n[i] = 0;
    if (i < F)  { g_sum[i] = 0.f; g_sumsq[i] = 0.f; }
    if (i < GG * F) g_pool[i] = 0.f;
    if (i < GG) g_cnt[i] = 0.f;
}
__global__ void csr_hist(const int* __restrict__ ei) {
    int e = blockIdx.x * blockDim.x + threadIdx.x;
    if (e >= ET) return;
    int d = (e < EE) ? ei[EE + e] : e - EE;
    atomicAdd(&g_cnt_n[d], 1);
}
#define SCAN_T 1024
#define CHUNK  ((NN + SCAN_T - 1) / SCAN_T)
__global__ void csr_scan() {
    __shared__ int ps[SCAN_T];
    int t = threadIdx.x;
    int lo = t * CHUNK, hi = min(lo + CHUNK, NN);
    int s = 0;
    for (int i = lo; i < hi; i++) s += g_cnt_n[i];
    ps[t] = s;
    __syncthreads();
    for (int off = 1; off < SCAN_T; off <<= 1) {
        int v = (t >= off) ? ps[t - off] : 0;
        __syncthreads();
        ps[t] += v;
        __syncthreads();
    }
    int run = t ? ps[t - 1] : 0;
    for (int i = lo; i < hi; i++) {
        int c = g_cnt_n[i];
        g_rp[i] = run;
        g_cnt_n[i] = run;
        run += c;
    }
    if (hi == NN) g_rp[NN] = run;
}
__global__ void csr_scatter(const int* __restrict__ ei) {
    int e = blockIdx.x * blockDim.x + threadIdx.x;
    if (e >= ET) return;
    int s, d;
    if (e < EE) { s = ei[e]; d = ei[EE + e]; }
    else        { s = d = e - EE; }
    int pos = atomicAdd(&g_cnt_n[d], 1);
    g_col[pos] = s;
}

// ----- fused GAT aggregate + bias + ELU + residual(+BN) + BN stats -----------
// One warp per (dst-row, 128-col half): lane covers 4 cols, head = hf*2+(lane>>4)
#define RPW 4
__global__ __launch_bounds__(256)
void gat_agg(const float* __restrict__ b,
             const float* __restrict__ xin,
             const float* __restrict__ rscale,
             const float* __restrict__ rshift,
             float* __restrict__ y) {
    __shared__ float bsum[F], bsq[F];
    int t = threadIdx.x;
    bsum[t] = 0.f; bsq[t] = 0.f;
    __syncthreads();

    int lane = t & 31;
    int gwarp = blockIdx.x * 8 + (t >> 5);
    int hf = gwarp & 1;                     // which 128-col half
    int d0 = (gwarp >> 1) * RPW;
    int c = hf * 128 + (lane << 2);         // 4 consecutive cols
    int h = hf * 2 + (lane >> 4);           // head

    float4 bias = *(const float4*)(b + c);
    float scv = rscale ? rscale[c] : 1.f,     shv = rshift ? rshift[c] : 0.f;
    float scy = rscale ? rscale[c + 1] : 1.f, shy = rshift ? rshift[c + 1] : 0.f;
    float scz = rscale ? rscale[c + 2] : 1.f, shz = rshift ? rshift[c + 2] : 0.f;
    float scw = rscale ? rscale[c + 3] : 1.f, shw = rshift ? rshift[c + 3] : 0.f;

    float ss[4] = {0, 0, 0, 0};
    float sq[4] = {0, 0, 0, 0};

#pragma unroll
    for (int rr = 0; rr < RPW; rr++) {
        int d = d0 + rr;
        if (d >= NN) break;
        float ad = g_adst[d * HH + h];
        float ax = 0.f, ay = 0.f, az = 0.f, aw = 0.f;
        float den = 0.f;
        int e0 = g_rp[d], e1 = g_rp[d + 1];
        for (int e = e0; e < e1; e++) {
            int s = g_col[e];
            float v = g_asrc[s * HH + h] + ad;
            v = v > 0.f ? v : 0.2f * v;
            float ex = __expf(v);
            den += ex;
            uint2 u = *(const uint2*)(g_hh + (size_t)s * F + c);
            float2 f0 = __half22float2(*(__half2*)&u.x);
            float2 f1 = __half22float2(*(__half2*)&u.y);
            ax += ex * f0.x; ay += ex * f0.y;
            az += ex * f1.x; aw += ex * f1.y;
        }
        float inv = __fdividef(1.f, den);
        float4 xr = *(const float4*)(xin + (size_t)d * F + c);
        float o[4];
        o[0] = ax * inv + bias.x; o[1] = ay * inv + bias.y;
        o[2] = az * inv + bias.z; o[3] = aw * inv + bias.w;
#pragma unroll
        for (int j = 0; j < 4; j++) o[j] = o[j] > 0.f ? o[j] : expm1f(o[j]);
        o[0] += xr.x * scv + shv; o[1] += xr.y * scy + shy;
        o[2] += xr.z * scz + shz; o[3] += xr.w * scw + shw;
        *(float4*)(y + (size_t)d * F + c) = make_float4(o[0], o[1], o[2], o[3]);
#pragma unroll
        for (int j = 0; j < 4; j++) { ss[j] += o[j]; sq[j] += o[j] * o[j]; }
    }
#pragma unroll
    for (int j = 0; j < 4; j++) {
        atomicAdd(&bsum[c + j], ss[j]);
        atomicAdd(&bsq[c + j],  sq[j]);
    }
    __syncthreads();
    atomicAdd(&g_sum[t],   bsum[t]);
    atomicAdd(&g_sumsq[t], bsq[t]);
}

__global__ void bn_final(const float* __restrict__ gm, const float* __restrict__ bt,
                         float* __restrict__ sc_out, float* __restrict__ sh_out) {
    int f = threadIdx.x;
    float mu  = g_sum[f] / (float)NN;
    float var = g_sumsq[f] / (float)NN - mu * mu;
    float sc  = gm[f] * rsqrtf(var + 1e-5f);
    sc_out[f] = sc;
    sh_out[f] = bt[f] - mu * sc;
    g_sum[f] = 0.f; g_sumsq[f] = 0.f;
}

// -------------- fused: BN2 apply + global mean pool (sorted batch) -----------
#define POOL_ROWS 512
__global__ void bn_pool(const int* __restrict__ bt, const float* __restrict__ y) {
    int f  = threadIdx.x;
    int r0 = blockIdx.x * POOL_ROWS;
    int r1 = min(r0 + POOL_ROWS, NN);
    if (r0 >= NN) return;
    float sc = g_sc2[f], sh = g_sh2[f];
    int g = bt[r0];
    float acc = 0.f, cnt = 0.f;
    for (int r = r0; r < r1; r++) {
        int gr = bt[r];
        if (gr != g) {
            atomicAdd(&g_pool[g * F + f], acc);
            if (f == 0) atomicAdd(&g_cnt[g], cnt);
            acc = 0.f; cnt = 0.f; g = gr;
        }
        acc += y[(size_t)r * F + f] * sc + sh;
        cnt += 1.f;
    }
    atomicAdd(&g_pool[g * F + f], acc);
    if (f == 0) atomicAdd(&g_cnt[g], cnt);
}

// --------------------------- MLP head + log softmax -------------------------
__global__ void mlp_head(const float* __restrict__ fc1w, const float* __restrict__ fc1b,
                         const float* __restrict__ fc2w, const float* __restrict__ fc2b,
                         float* __restrict__ out) {
    __shared__ float p[F];
    __shared__ float z[CC];
    __shared__ float l[NCLS];
    __shared__ float red[2];
    int g = blockIdx.x;
    int t = threadIdx.x;
    float inv = 1.f / fmaxf(g_cnt[g], 1.f);
    for (int k = t; k < F; k += 64) p[k] = g_pool[g * F + k] * inv;
    __syncthreads();
    float acc = fc1b[t];
    for (int k = 0; k < F; k++) acc += p[k] * fc1w[k * CC + t];
    z[t] = fmaxf(acc, 0.f);
    __syncthreads();
    if (t < NCLS) {
        float a = fc2b[t];
        for (int k = 0; k < CC; k++) a += z[k] * fc2w[k * NCLS + t];
        l[t] = a;
    }
    __syncthreads();
    if (t == 0) {
        float m = l[0];
        for (int i = 1; i < NCLS; i++) m = fmaxf(m, l[i]);
        float s = 0.f;
        for (int i = 0; i < NCLS; i++) s += expf(l[i] - m);
        red[0] = m; red[1] = logf(s);
    }
    __syncthreads();
    if (t < NCLS) out[g * NCLS + t] = l[t] - red[0] - red[1];
}

// ---------------------------------- launch ----------------------------------
extern "C" void kernel_launch(void* const* d_in, const int* in_sizes, int n_in,
                              void* d_out, int out_size) {
    const float* x    = (const float*)d_in[0];
    const int*   ei   = (const int*)  d_in[1];
    const int*   bat  = (const int*)  d_in[2];
    const float* W1   = (const float*)d_in[3];
    const float* as1  = (const float*)d_in[4];
    const float* ad1  = (const float*)d_in[5];
    const float* b1   = (const float*)d_in[6];
    const float* gm1  = (const float*)d_in[7];
    const float* be1  = (const float*)d_in[8];
    const float* W2   = (const float*)d_in[9];
    const float* as2  = (const float*)d_in[10];
    const float* ad2  = (const float*)d_in[11];
    const float* b2   = (const float*)d_in[12];
    const float* gm2  = (const float*)d_in[13];
    const float* be2  = (const float*)d_in[14];
    const float* fc1w = (const float*)d_in[15];
    const float* fc1b = (const float*)d_in[16];
    const float* fc2w = (const float*)d_in[17];
    const float* fc2b = (const float*)d_in[18];
    float* out = (float*)d_out;

    __half* phh;
    float *py1, *py2, *psc1, *psh1, *psc2, *psh2;
    cudaGetSymbolAddress((void**)&phh,  g_hh);
    cudaGetSymbolAddress((void**)&py1,  g_y1);
    cudaGetSymbolAddress((void**)&py2,  g_y2);
    cudaGetSymbolAddress((void**)&psc1, g_sc1);
    cudaGetSymbolAddress((void**)&psh1, g_sh1);
    cudaGetSymbolAddress((void**)&psc2, g_sc2);
    cudaGetSymbolAddress((void**)&psh2, g_sh2);

    const int TPB = 256;
    const int nET = (ET + TPB - 1) / TPB;
    dim3 mmGrid((NN + 127) / 128, 2);
    const int nAGG  = (2 * NN + 8 * RPW - 1) / (8 * RPW);
    const int nPOOL = (NN + POOL_ROWS - 1) / POOL_ROWS;
    const int nZERO = (GG * F + TPB - 1) / TPB > (NN + TPB - 1) / TPB
                      ? (GG * F + TPB - 1) / TPB : (NN + TPB - 1) / TPB;

    // ---------------- CSR build ----------------
    csr_zero<<<nZERO, TPB>>>();
    csr_hist<<<nET, TPB>>>(ei);
    csr_scan<<<1, SCAN_T>>>();
    csr_scatter<<<nET, TPB>>>(ei);

    // ---------------- layer 1 ----------------
    conv_B<<<256, 256>>>(W1);
    gemm_bf16<<<mmGrid, 256>>>(x, phh, NN, NULL, NULL, as1, ad1);
    gat_agg<<<nAGG, 256>>>(b1, x, NULL, NULL, py1);
    bn_final<<<1, F>>>(gm1, be1, psc1, psh1);

    // ---------------- layer 2 ----------------
    conv_B<<<256, 256>>>(W2);
    gemm_bf16<<<mmGrid, 256>>>(py1, phh, NN, psc1, psh1, as2, ad2);
    gat_agg<<<nAGG, 256>>>(b2, py1, psc1, psh1, py2);
    bn_final<<<1, F>>>(gm2, be2, psc2, psh2);

    // ---------------- pool + head ----------------
    bn_pool<<<nPOOL, 256>>>(bat, py2);
    mlp_head<<<GG, 64>>>(fc1w, fc1b, fc2w, fc2b, out);
}

// round 8
// speedup vs baseline: 2.9258x; 1.2208x over previous
#include <cuda_runtime.h>
#include <cuda_bf16.h>
#include <cuda_fp16.h>
#include <math.h>
#include <stdint.h>

#define NN   50000
#define EE   400000
#define ET   (EE + NN)
#define F    256
#define HH   4
#define CC   64
#define GG   64
#define NCLS 10

// ---------------- scratch (static device globals; no allocations) -----------
__device__ __align__(16) __half g_hh[(size_t)NN * F];   // h = A' @ W, fp16
__device__ float g_y1[NN * F];
__device__ float g_y2[NN * F];
__device__ float g_asrc[NN * HH];
__device__ float g_adst[NN * HH];
__device__ float g_sum[F], g_sumsq[F];
__device__ float g_sc1[F], g_sh1[F];
__device__ float g_sc2[F], g_sh2[F];
__device__ float g_pool[GG * F];
__device__ float g_cnt[GG];
__device__ __align__(16) __nv_bfloat16 g_Bp[768 * 256];   // split W, stage-ordered
// CSR
__device__ int   g_cnt_n[NN];
__device__ int   g_rp[NN + 1];
__device__ int   g_col[ET];

// ---------------- bf16 pack helpers ------------------------------------------
__device__ __forceinline__ uint32_t pack_hi(float a, float b) {
    __nv_bfloat162 h = __floats2bfloat162_rn(a, b);
    return *(uint32_t*)&h;
}
__device__ __forceinline__ uint32_t pack_lo(float a, float b, uint32_t hi) {
    __nv_bfloat162 h = *(__nv_bfloat162*)&hi;
    __nv_bfloat162 l = __floats2bfloat162_rn(a - __bfloat162float(h.x),
                                             b - __bfloat162float(h.y));
    return *(uint32_t*)&l;
}

// ---- conv_B: W[256][256] -> B'[768][256], per 64-block j, per 32-half:
// rows [hi, hi, lo] so stages pair (A_hi*Bh, A_lo*Bh, A_hi*Bl) ------------------
__global__ void conv_B(const float* __restrict__ W) {
    int k = blockIdx.x, n = threadIdx.x;
    float v = W[k * 256 + n];
    __nv_bfloat16 hi = __float2bfloat16_rn(v);
    __nv_bfloat16 lo = __float2bfloat16_rn(v - __bfloat162float(hi));
    int j = k >> 6, kl = k & 63, half = kl >> 5, i = kl & 31;
    int base = j * 192 + half * 96 + i;
    g_Bp[(size_t)(base)      * 256 + n] = hi;
    g_Bp[(size_t)(base + 32) * 256 + n] = hi;
    g_Bp[(size_t)(base + 64) * 256 + n] = lo;
}

// ============ bf16 mma.sync GEMM, K'=768, inline A split, fused attn =========
#define PA 80
#define PB 272
#define ABUF (128 * PA)
#define BBUF (32 * PB)
#define STG  (ABUF + BBUF)

__device__ __forceinline__ uint32_t smem_u32(const void* p) {
    uint32_t a;
    asm("{ .reg .u64 t; cvta.to.shared.u64 t, %1; cvt.u32.u64 %0, t; }"
        : "=r"(a) : "l"(p));
    return a;
}
__device__ __forceinline__ void ldsm_x4(uint32_t* a, uint32_t addr) {
    asm volatile("ldmatrix.sync.aligned.m8n8.x4.shared.b16 {%0,%1,%2,%3}, [%4];"
                 : "=r"(a[0]), "=r"(a[1]), "=r"(a[2]), "=r"(a[3]) : "r"(addr));
}
__device__ __forceinline__ void ldsm_x2t(uint32_t* b, uint32_t addr) {
    asm volatile("ldmatrix.sync.aligned.m8n8.x2.trans.shared.b16 {%0,%1}, [%2];"
                 : "=r"(b[0]), "=r"(b[1]) : "r"(addr));
}
__device__ __forceinline__ void mma16816(float* d, const uint32_t* a,
                                         const uint32_t* b) {
    asm volatile(
        "mma.sync.aligned.m16n8k16.row.col.f32.bf16.bf16.f32 "
        "{%0,%1,%2,%3}, {%4,%5,%6,%7}, {%8,%9}, {%0,%1,%2,%3};"
        : "+f"(d[0]), "+f"(d[1]), "+f"(d[2]), "+f"(d[3])
        : "r"(a[0]), "r"(a[1]), "r"(a[2]), "r"(a[3]), "r"(b[0]), "r"(b[1]));
}
__device__ __forceinline__ void load_split(const float* agp32, int kbase, int sidx,
                                           const float* scale, const float* shift,
                                           bool ok, float* e, uint32_t* hp) {
    if (ok) {
#pragma unroll
        for (int i = 0; i < 4; i++) {
            float4 v = *(const float4*)(agp32 + kbase + i * 4);
            e[i * 4 + 0] = v.x; e[i * 4 + 1] = v.y;
            e[i * 4 + 2] = v.z; e[i * 4 + 3] = v.w;
        }
        if (scale) {
#pragma unroll
            for (int i = 0; i < 16; i++)
                e[i] = e[i] * scale[sidx + i] + shift[sidx + i];
        }
    } else {
#pragma unroll
        for (int i = 0; i < 16; i++) e[i] = 0.f;
    }
#pragma unroll
    for (int p = 0; p < 8; p++) hp[p] = pack_hi(e[2 * p], e[2 * p + 1]);
}

__global__ __launch_bounds__(256)
void gemm_bf16(const float* __restrict__ A, __half* __restrict__ C, int M,
               const float* __restrict__ scale, const float* __restrict__ shift,
               const float* __restrict__ atts, const float* __restrict__ attd) {
    __shared__ __align__(16) char sm[2 * STG];
    const int t = threadIdx.x, lane = t & 31, w = t >> 5;
    const int wm = w & 1, wn = w >> 1;
    const int row0 = blockIdx.x * 128, col0 = blockIdx.y * 128;
    const uint32_t sb = smem_u32(sm);

    float acc[4][4][4];
#pragma unroll
    for (int i = 0; i < 4; i++)
#pragma unroll
        for (int j = 0; j < 4; j++)
#pragma unroll
            for (int k = 0; k < 4; k++) acc[i][j][k] = 0.f;

    const int ar = t >> 1, apart = t & 1;
    const bool a_ok = (row0 + ar) < M;
    const float* agp32 = A + (size_t)(row0 + ar) * 256 + apart * 16;
    const int br = t >> 3, bseg = t & 7;
    const __nv_bfloat16* bgp = g_Bp + (size_t)br * 256 + col0 + bseg * 16;

    float e[16];
    uint32_t hp[8];

    load_split(agp32, 0, apart * 16, scale, shift, a_ok, e, hp);
    {
        char* pa = sm + ar * PA + apart * 32;
        *(uint4*)pa = *(uint4*)&hp[0];
        *(uint4*)(pa + 16) = *(uint4*)&hp[4];
        uint4 lb0 = *(const uint4*)(bgp);
        uint4 lb1 = *(const uint4*)(bgp + 8);
        char* pb = sm + ABUF + br * PB + bseg * 32;
        *(uint4*)pb = lb0; *(uint4*)(pb + 16) = lb1;
    }
    __syncthreads();

    for (int s = 0; s < 24; s++) {
        const int buf = s & 1;
        const uint32_t sba = sb + buf * STG;
        const int sn = s + 1;
        const int rn = sn % 6;
        uint4 lb0, lb1;
        if (s < 23) {
            lb0 = *(const uint4*)(bgp + (size_t)(sn * 32) * 256);
            lb1 = *(const uint4*)(bgp + (size_t)(sn * 32) * 256 + 8);
            if (rn == 0 || rn == 3) {
                int kbase = (sn / 6) * 64 + (rn == 3 ? 32 : 0);
                load_split(agp32, kbase, kbase + apart * 16, scale, shift,
                           a_ok, e, hp);
            }
        }
#pragma unroll
        for (int kh = 0; kh < 2; kh++) {
            uint32_t afr[4][4], bfr[4][2];
#pragma unroll
            for (int mi = 0; mi < 4; mi++) {
                uint32_t addr = sba + (uint32_t)(wm * 64 + mi * 16 + (lane & 15)) * PA
                              + kh * 32 + (lane >> 4) * 16;
                ldsm_x4(afr[mi], addr);
            }
#pragma unroll
            for (int nf = 0; nf < 4; nf++) {
                uint32_t addr = sba + ABUF + (uint32_t)(kh * 16 + (lane & 15)) * PB
                              + (wn * 32 + nf * 8) * 2;
                ldsm_x2t(bfr[nf], addr);
            }
#pragma unroll
            for (int mi = 0; mi < 4; mi++)
#pragma unroll
                for (int nf = 0; nf < 4; nf++)
                    mma16816(acc[mi][nf], afr[mi], bfr[nf]);
        }
        if (s < 23) {
            char* base = sm + (buf ^ 1) * STG;
            char* pb = base + ABUF + br * PB + bseg * 32;
            *(uint4*)pb = lb0; *(uint4*)(pb + 16) = lb1;
            if (rn == 0 || rn == 3) {
                char* pa = base + ar * PA + apart * 32;
                *(uint4*)pa = *(uint4*)&hp[0];
                *(uint4*)(pa + 16) = *(uint4*)&hp[4];
            } else if (rn == 1 || rn == 4) {
                uint32_t lp[8];
#pragma unroll
                for (int p = 0; p < 8; p++)
                    lp[p] = pack_lo(e[2 * p], e[2 * p + 1], hp[p]);
                char* pa = base + ar * PA + apart * 32;
                *(uint4*)pa = *(uint4*)&lp[0];
                *(uint4*)(pa + 16) = *(uint4*)&lp[4];
            }
        }
        __syncthreads();
    }

    // ---- epilogue: store C (fp16), per-warp att partials -> smem, combine ---
    float* part = (float*)sm;
#pragma unroll
    for (int mi = 0; mi < 4; mi++) {
        int lr_lo = wm * 64 + mi * 16 + (lane >> 2);
        int lr_hi = lr_lo + 8;
        int r_lo = row0 + lr_lo, r_hi = row0 + lr_hi;
        float ds0 = 0.f, dd0 = 0.f, ds1 = 0.f, dd1 = 0.f;
#pragma unroll
        for (int nf = 0; nf < 4; nf++) {
            int c = col0 + wn * 32 + nf * 8 + (lane & 3) * 2;
            float v0 = acc[mi][nf][0], v1 = acc[mi][nf][1];
            float v2 = acc[mi][nf][2], v3 = acc[mi][nf][3];
            if (r_lo < M) *(__half2*)(C + (size_t)r_lo * 256 + c) = __floats2half2_rn(v0, v1);
            if (r_hi < M) *(__half2*)(C + (size_t)r_hi * 256 + c) = __floats2half2_rn(v2, v3);
            float s0 = atts[c], s1 = atts[c + 1];
            float d0 = attd[c], d1 = attd[c + 1];
            ds0 += v0 * s0 + v1 * s1; dd0 += v0 * d0 + v1 * d1;
            ds1 += v2 * s0 + v3 * s1; dd1 += v2 * d0 + v3 * d1;
        }
#pragma unroll
        for (int o = 1; o <= 2; o <<= 1) {
            ds0 += __shfl_xor_sync(0xFFFFFFFFu, ds0, o);
            dd0 += __shfl_xor_sync(0xFFFFFFFFu, dd0, o);
            ds1 += __shfl_xor_sync(0xFFFFFFFFu, ds1, o);
            dd1 += __shfl_xor_sync(0xFFFFFFFFu, dd1, o);
        }
        if ((lane & 3) == 0) {
            part[(lr_lo * 4 + wn) * 2 + 0] = ds0;
            part[(lr_lo * 4 + wn) * 2 + 1] = dd0;
            part[(lr_hi * 4 + wn) * 2 + 0] = ds1;
            part[(lr_hi * 4 + wn) * 2 + 1] = dd1;
        }
    }
    __syncthreads();
    {
        int lr = t & 127, sd = t >> 7;
        int gr = row0 + lr;
        if (gr < M) {
            float* dst = sd ? g_adst : g_asrc;
#pragma unroll
            for (int hl = 0; hl < 2; hl++) {
                float v = part[(lr * 4 + 2 * hl) * 2 + sd]
                        + part[(lr * 4 + 2 * hl + 1) * 2 + sd];
                dst[gr * HH + (col0 >> 6) + hl] = v;
            }
        }
    }
}

// ------------------------------ CSR build -----------------------------------
__global__ void csr_zero() {
    int i = blockIdx.x * blockDim.x + threadIdx.x;
    if (i < NN) g_cnt_n[i] = 0;
    if (i < F)  { g_sum[i] = 0.f; g_sumsq[i] = 0.f; }
    if (i < GG * F) g_pool[i] = 0.f;
    if (i < GG) g_cnt[i] = 0.f;
}
__global__ void csr_hist(const int* __restrict__ ei) {
    int e = blockIdx.x * blockDim.x + threadIdx.x;
    if (e >= ET) return;
    int d = (e < EE) ? ei[EE + e] : e - EE;
    atomicAdd(&g_cnt_n[d], 1);
}
#define SCAN_T 1024
#define CHUNK  ((NN + SCAN_T - 1) / SCAN_T)
__global__ void csr_scan() {
    __shared__ int ps[SCAN_T];
    int t = threadIdx.x;
    int lo = t * CHUNK, hi = min(lo + CHUNK, NN);
    int s = 0;
    for (int i = lo; i < hi; i++) s += g_cnt_n[i];
    ps[t] = s;
    __syncthreads();
    for (int off = 1; off < SCAN_T; off <<= 1) {
        int v = (t >= off) ? ps[t - off] : 0;
        __syncthreads();
        ps[t] += v;
        __syncthreads();
    }
    int run = t ? ps[t - 1] : 0;
    for (int i = lo; i < hi; i++) {
        int c = g_cnt_n[i];
        g_rp[i] = run;
        g_cnt_n[i] = run;
        run += c;
    }
    if (hi == NN) g_rp[NN] = run;
}
__global__ void csr_scatter(const int* __restrict__ ei) {
    int e = blockIdx.x * blockDim.x + threadIdx.x;
    if (e >= ET) return;
    int s, d;
    if (e < EE) { s = ei[e]; d = ei[EE + e]; }
    else        { s = d = e - EE; }
    int pos = atomicAdd(&g_cnt_n[d], 1);
    g_col[pos] = s;
}

// ----- fused GAT aggregate + bias + ELU + residual(+BN) + BN stats -----------
// Warp per (dst-row, 128-col half); edge loop software-pipelined (unroll 4).
#define RPW 4
__global__ __launch_bounds__(256)
void gat_agg(const float* __restrict__ b,
             const float* __restrict__ xin,
             const float* __restrict__ rscale,
             const float* __restrict__ rshift,
             float* __restrict__ y) {
    __shared__ float bsum[F], bsq[F];
    int t = threadIdx.x;
    bsum[t] = 0.f; bsq[t] = 0.f;
    __syncthreads();

    int lane = t & 31;
    int gwarp = blockIdx.x * 8 + (t >> 5);
    int hf = gwarp & 1;
    int d0 = (gwarp >> 1) * RPW;
    int c = hf * 128 + (lane << 2);
    int h = hf * 2 + (lane >> 4);

    float4 bias = *(const float4*)(b + c);
    float scv = rscale ? rscale[c] : 1.f,     shv = rshift ? rshift[c] : 0.f;
    float scy = rscale ? rscale[c + 1] : 1.f, shy = rshift ? rshift[c + 1] : 0.f;
    float scz = rscale ? rscale[c + 2] : 1.f, shz = rshift ? rshift[c + 2] : 0.f;
    float scw = rscale ? rscale[c + 3] : 1.f, shw = rshift ? rshift[c + 3] : 0.f;

    float ss[4] = {0, 0, 0, 0};
    float sq[4] = {0, 0, 0, 0};

#pragma unroll
    for (int rr = 0; rr < RPW; rr++) {
        int d = d0 + rr;
        if (d >= NN) break;
        float ad = g_adst[d * HH + h];
        float ax = 0.f, ay = 0.f, az = 0.f, aw = 0.f;
        float den = 0.f;
        int e0 = g_rp[d], e1 = g_rp[d + 1];
        int e = e0;
        // unrolled-by-4, load-batched main loop (MLP ~ 8)
        for (; e + 4 <= e1; e += 4) {
            int s0 = g_col[e], s1 = g_col[e + 1];
            int s2 = g_col[e + 2], s3 = g_col[e + 3];
            float a0 = g_asrc[s0 * HH + h], a1 = g_asrc[s1 * HH + h];
            float a2 = g_asrc[s2 * HH + h], a3 = g_asrc[s3 * HH + h];
            uint2 u0 = *(const uint2*)(g_hh + (size_t)s0 * F + c);
            uint2 u1 = *(const uint2*)(g_hh + (size_t)s1 * F + c);
            uint2 u2 = *(const uint2*)(g_hh + (size_t)s2 * F + c);
            uint2 u3 = *(const uint2*)(g_hh + (size_t)s3 * F + c);
            float v0 = a0 + ad, v1 = a1 + ad, v2 = a2 + ad, v3 = a3 + ad;
            v0 = v0 > 0.f ? v0 : 0.2f * v0;
            v1 = v1 > 0.f ? v1 : 0.2f * v1;
            v2 = v2 > 0.f ? v2 : 0.2f * v2;
            v3 = v3 > 0.f ? v3 : 0.2f * v3;
            float x0 = __expf(v0), x1 = __expf(v1);
            float x2 = __expf(v2), x3 = __expf(v3);
            den += (x0 + x1) + (x2 + x3);
            float2 p0 = __half22float2(*(__half2*)&u0.x);
            float2 q0 = __half22float2(*(__half2*)&u0.y);
            float2 p1 = __half22float2(*(__half2*)&u1.x);
            float2 q1 = __half22float2(*(__half2*)&u1.y);
            float2 p2 = __half22float2(*(__half2*)&u2.x);
            float2 q2 = __half22float2(*(__half2*)&u2.y);
            float2 p3 = __half22float2(*(__half2*)&u3.x);
            float2 q3 = __half22float2(*(__half2*)&u3.y);
            ax += x0 * p0.x + x1 * p1.x + x2 * p2.x + x3 * p3.x;
            ay += x0 * p0.y + x1 * p1.y + x2 * p2.y + x3 * p3.y;
            az += x0 * q0.x + x1 * q1.x + x2 * q2.x + x3 * q3.x;
            aw += x0 * q0.y + x1 * q1.y + x2 * q2.y + x3 * q3.y;
        }
        for (; e < e1; e++) {
            int s = g_col[e];
            float v = g_asrc[s * HH + h] + ad;
            v = v > 0.f ? v : 0.2f * v;
            float ex = __expf(v);
            den += ex;
            uint2 u = *(const uint2*)(g_hh + (size_t)s * F + c);
            float2 f0 = __half22float2(*(__half2*)&u.x);
            float2 f1 = __half22float2(*(__half2*)&u.y);
            ax += ex * f0.x; ay += ex * f0.y;
            az += ex * f1.x; aw += ex * f1.y;
        }
        float inv = __fdividef(1.f, den);
        float4 xr = *(const float4*)(xin + (size_t)d * F + c);
        float o[4];
        o[0] = ax * inv + bias.x; o[1] = ay * inv + bias.y;
        o[2] = az * inv + bias.z; o[3] = aw * inv + bias.w;
#pragma unroll
        for (int j = 0; j < 4; j++) o[j] = o[j] > 0.f ? o[j] : expm1f(o[j]);
        o[0] += xr.x * scv + shv; o[1] += xr.y * scy + shy;
        o[2] += xr.z * scz + shz; o[3] += xr.w * scw + shw;
        *(float4*)(y + (size_t)d * F + c) = make_float4(o[0], o[1], o[2], o[3]);
#pragma unroll
        for (int j = 0; j < 4; j++) { ss[j] += o[j]; sq[j] += o[j] * o[j]; }
    }
#pragma unroll
    for (int j = 0; j < 4; j++) {
        atomicAdd(&bsum[c + j], ss[j]);
        atomicAdd(&bsq[c + j],  sq[j]);
    }
    __syncthreads();
    atomicAdd(&g_sum[t],   bsum[t]);
    atomicAdd(&g_sumsq[t], bsq[t]);
}

__global__ void bn_final(const float* __restrict__ gm, const float* __restrict__ bt,
                         float* __restrict__ sc_out, float* __restrict__ sh_out) {
    int f = threadIdx.x;
    float mu  = g_sum[f] / (float)NN;
    float var = g_sumsq[f] / (float)NN - mu * mu;
    float sc  = gm[f] * rsqrtf(var + 1e-5f);
    sc_out[f] = sc;
    sh_out[f] = bt[f] - mu * sc;
    g_sum[f] = 0.f; g_sumsq[f] = 0.f;
}

// -------------- fused: BN2 apply + global mean pool (sorted batch) -----------
#define POOL_ROWS 128
__global__ void bn_pool(const int* __restrict__ bt, const float* __restrict__ y) {
    int f  = threadIdx.x;
    int r0 = blockIdx.x * POOL_ROWS;
    int r1 = min(r0 + POOL_ROWS, NN);
    if (r0 >= NN) return;
    float sc = g_sc2[f], sh = g_sh2[f];
    int g = bt[r0];
    float acc = 0.f, cnt = 0.f;
    for (int r = r0; r < r1; r++) {
        int gr = bt[r];
        if (gr != g) {
            atomicAdd(&g_pool[g * F + f], acc);
            if (f == 0) atomicAdd(&g_cnt[g], cnt);
            acc = 0.f; cnt = 0.f; g = gr;
        }
        acc += y[(size_t)r * F + f] * sc + sh;
        cnt += 1.f;
    }
    atomicAdd(&g_pool[g * F + f], acc);
    if (f == 0) atomicAdd(&g_cnt[g], cnt);
}

// --------------------------- MLP head + log softmax -------------------------
__global__ void mlp_head(const float* __restrict__ fc1w, const float* __restrict__ fc1b,
                         const float* __restrict__ fc2w, const float* __restrict__ fc2b,
                         float* __restrict__ out) {
    __shared__ float p[F];
    __shared__ float z[CC];
    __shared__ float l[NCLS];
    __shared__ float red[2];
    int g = blockIdx.x;
    int t = threadIdx.x;
    float inv = 1.f / fmaxf(g_cnt[g], 1.f);
    for (int k = t; k < F; k += 64) p[k] = g_pool[g * F + k] * inv;
    __syncthreads();
    float acc = fc1b[t];
    for (int k = 0; k < F; k++) acc += p[k] * fc1w[k * CC + t];
    z[t] = fmaxf(acc, 0.f);
    __syncthreads();
    if (t < NCLS) {
        float a = fc2b[t];
        for (int k = 0; k < CC; k++) a += z[k] * fc2w[k * NCLS + t];
        l[t] = a;
    }
    __syncthreads();
    if (t == 0) {
        float m = l[0];
        for (int i = 1; i < NCLS; i++) m = fmaxf(m, l[i]);
        float s = 0.f;
        for (int i = 0; i < NCLS; i++) s += expf(l[i] - m);
        red[0] = m; red[1] = logf(s);
    }
    __syncthreads();
    if (t < NCLS) out[g * NCLS + t] = l[t] - red[0] - red[1];
}

// ---------------------------------- launch ----------------------------------
extern "C" void kernel_launch(void* const* d_in, const int* in_sizes, int n_in,
                              void* d_out, int out_size) {
    const float* x    = (const float*)d_in[0];
    const int*   ei   = (const int*)  d_in[1];
    const int*   bat  = (const int*)  d_in[2];
    const float* W1   = (const float*)d_in[3];
    const float* as1  = (const float*)d_in[4];
    const float* ad1  = (const float*)d_in[5];
    const float* b1   = (const float*)d_in[6];
    const float* gm1  = (const float*)d_in[7];
    const float* be1  = (const float*)d_in[8];
    const float* W2   = (const float*)d_in[9];
    const float* as2  = (const float*)d_in[10];
    const float* ad2  = (const float*)d_in[11];
    const float* b2   = (const float*)d_in[12];
    const float* gm2  = (const float*)d_in[13];
    const float* be2  = (const float*)d_in[14];
    const float* fc1w = (const float*)d_in[15];
    const float* fc1b = (const float*)d_in[16];
    const float* fc2w = (const float*)d_in[17];
    const float* fc2b = (const float*)d_in[18];
    float* out = (float*)d_out;

    __half* phh;
    float *py1, *py2, *psc1, *psh1, *psc2, *psh2;
    cudaGetSymbolAddress((void**)&phh,  g_hh);
    cudaGetSymbolAddress((void**)&py1,  g_y1);
    cudaGetSymbolAddress((void**)&py2,  g_y2);
    cudaGetSymbolAddress((void**)&psc1, g_sc1);
    cudaGetSymbolAddress((void**)&psh1, g_sh1);
    cudaGetSymbolAddress((void**)&psc2, g_sc2);
    cudaGetSymbolAddress((void**)&psh2, g_sh2);

    const int TPB = 256;
    const int nET = (ET + TPB - 1) / TPB;
    dim3 mmGrid((NN + 127) / 128, 2);
    const int nAGG  = (2 * NN + 8 * RPW - 1) / (8 * RPW);
    const int nPOOL = (NN + POOL_ROWS - 1) / POOL_ROWS;
    const int nZERO = (GG * F + TPB - 1) / TPB > (NN + TPB - 1) / TPB
                      ? (GG * F + TPB - 1) / TPB : (NN + TPB - 1) / TPB;

    // ---------------- CSR build ----------------
    csr_zero<<<nZERO, TPB>>>();
    csr_hist<<<nET, TPB>>>(ei);
    csr_scan<<<1, SCAN_T>>>();
    csr_scatter<<<nET, TPB>>>(ei);

    // ---------------- layer 1 ----------------
    conv_B<<<256, 256>>>(W1);
    gemm_bf16<<<mmGrid, 256>>>(x, phh, NN, NULL, NULL, as1, ad1);
    gat_agg<<<nAGG, 256>>>(b1, x, NULL, NULL, py1);
    bn_final<<<1, F>>>(gm1, be1, psc1, psh1);

    // ---------------- layer 2 ----------------
    conv_B<<<256, 256>>>(W2);
    gemm_bf16<<<mmGrid, 256>>>(py1, phh, NN, psc1, psh1, as2, ad2);
    gat_agg<<<nAGG, 256>>>(b2, py1, psc1, psh1, py2);
    bn_final<<<1, F>>>(gm2, be2, psc2, psh2);

    // ---------------- pool + head ----------------
    bn_pool<<<nPOOL, 256>>>(bat, py2);
    mlp_head<<<GG, 64>>>(fc1w, fc1b, fc2w, fc2b, out);
}

// round 9
// speedup vs baseline: 3.0624x; 1.0467x over previous
#include <cuda_runtime.h>
#include <cuda_bf16.h>
#include <cuda_fp16.h>
#include <math.h>
#include <stdint.h>

#define NN   50000
#define EE   400000
#define ET   (EE + NN)
#define F    256
#define HH   4
#define CC   64
#define GG   64
#define NCLS 10

// ---------------- scratch (static device globals; no allocations) -----------
__device__ __align__(16) __half g_hh[(size_t)NN * F];   // h = A' @ W, fp16
__device__ float g_y1[NN * F];
__device__ float g_asrc[NN * HH];
__device__ float g_adst[NN * HH];
__device__ float g_sum[F], g_sumsq[F];
__device__ float g_sc1[F], g_sh1[F];
__device__ float g_sc2[F], g_sh2[F];
__device__ float g_pool[GG * F];        // raw sums of layer-2 output (pre-BN2)
__device__ float g_cnt[GG];
__device__ __align__(16) __nv_bfloat16 g_Bp[768 * 256];   // split W, stage-ordered
// CSR
__device__ int   g_cnt_n[NN];
__device__ int   g_rp[NN + 1];
__device__ int   g_col[ET];

// ---------------- bf16 pack helpers ------------------------------------------
__device__ __forceinline__ uint32_t pack_hi(float a, float b) {
    __nv_bfloat162 h = __floats2bfloat162_rn(a, b);
    return *(uint32_t*)&h;
}
__device__ __forceinline__ uint32_t pack_lo(float a, float b, uint32_t hi) {
    __nv_bfloat162 h = *(__nv_bfloat162*)&hi;
    __nv_bfloat162 l = __floats2bfloat162_rn(a - __bfloat162float(h.x),
                                             b - __bfloat162float(h.y));
    return *(uint32_t*)&l;
}
__device__ __forceinline__ void red4(float* p, float a, float b, float c, float d) {
    asm volatile("red.global.add.v4.f32 [%0], {%1,%2,%3,%4};"
                 :: "l"(p), "f"(a), "f"(b), "f"(c), "f"(d) : "memory");
}

// ---- conv_B: W[256][256] -> B'[768][256], per 64-block j, per 32-half:
// rows [hi, hi, lo] so stages pair (A_hi*Bh, A_lo*Bh, A_hi*Bl) ------------------
__global__ void conv_B(const float* __restrict__ W) {
    int k = blockIdx.x, n = threadIdx.x;
    float v = W[k * 256 + n];
    __nv_bfloat16 hi = __float2bfloat16_rn(v);
    __nv_bfloat16 lo = __float2bfloat16_rn(v - __bfloat162float(hi));
    int j = k >> 6, kl = k & 63, half = kl >> 5, i = kl & 31;
    int base = j * 192 + half * 96 + i;
    g_Bp[(size_t)(base)      * 256 + n] = hi;
    g_Bp[(size_t)(base + 32) * 256 + n] = hi;
    g_Bp[(size_t)(base + 64) * 256 + n] = lo;
}

// ============ bf16 mma.sync GEMM, K'=768, inline A split, fused attn =========
#define PA 80
#define PB 272
#define ABUF (128 * PA)
#define BBUF (32 * PB)
#define STG  (ABUF + BBUF)

__device__ __forceinline__ uint32_t smem_u32(const void* p) {
    uint32_t a;
    asm("{ .reg .u64 t; cvta.to.shared.u64 t, %1; cvt.u32.u64 %0, t; }"
        : "=r"(a) : "l"(p));
    return a;
}
__device__ __forceinline__ void ldsm_x4(uint32_t* a, uint32_t addr) {
    asm volatile("ldmatrix.sync.aligned.m8n8.x4.shared.b16 {%0,%1,%2,%3}, [%4];"
                 : "=r"(a[0]), "=r"(a[1]), "=r"(a[2]), "=r"(a[3]) : "r"(addr));
}
__device__ __forceinline__ void ldsm_x2t(uint32_t* b, uint32_t addr) {
    asm volatile("ldmatrix.sync.aligned.m8n8.x2.trans.shared.b16 {%0,%1}, [%2];"
                 : "=r"(b[0]), "=r"(b[1]) : "r"(addr));
}
__device__ __forceinline__ void mma16816(float* d, const uint32_t* a,
                                         const uint32_t* b) {
    asm volatile(
        "mma.sync.aligned.m16n8k16.row.col.f32.bf16.bf16.f32 "
        "{%0,%1,%2,%3}, {%4,%5,%6,%7}, {%8,%9}, {%0,%1,%2,%3};"
        : "+f"(d[0]), "+f"(d[1]), "+f"(d[2]), "+f"(d[3])
        : "r"(a[0]), "r"(a[1]), "r"(a[2]), "r"(a[3]), "r"(b[0]), "r"(b[1]));
}
__device__ __forceinline__ void load_split(const float* agp32, int kbase, int sidx,
                                           const float* scale, const float* shift,
                                           bool ok, float* e, uint32_t* hp) {
    if (ok) {
#pragma unroll
        for (int i = 0; i < 4; i++) {
            float4 v = *(const float4*)(agp32 + kbase + i * 4);
            e[i * 4 + 0] = v.x; e[i * 4 + 1] = v.y;
            e[i * 4 + 2] = v.z; e[i * 4 + 3] = v.w;
        }
        if (scale) {
#pragma unroll
            for (int i = 0; i < 16; i++)
                e[i] = e[i] * scale[sidx + i] + shift[sidx + i];
        }
    } else {
#pragma unroll
        for (int i = 0; i < 16; i++) e[i] = 0.f;
    }
#pragma unroll
    for (int p = 0; p < 8; p++) hp[p] = pack_hi(e[2 * p], e[2 * p + 1]);
}

__global__ __launch_bounds__(256)
void gemm_bf16(const float* __restrict__ A, __half* __restrict__ C, int M,
               const float* __restrict__ scale, const float* __restrict__ shift,
               const float* __restrict__ atts, const float* __restrict__ attd) {
    __shared__ __align__(16) char sm[2 * STG];
    const int t = threadIdx.x, lane = t & 31, w = t >> 5;
    const int wm = w & 1, wn = w >> 1;
    const int row0 = blockIdx.x * 128, col0 = blockIdx.y * 128;
    const uint32_t sb = smem_u32(sm);

    float acc[4][4][4];
#pragma unroll
    for (int i = 0; i < 4; i++)
#pragma unroll
        for (int j = 0; j < 4; j++)
#pragma unroll
            for (int k = 0; k < 4; k++) acc[i][j][k] = 0.f;

    const int ar = t >> 1, apart = t & 1;
    const bool a_ok = (row0 + ar) < M;
    const float* agp32 = A + (size_t)(row0 + ar) * 256 + apart * 16;
    const int br = t >> 3, bseg = t & 7;
    const __nv_bfloat16* bgp = g_Bp + (size_t)br * 256 + col0 + bseg * 16;

    float e[16];
    uint32_t hp[8];

    load_split(agp32, 0, apart * 16, scale, shift, a_ok, e, hp);
    {
        char* pa = sm + ar * PA + apart * 32;
        *(uint4*)pa = *(uint4*)&hp[0];
        *(uint4*)(pa + 16) = *(uint4*)&hp[4];
        uint4 lb0 = *(const uint4*)(bgp);
        uint4 lb1 = *(const uint4*)(bgp + 8);
        char* pb = sm + ABUF + br * PB + bseg * 32;
        *(uint4*)pb = lb0; *(uint4*)(pb + 16) = lb1;
    }
    __syncthreads();

    for (int s = 0; s < 24; s++) {
        const int buf = s & 1;
        const uint32_t sba = sb + buf * STG;
        const int sn = s + 1;
        const int rn = sn % 6;
        uint4 lb0, lb1;
        if (s < 23) {
            lb0 = *(const uint4*)(bgp + (size_t)(sn * 32) * 256);
            lb1 = *(const uint4*)(bgp + (size_t)(sn * 32) * 256 + 8);
            if (rn == 0 || rn == 3) {
                int kbase = (sn / 6) * 64 + (rn == 3 ? 32 : 0);
                load_split(agp32, kbase, kbase + apart * 16, scale, shift,
                           a_ok, e, hp);
            }
        }
#pragma unroll
        for (int kh = 0; kh < 2; kh++) {
            uint32_t afr[4][4], bfr[4][2];
#pragma unroll
            for (int mi = 0; mi < 4; mi++) {
                uint32_t addr = sba + (uint32_t)(wm * 64 + mi * 16 + (lane & 15)) * PA
                              + kh * 32 + (lane >> 4) * 16;
                ldsm_x4(afr[mi], addr);
            }
#pragma unroll
            for (int nf = 0; nf < 4; nf++) {
                uint32_t addr = sba + ABUF + (uint32_t)(kh * 16 + (lane & 15)) * PB
                              + (wn * 32 + nf * 8) * 2;
                ldsm_x2t(bfr[nf], addr);
            }
#pragma unroll
            for (int mi = 0; mi < 4; mi++)
#pragma unroll
                for (int nf = 0; nf < 4; nf++)
                    mma16816(acc[mi][nf], afr[mi], bfr[nf]);
        }
        if (s < 23) {
            char* base = sm + (buf ^ 1) * STG;
            char* pb = base + ABUF + br * PB + bseg * 32;
            *(uint4*)pb = lb0; *(uint4*)(pb + 16) = lb1;
            if (rn == 0 || rn == 3) {
                char* pa = base + ar * PA + apart * 32;
                *(uint4*)pa = *(uint4*)&hp[0];
                *(uint4*)(pa + 16) = *(uint4*)&hp[4];
            } else if (rn == 1 || rn == 4) {
                uint32_t lp[8];
#pragma unroll
                for (int p = 0; p < 8; p++)
                    lp[p] = pack_lo(e[2 * p], e[2 * p + 1], hp[p]);
                char* pa = base + ar * PA + apart * 32;
                *(uint4*)pa = *(uint4*)&lp[0];
                *(uint4*)(pa + 16) = *(uint4*)&lp[4];
            }
        }
        __syncthreads();
    }

    // ---- epilogue: store C (fp16), per-warp att partials -> smem, combine ---
    float* part = (float*)sm;
#pragma unroll
    for (int mi = 0; mi < 4; mi++) {
        int lr_lo = wm * 64 + mi * 16 + (lane >> 2);
        int lr_hi = lr_lo + 8;
        int r_lo = row0 + lr_lo, r_hi = row0 + lr_hi;
        float ds0 = 0.f, dd0 = 0.f, ds1 = 0.f, dd1 = 0.f;
#pragma unroll
        for (int nf = 0; nf < 4; nf++) {
            int c = col0 + wn * 32 + nf * 8 + (lane & 3) * 2;
            float v0 = acc[mi][nf][0], v1 = acc[mi][nf][1];
            float v2 = acc[mi][nf][2], v3 = acc[mi][nf][3];
            if (r_lo < M) *(__half2*)(C + (size_t)r_lo * 256 + c) = __floats2half2_rn(v0, v1);
            if (r_hi < M) *(__half2*)(C + (size_t)r_hi * 256 + c) = __floats2half2_rn(v2, v3);
            float s0 = atts[c], s1 = atts[c + 1];
            float d0 = attd[c], d1 = attd[c + 1];
            ds0 += v0 * s0 + v1 * s1; dd0 += v0 * d0 + v1 * d1;
            ds1 += v2 * s0 + v3 * s1; dd1 += v2 * d0 + v3 * d1;
        }
#pragma unroll
        for (int o = 1; o <= 2; o <<= 1) {
            ds0 += __shfl_xor_sync(0xFFFFFFFFu, ds0, o);
            dd0 += __shfl_xor_sync(0xFFFFFFFFu, dd0, o);
            ds1 += __shfl_xor_sync(0xFFFFFFFFu, ds1, o);
            dd1 += __shfl_xor_sync(0xFFFFFFFFu, dd1, o);
        }
        if ((lane & 3) == 0) {
            part[(lr_lo * 4 + wn) * 2 + 0] = ds0;
            part[(lr_lo * 4 + wn) * 2 + 1] = dd0;
            part[(lr_hi * 4 + wn) * 2 + 0] = ds1;
            part[(lr_hi * 4 + wn) * 2 + 1] = dd1;
        }
    }
    __syncthreads();
    {
        int lr = t & 127, sd = t >> 7;
        int gr = row0 + lr;
        if (gr < M) {
            float* dst = sd ? g_adst : g_asrc;
#pragma unroll
            for (int hl = 0; hl < 2; hl++) {
                float v = part[(lr * 4 + 2 * hl) * 2 + sd]
                        + part[(lr * 4 + 2 * hl + 1) * 2 + sd];
                dst[gr * HH + (col0 >> 6) + hl] = v;
            }
        }
    }
}

// ------------------------------ CSR build -----------------------------------
__global__ void csr_zero() {
    int i = blockIdx.x * blockDim.x + threadIdx.x;
    if (i < NN) g_cnt_n[i] = 0;
    if (i < F)  { g_sum[i] = 0.f; g_sumsq[i] = 0.f; }
    if (i < GG * F) g_pool[i] = 0.f;
    if (i < GG) g_cnt[i] = 0.f;
}
__global__ void csr_hist(const int* __restrict__ ei) {
    int e = blockIdx.x * blockDim.x + threadIdx.x;
    if (e >= ET) return;
    int d = (e < EE) ? ei[EE + e] : e - EE;
    atomicAdd(&g_cnt_n[d], 1);
}
// per-graph node counts (64 bins, smem histogram)
__global__ void cnt_hist(const int* __restrict__ bt) {
    __shared__ int hcnt[GG];
    int t = threadIdx.x;
    if (t < GG) hcnt[t] = 0;
    __syncthreads();
    int i = blockIdx.x * blockDim.x + t;
    if (i < NN) atomicAdd(&hcnt[bt[i]], 1);
    __syncthreads();
    if (t < GG && hcnt[t]) atomicAdd(&g_cnt[t], (float)hcnt[t]);
}
#define SCAN_T 1024
#define CHUNK  ((NN + SCAN_T - 1) / SCAN_T)
__global__ void csr_scan() {
    __shared__ int ps[SCAN_T];
    int t = threadIdx.x;
    int lo = t * CHUNK, hi = min(lo + CHUNK, NN);
    int s = 0;
    for (int i = lo; i < hi; i++) s += g_cnt_n[i];
    ps[t] = s;
    __syncthreads();
    for (int off = 1; off < SCAN_T; off <<= 1) {
        int v = (t >= off) ? ps[t - off] : 0;
        __syncthreads();
        ps[t] += v;
        __syncthreads();
    }
    int run = t ? ps[t - 1] : 0;
    for (int i = lo; i < hi; i++) {
        int c = g_cnt_n[i];
        g_rp[i] = run;
        g_cnt_n[i] = run;
        run += c;
    }
    if (hi == NN) g_rp[NN] = run;
}
__global__ void csr_scatter(const int* __restrict__ ei) {
    int e = blockIdx.x * blockDim.x + threadIdx.x;
    if (e >= ET) return;
    int s, d;
    if (e < EE) { s = ei[e]; d = ei[EE + e]; }
    else        { s = d = e - EE; }
    int pos = atomicAdd(&g_cnt_n[d], 1);
    g_col[pos] = s;
}

// ----- fused GAT aggregate + bias + ELU + residual(+BN) + BN stats -----------
// Warp per (dst-row, 128-col half); edge loop software-pipelined (unroll 4).
// do_pool: accumulate raw per-graph sums into g_pool instead of writing y.
#define RPW 4
__global__ __launch_bounds__(256)
void gat_agg(const float* __restrict__ b,
             const float* __restrict__ xin,
             const float* __restrict__ rscale,
             const float* __restrict__ rshift,
             float* __restrict__ y,
             const int* __restrict__ bat, int do_pool) {
    __shared__ float bsum[F], bsq[F];
    int t = threadIdx.x;
    bsum[t] = 0.f; bsq[t] = 0.f;
    __syncthreads();

    int lane = t & 31;
    int gwarp = blockIdx.x * 8 + (t >> 5);
    int hf = gwarp & 1;
    int d0 = (gwarp >> 1) * RPW;
    int c = hf * 128 + (lane << 2);
    int h = hf * 2 + (lane >> 4);

    float4 bias = *(const float4*)(b + c);
    float scv = rscale ? rscale[c] : 1.f,     shv = rshift ? rshift[c] : 0.f;
    float scy = rscale ? rscale[c + 1] : 1.f, shy = rshift ? rshift[c + 1] : 0.f;
    float scz = rscale ? rscale[c + 2] : 1.f, shz = rshift ? rshift[c + 2] : 0.f;
    float scw = rscale ? rscale[c + 3] : 1.f, shw = rshift ? rshift[c + 3] : 0.f;

    float ss[4] = {0, 0, 0, 0};
    float sq[4] = {0, 0, 0, 0};
    float pa[4] = {0, 0, 0, 0};
    int curg = -1;

#pragma unroll
    for (int rr = 0; rr < RPW; rr++) {
        int d = d0 + rr;
        if (d >= NN) break;
        float ad = g_adst[d * HH + h];
        float ax = 0.f, ay = 0.f, az = 0.f, aw = 0.f;
        float den = 0.f;
        int e0 = g_rp[d], e1 = g_rp[d + 1];
        int e = e0;
        for (; e + 4 <= e1; e += 4) {
            int s0 = g_col[e], s1 = g_col[e + 1];
            int s2 = g_col[e + 2], s3 = g_col[e + 3];
            float a0 = g_asrc[s0 * HH + h], a1 = g_asrc[s1 * HH + h];
            float a2 = g_asrc[s2 * HH + h], a3 = g_asrc[s3 * HH + h];
            uint2 u0 = *(const uint2*)(g_hh + (size_t)s0 * F + c);
            uint2 u1 = *(const uint2*)(g_hh + (size_t)s1 * F + c);
            uint2 u2 = *(const uint2*)(g_hh + (size_t)s2 * F + c);
            uint2 u3 = *(const uint2*)(g_hh + (size_t)s3 * F + c);
            float v0 = a0 + ad, v1 = a1 + ad, v2 = a2 + ad, v3 = a3 + ad;
            v0 = v0 > 0.f ? v0 : 0.2f * v0;
            v1 = v1 > 0.f ? v1 : 0.2f * v1;
            v2 = v2 > 0.f ? v2 : 0.2f * v2;
            v3 = v3 > 0.f ? v3 : 0.2f * v3;
            float x0 = __expf(v0), x1 = __expf(v1);
            float x2 = __expf(v2), x3 = __expf(v3);
            den += (x0 + x1) + (x2 + x3);
            float2 p0 = __half22float2(*(__half2*)&u0.x);
            float2 q0 = __half22float2(*(__half2*)&u0.y);
            float2 p1 = __half22float2(*(__half2*)&u1.x);
            float2 q1 = __half22float2(*(__half2*)&u1.y);
            float2 p2 = __half22float2(*(__half2*)&u2.x);
            float2 q2 = __half22float2(*(__half2*)&u2.y);
            float2 p3 = __half22float2(*(__half2*)&u3.x);
            float2 q3 = __half22float2(*(__half2*)&u3.y);
            ax += x0 * p0.x + x1 * p1.x + x2 * p2.x + x3 * p3.x;
            ay += x0 * p0.y + x1 * p1.y + x2 * p2.y + x3 * p3.y;
            az += x0 * q0.x + x1 * q1.x + x2 * q2.x + x3 * q3.x;
            aw += x0 * q0.y + x1 * q1.y + x2 * q2.y + x3 * q3.y;
        }
        for (; e < e1; e++) {
            int s = g_col[e];
            float v = g_asrc[s * HH + h] + ad;
            v = v > 0.f ? v : 0.2f * v;
            float ex = __expf(v);
            den += ex;
            uint2 u = *(const uint2*)(g_hh + (size_t)s * F + c);
            float2 f0 = __half22float2(*(__half2*)&u.x);
            float2 f1 = __half22float2(*(__half2*)&u.y);
            ax += ex * f0.x; ay += ex * f0.y;
            az += ex * f1.x; aw += ex * f1.y;
        }
        float inv = __fdividef(1.f, den);
        float4 xr = *(const float4*)(xin + (size_t)d * F + c);
        float o[4];
        o[0] = ax * inv + bias.x; o[1] = ay * inv + bias.y;
        o[2] = az * inv + bias.z; o[3] = aw * inv + bias.w;
#pragma unroll
        for (int j = 0; j < 4; j++) o[j] = o[j] > 0.f ? o[j] : expm1f(o[j]);
        o[0] += xr.x * scv + shv; o[1] += xr.y * scy + shy;
        o[2] += xr.z * scz + shz; o[3] += xr.w * scw + shw;
        if (do_pool) {
            int gb = bat[d];
            if (gb != curg) {
                if (curg >= 0)
                    red4(&g_pool[curg * F + c], pa[0], pa[1], pa[2], pa[3]);
                curg = gb;
                pa[0] = pa[1] = pa[2] = pa[3] = 0.f;
            }
#pragma unroll
            for (int j = 0; j < 4; j++) pa[j] += o[j];
        } else {
            *(float4*)(y + (size_t)d * F + c) = make_float4(o[0], o[1], o[2], o[3]);
        }
#pragma unroll
        for (int j = 0; j < 4; j++) { ss[j] += o[j]; sq[j] += o[j] * o[j]; }
    }
    if (do_pool && curg >= 0)
        red4(&g_pool[curg * F + c], pa[0], pa[1], pa[2], pa[3]);
#pragma unroll
    for (int j = 0; j < 4; j++) {
        atomicAdd(&bsum[c + j], ss[j]);
        atomicAdd(&bsq[c + j],  sq[j]);
    }
    __syncthreads();
    atomicAdd(&g_sum[t],   bsum[t]);
    atomicAdd(&g_sumsq[t], bsq[t]);
}

__global__ void bn_final(const float* __restrict__ gm, const float* __restrict__ bt,
                         float* __restrict__ sc_out, float* __restrict__ sh_out) {
    int f = threadIdx.x;
    float mu  = g_sum[f] / (float)NN;
    float var = g_sumsq[f] / (float)NN - mu * mu;
    float sc  = gm[f] * rsqrtf(var + 1e-5f);
    sc_out[f] = sc;
    sh_out[f] = bt[f] - mu * sc;
    g_sum[f] = 0.f; g_sumsq[f] = 0.f;
}

// ---------- MLP head: BN2 affine on pooled raw sums + log softmax ------------
__global__ void mlp_head(const float* __restrict__ fc1w, const float* __restrict__ fc1b,
                         const float* __restrict__ fc2w, const float* __restrict__ fc2b,
                         float* __restrict__ out) {
    __shared__ float p[F];
    __shared__ float z[CC];
    __shared__ float l[NCLS];
    __shared__ float red[2];
    int g = blockIdx.x;
    int t = threadIdx.x;   // 64
    float cnt = fmaxf(g_cnt[g], 1.f);
    float inv = 1.f / cnt;
    // pooled_mean = (sc2 * sum + sh2 * cnt) / cnt
    for (int k = t; k < F; k += 64)
        p[k] = (g_sc2[k] * g_pool[g * F + k] + g_sh2[k] * cnt) * inv;
    __syncthreads();
    float acc = fc1b[t];
    for (int k = 0; k < F; k++) acc += p[k] * fc1w[k * CC + t];
    z[t] = fmaxf(acc, 0.f);
    __syncthreads();
    if (t < NCLS) {
        float a = fc2b[t];
        for (int k = 0; k < CC; k++) a += z[k] * fc2w[k * NCLS + t];
        l[t] = a;
    }
    __syncthreads();
    if (t == 0) {
        float m = l[0];
        for (int i = 1; i < NCLS; i++) m = fmaxf(m, l[i]);
        float s = 0.f;
        for (int i = 0; i < NCLS; i++) s += expf(l[i] - m);
        red[0] = m; red[1] = logf(s);
    }
    __syncthreads();
    if (t < NCLS) out[g * NCLS + t] = l[t] - red[0] - red[1];
}

// ---------------------------------- launch ----------------------------------
extern "C" void kernel_launch(void* const* d_in, const int* in_sizes, int n_in,
                              void* d_out, int out_size) {
    const float* x    = (const float*)d_in[0];
    const int*   ei   = (const int*)  d_in[1];
    const int*   bat  = (const int*)  d_in[2];
    const float* W1   = (const float*)d_in[3];
    const float* as1  = (const float*)d_in[4];
    const float* ad1  = (const float*)d_in[5];
    const float* b1   = (const float*)d_in[6];
    const float* gm1  = (const float*)d_in[7];
    const float* be1  = (const float*)d_in[8];
    const float* W2   = (const float*)d_in[9];
    const float* as2  = (const float*)d_in[10];
    const float* ad2  = (const float*)d_in[11];
    const float* b2   = (const float*)d_in[12];
    const float* gm2  = (const float*)d_in[13];
    const float* be2  = (const float*)d_in[14];
    const float* fc1w = (const float*)d_in[15];
    const float* fc1b = (const float*)d_in[16];
    const float* fc2w = (const float*)d_in[17];
    const float* fc2b = (const float*)d_in[18];
    float* out = (float*)d_out;

    __half* phh;
    float *py1, *psc1, *psh1, *psc2, *psh2;
    cudaGetSymbolAddress((void**)&phh,  g_hh);
    cudaGetSymbolAddress((void**)&py1,  g_y1);
    cudaGetSymbolAddress((void**)&psc1, g_sc1);
    cudaGetSymbolAddress((void**)&psh1, g_sh1);
    cudaGetSymbolAddress((void**)&psc2, g_sc2);
    cudaGetSymbolAddress((void**)&psh2, g_sh2);

    const int TPB = 256;
    const int nET = (ET + TPB - 1) / TPB;
    const int nNN = (NN + TPB - 1) / TPB;
    dim3 mmGrid((NN + 127) / 128, 2);
    const int nAGG  = (2 * NN + 8 * RPW - 1) / (8 * RPW);
    const int nZERO = (GG * F + TPB - 1) / TPB > nNN
                      ? (GG * F + TPB - 1) / TPB : nNN;

    // ---------------- CSR build + counts ----------------
    csr_zero<<<nZERO, TPB>>>();
    csr_hist<<<nET, TPB>>>(ei);
    cnt_hist<<<nNN, TPB>>>(bat);
    csr_scan<<<1, SCAN_T>>>();
    csr_scatter<<<nET, TPB>>>(ei);

    // ---------------- layer 1 ----------------
    conv_B<<<256, 256>>>(W1);
    gemm_bf16<<<mmGrid, 256>>>(x, phh, NN, NULL, NULL, as1, ad1);
    gat_agg<<<nAGG, 256>>>(b1, x, NULL, NULL, py1, bat, 0);
    bn_final<<<1, F>>>(gm1, be1, psc1, psh1);

    // ---------------- layer 2 (pooling fused; y2 never materialized) --------
    conv_B<<<256, 256>>>(W2);
    gemm_bf16<<<mmGrid, 256>>>(py1, phh, NN, psc1, psh1, as2, ad2);
    gat_agg<<<nAGG, 256>>>(b2, py1, psc1, psh1, NULL, bat, 1);
    bn_final<<<1, F>>>(gm2, be2, psc2, psh2);

    // ---------------- head ----------------
    mlp_head<<<GG, 64>>>(fc1w, fc1b, fc2w, fc2b, out);
}

// round 10
// speedup vs baseline: 3.5497x; 1.1591x over previous
#include <cuda_runtime.h>
#include <cuda_bf16.h>
#include <cuda_fp16.h>
#include <math.h>
#include <stdint.h>

#define NN   50000
#define EE   400000
#define ET   (EE + NN)
#define F    256
#define HH   4
#define CC   64
#define GG   64
#define NCLS 10

// ---------------- scratch (static device globals; no allocations) -----------
__device__ __align__(16) __half g_hh[(size_t)NN * F];   // h = A' @ W, fp16
__device__ float g_y1[NN * F];
__device__ float g_asrc[NN * HH];
__device__ float g_adst[NN * HH];
__device__ float g_sum[F], g_sumsq[F];
__device__ float g_sc1[F], g_sh1[F];
__device__ float g_sc2[F], g_sh2[F];
__device__ float g_pool[GG * F];        // raw sums of layer-2 output (pre-BN2)
__device__ float g_cnt[GG];
__device__ __align__(16) __nv_bfloat16 g_Bp[768 * 256];   // split W, stage-ordered
// CSR
__device__ int   g_cnt_n[NN];
__device__ int   g_rp[NN + 1];
__device__ int   g_col[ET];
#define SCAN_NB ((NN + 255) / 256)      // 196
__device__ int   g_blk[256];            // per-block sums (padded)

// ---------------- bf16 pack helpers ------------------------------------------
__device__ __forceinline__ uint32_t pack_hi(float a, float b) {
    __nv_bfloat162 h = __floats2bfloat162_rn(a, b);
    return *(uint32_t*)&h;
}
__device__ __forceinline__ uint32_t pack_lo(float a, float b, uint32_t hi) {
    __nv_bfloat162 h = *(__nv_bfloat162*)&hi;
    __nv_bfloat162 l = __floats2bfloat162_rn(a - __bfloat162float(h.x),
                                             b - __bfloat162float(h.y));
    return *(uint32_t*)&l;
}
__device__ __forceinline__ void red4(float* p, float a, float b, float c, float d) {
    asm volatile("red.global.add.v4.f32 [%0], {%1,%2,%3,%4};"
                 :: "l"(p), "f"(a), "f"(b), "f"(c), "f"(d) : "memory");
}

// ---- conv_B: W[256][256] -> B'[768][256], per 64-block j, per 32-half:
// rows [hi, hi, lo] so stages pair (A_hi*Bh, A_lo*Bh, A_hi*Bl) ------------------
__global__ void conv_B(const float* __restrict__ W) {
    int k = blockIdx.x, n = threadIdx.x;
    float v = W[k * 256 + n];
    __nv_bfloat16 hi = __float2bfloat16_rn(v);
    __nv_bfloat16 lo = __float2bfloat16_rn(v - __bfloat162float(hi));
    int j = k >> 6, kl = k & 63, half = kl >> 5, i = kl & 31;
    int base = j * 192 + half * 96 + i;
    g_Bp[(size_t)(base)      * 256 + n] = hi;
    g_Bp[(size_t)(base + 32) * 256 + n] = hi;
    g_Bp[(size_t)(base + 64) * 256 + n] = lo;
}

// ============ bf16 mma.sync GEMM, K'=768, inline A split, fused attn =========
#define PA 80
#define PB 272
#define ABUF (128 * PA)
#define BBUF (32 * PB)
#define STG  (ABUF + BBUF)

__device__ __forceinline__ uint32_t smem_u32(const void* p) {
    uint32_t a;
    asm("{ .reg .u64 t; cvta.to.shared.u64 t, %1; cvt.u32.u64 %0, t; }"
        : "=r"(a) : "l"(p));
    return a;
}
__device__ __forceinline__ void ldsm_x4(uint32_t* a, uint32_t addr) {
    asm volatile("ldmatrix.sync.aligned.m8n8.x4.shared.b16 {%0,%1,%2,%3}, [%4];"
                 : "=r"(a[0]), "=r"(a[1]), "=r"(a[2]), "=r"(a[3]) : "r"(addr));
}
__device__ __forceinline__ void ldsm_x2t(uint32_t* b, uint32_t addr) {
    asm volatile("ldmatrix.sync.aligned.m8n8.x2.trans.shared.b16 {%0,%1}, [%2];"
                 : "=r"(b[0]), "=r"(b[1]) : "r"(addr));
}
__device__ __forceinline__ void mma16816(float* d, const uint32_t* a,
                                         const uint32_t* b) {
    asm volatile(
        "mma.sync.aligned.m16n8k16.row.col.f32.bf16.bf16.f32 "
        "{%0,%1,%2,%3}, {%4,%5,%6,%7}, {%8,%9}, {%0,%1,%2,%3};"
        : "+f"(d[0]), "+f"(d[1]), "+f"(d[2]), "+f"(d[3])
        : "r"(a[0]), "r"(a[1]), "r"(a[2]), "r"(a[3]), "r"(b[0]), "r"(b[1]));
}
__device__ __forceinline__ void load_split(const float* agp32, int kbase, int sidx,
                                           const float* scale, const float* shift,
                                           bool ok, float* e, uint32_t* hp) {
    if (ok) {
#pragma unroll
        for (int i = 0; i < 4; i++) {
            float4 v = *(const float4*)(agp32 + kbase + i * 4);
            e[i * 4 + 0] = v.x; e[i * 4 + 1] = v.y;
            e[i * 4 + 2] = v.z; e[i * 4 + 3] = v.w;
        }
        if (scale) {
#pragma unroll
            for (int i = 0; i < 16; i++)
                e[i] = e[i] * scale[sidx + i] + shift[sidx + i];
        }
    } else {
#pragma unroll
        for (int i = 0; i < 16; i++) e[i] = 0.f;
    }
#pragma unroll
    for (int p = 0; p < 8; p++) hp[p] = pack_hi(e[2 * p], e[2 * p + 1]);
}

__global__ __launch_bounds__(256)
void gemm_bf16(const float* __restrict__ A, __half* __restrict__ C, int M,
               const float* __restrict__ scale, const float* __restrict__ shift,
               const float* __restrict__ atts, const float* __restrict__ attd) {
    __shared__ __align__(16) char sm[2 * STG];
    const int t = threadIdx.x, lane = t & 31, w = t >> 5;
    const int wm = w & 1, wn = w >> 1;
    const int row0 = blockIdx.x * 128, col0 = blockIdx.y * 128;
    const uint32_t sb = smem_u32(sm);

    float acc[4][4][4];
#pragma unroll
    for (int i = 0; i < 4; i++)
#pragma unroll
        for (int j = 0; j < 4; j++)
#pragma unroll
            for (int k = 0; k < 4; k++) acc[i][j][k] = 0.f;

    const int ar = t >> 1, apart = t & 1;
    const bool a_ok = (row0 + ar) < M;
    const float* agp32 = A + (size_t)(row0 + ar) * 256 + apart * 16;
    const int br = t >> 3, bseg = t & 7;
    const __nv_bfloat16* bgp = g_Bp + (size_t)br * 256 + col0 + bseg * 16;

    float e[16];
    uint32_t hp[8];

    load_split(agp32, 0, apart * 16, scale, shift, a_ok, e, hp);
    {
        char* pa = sm + ar * PA + apart * 32;
        *(uint4*)pa = *(uint4*)&hp[0];
        *(uint4*)(pa + 16) = *(uint4*)&hp[4];
        uint4 lb0 = *(const uint4*)(bgp);
        uint4 lb1 = *(const uint4*)(bgp + 8);
        char* pb = sm + ABUF + br * PB + bseg * 32;
        *(uint4*)pb = lb0; *(uint4*)(pb + 16) = lb1;
    }
    __syncthreads();

    for (int s = 0; s < 24; s++) {
        const int buf = s & 1;
        const uint32_t sba = sb + buf * STG;
        const int sn = s + 1;
        const int rn = sn % 6;
        uint4 lb0, lb1;
        if (s < 23) {
            lb0 = *(const uint4*)(bgp + (size_t)(sn * 32) * 256);
            lb1 = *(const uint4*)(bgp + (size_t)(sn * 32) * 256 + 8);
            if (rn == 0 || rn == 3) {
                int kbase = (sn / 6) * 64 + (rn == 3 ? 32 : 0);
                load_split(agp32, kbase, kbase + apart * 16, scale, shift,
                           a_ok, e, hp);
            }
        }
#pragma unroll
        for (int kh = 0; kh < 2; kh++) {
            uint32_t afr[4][4], bfr[4][2];
#pragma unroll
            for (int mi = 0; mi < 4; mi++) {
                uint32_t addr = sba + (uint32_t)(wm * 64 + mi * 16 + (lane & 15)) * PA
                              + kh * 32 + (lane >> 4) * 16;
                ldsm_x4(afr[mi], addr);
            }
#pragma unroll
            for (int nf = 0; nf < 4; nf++) {
                uint32_t addr = sba + ABUF + (uint32_t)(kh * 16 + (lane & 15)) * PB
                              + (wn * 32 + nf * 8) * 2;
                ldsm_x2t(bfr[nf], addr);
            }
#pragma unroll
            for (int mi = 0; mi < 4; mi++)
#pragma unroll
                for (int nf = 0; nf < 4; nf++)
                    mma16816(acc[mi][nf], afr[mi], bfr[nf]);
        }
        if (s < 23) {
            char* base = sm + (buf ^ 1) * STG;
            char* pb = base + ABUF + br * PB + bseg * 32;
            *(uint4*)pb = lb0; *(uint4*)(pb + 16) = lb1;
            if (rn == 0 || rn == 3) {
                char* pa = base + ar * PA + apart * 32;
                *(uint4*)pa = *(uint4*)&hp[0];
                *(uint4*)(pa + 16) = *(uint4*)&hp[4];
            } else if (rn == 1 || rn == 4) {
                uint32_t lp[8];
#pragma unroll
                for (int p = 0; p < 8; p++)
                    lp[p] = pack_lo(e[2 * p], e[2 * p + 1], hp[p]);
                char* pa = base + ar * PA + apart * 32;
                *(uint4*)pa = *(uint4*)&lp[0];
                *(uint4*)(pa + 16) = *(uint4*)&lp[4];
            }
        }
        __syncthreads();
    }

    // ---- epilogue: store C (fp16), per-warp att partials -> smem, combine ---
    float* part = (float*)sm;
#pragma unroll
    for (int mi = 0; mi < 4; mi++) {
        int lr_lo = wm * 64 + mi * 16 + (lane >> 2);
        int lr_hi = lr_lo + 8;
        int r_lo = row0 + lr_lo, r_hi = row0 + lr_hi;
        float ds0 = 0.f, dd0 = 0.f, ds1 = 0.f, dd1 = 0.f;
#pragma unroll
        for (int nf = 0; nf < 4; nf++) {
            int c = col0 + wn * 32 + nf * 8 + (lane & 3) * 2;
            float v0 = acc[mi][nf][0], v1 = acc[mi][nf][1];
            float v2 = acc[mi][nf][2], v3 = acc[mi][nf][3];
            if (r_lo < M) *(__half2*)(C + (size_t)r_lo * 256 + c) = __floats2half2_rn(v0, v1);
            if (r_hi < M) *(__half2*)(C + (size_t)r_hi * 256 + c) = __floats2half2_rn(v2, v3);
            float s0 = atts[c], s1 = atts[c + 1];
            float d0 = attd[c], d1 = attd[c + 1];
            ds0 += v0 * s0 + v1 * s1; dd0 += v0 * d0 + v1 * d1;
            ds1 += v2 * s0 + v3 * s1; dd1 += v2 * d0 + v3 * d1;
        }
#pragma unroll
        for (int o = 1; o <= 2; o <<= 1) {
            ds0 += __shfl_xor_sync(0xFFFFFFFFu, ds0, o);
            dd0 += __shfl_xor_sync(0xFFFFFFFFu, dd0, o);
            ds1 += __shfl_xor_sync(0xFFFFFFFFu, ds1, o);
            dd1 += __shfl_xor_sync(0xFFFFFFFFu, dd1, o);
        }
        if ((lane & 3) == 0) {
            part[(lr_lo * 4 + wn) * 2 + 0] = ds0;
            part[(lr_lo * 4 + wn) * 2 + 1] = dd0;
            part[(lr_hi * 4 + wn) * 2 + 0] = ds1;
            part[(lr_hi * 4 + wn) * 2 + 1] = dd1;
        }
    }
    __syncthreads();
    {
        int lr = t & 127, sd = t >> 7;
        int gr = row0 + lr;
        if (gr < M) {
            float* dst = sd ? g_adst : g_asrc;
#pragma unroll
            for (int hl = 0; hl < 2; hl++) {
                float v = part[(lr * 4 + 2 * hl) * 2 + sd]
                        + part[(lr * 4 + 2 * hl + 1) * 2 + sd];
                dst[gr * HH + (col0 >> 6) + hl] = v;
            }
        }
    }
}

// ------------------------------ CSR build -----------------------------------
__global__ void csr_zero() {
    int i = blockIdx.x * blockDim.x + threadIdx.x;
    if (i < NN) g_cnt_n[i] = 0;
    if (i < F)  { g_sum[i] = 0.f; g_sumsq[i] = 0.f; }
    if (i < GG * F) g_pool[i] = 0.f;
    if (i < GG) g_cnt[i] = 0.f;
}
__global__ void csr_hist(const int* __restrict__ ei) {
    int e = blockIdx.x * blockDim.x + threadIdx.x;
    if (e >= ET) return;
    int d = (e < EE) ? ei[EE + e] : e - EE;
    atomicAdd(&g_cnt_n[d], 1);
}
// per-graph node counts (64 bins, smem histogram)
__global__ void cnt_hist(const int* __restrict__ bt) {
    __shared__ int hcnt[GG];
    int t = threadIdx.x;
    if (t < GG) hcnt[t] = 0;
    __syncthreads();
    int i = blockIdx.x * blockDim.x + t;
    if (i < NN) atomicAdd(&hcnt[bt[i]], 1);
    __syncthreads();
    if (t < GG && hcnt[t]) atomicAdd(&g_cnt[t], (float)hcnt[t]);
}

// ---------- multi-block exclusive scan of g_cnt_n -> g_rp + cursor ----------
__global__ void scan_p1() {           // per-block sums
    __shared__ int ps[256];
    int t = threadIdx.x, i = blockIdx.x * 256 + t;
    int v = (i < NN) ? g_cnt_n[i] : 0;
    ps[t] = v;
    __syncthreads();
#pragma unroll
    for (int off = 128; off; off >>= 1) {
        if (t < off) ps[t] += ps[t + off];
        __syncthreads();
    }
    if (t == 0) g_blk[blockIdx.x] = ps[0];
}
__global__ void scan_p2() {           // inclusive scan of 196 block sums
    __shared__ int ps[256];
    int t = threadIdx.x;
    ps[t] = (t < SCAN_NB) ? g_blk[t] : 0;
    __syncthreads();
#pragma unroll
    for (int off = 1; off < 256; off <<= 1) {
        int v = (t >= off) ? ps[t - off] : 0;
        __syncthreads();
        ps[t] += v;
        __syncthreads();
    }
    g_blk[t] = ps[t];                 // inclusive
}
__global__ void scan_p3() {           // in-block exclusive scan + offset
    __shared__ int ps[256];
    int t = threadIdx.x, b = blockIdx.x, i = b * 256 + t;
    int v = (i < NN) ? g_cnt_n[i] : 0;
    ps[t] = v;
    __syncthreads();
#pragma unroll
    for (int off = 1; off < 256; off <<= 1) {
        int u = (t >= off) ? ps[t - off] : 0;
        __syncthreads();
        ps[t] += u;
        __syncthreads();
    }
    int base = b ? g_blk[b - 1] : 0;
    int excl = base + ps[t] - v;
    if (i < NN) {
        g_rp[i] = excl;
        g_cnt_n[i] = excl;            // write-cursor for scatter
        if (i == NN - 1) g_rp[NN] = excl + v;
    }
}
__global__ void csr_scatter(const int* __restrict__ ei) {
    int e = blockIdx.x * blockDim.x + threadIdx.x;
    if (e >= ET) return;
    int s, d;
    if (e < EE) { s = ei[e]; d = ei[EE + e]; }
    else        { s = d = e - EE; }
    int pos = atomicAdd(&g_cnt_n[d], 1);
    g_col[pos] = s;
}

// ----- fused GAT aggregate + bias + ELU + residual(+BN) + BN stats -----------
// Warp per (dst-row, 128-col half); edge loop software-pipelined (unroll 4).
// do_pool: accumulate raw per-graph sums into g_pool instead of writing y.
#define RPW 4
__global__ __launch_bounds__(256)
void gat_agg(const float* __restrict__ b,
             const float* __restrict__ xin,
             const float* __restrict__ rscale,
             const float* __restrict__ rshift,
             float* __restrict__ y,
             const int* __restrict__ bat, int do_pool) {
    __shared__ float bsum[F], bsq[F];
    int t = threadIdx.x;
    bsum[t] = 0.f; bsq[t] = 0.f;
    __syncthreads();

    int lane = t & 31;
    int gwarp = blockIdx.x * 8 + (t >> 5);
    int hf = gwarp & 1;
    int d0 = (gwarp >> 1) * RPW;
    int c = hf * 128 + (lane << 2);
    int h = hf * 2 + (lane >> 4);

    float4 bias = *(const float4*)(b + c);
    float scv = rscale ? rscale[c] : 1.f,     shv = rshift ? rshift[c] : 0.f;
    float scy = rscale ? rscale[c + 1] : 1.f, shy = rshift ? rshift[c + 1] : 0.f;
    float scz = rscale ? rscale[c + 2] : 1.f, shz = rshift ? rshift[c + 2] : 0.f;
    float scw = rscale ? rscale[c + 3] : 1.f, shw = rshift ? rshift[c + 3] : 0.f;

    float ss[4] = {0, 0, 0, 0};
    float sq[4] = {0, 0, 0, 0};
    float pa[4] = {0, 0, 0, 0};
    int curg = -1;

#pragma unroll
    for (int rr = 0; rr < RPW; rr++) {
        int d = d0 + rr;
        if (d >= NN) break;
        float ad = g_adst[d * HH + h];
        float ax = 0.f, ay = 0.f, az = 0.f, aw = 0.f;
        float den = 0.f;
        int e0 = g_rp[d], e1 = g_rp[d + 1];
        int e = e0;
        for (; e + 4 <= e1; e += 4) {
            int s0 = g_col[e], s1 = g_col[e + 1];
            int s2 = g_col[e + 2], s3 = g_col[e + 3];
            float a0 = g_asrc[s0 * HH + h], a1 = g_asrc[s1 * HH + h];
            float a2 = g_asrc[s2 * HH + h], a3 = g_asrc[s3 * HH + h];
            uint2 u0 = *(const uint2*)(g_hh + (size_t)s0 * F + c);
            uint2 u1 = *(const uint2*)(g_hh + (size_t)s1 * F + c);
            uint2 u2 = *(const uint2*)(g_hh + (size_t)s2 * F + c);
            uint2 u3 = *(const uint2*)(g_hh + (size_t)s3 * F + c);
            float v0 = a0 + ad, v1 = a1 + ad, v2 = a2 + ad, v3 = a3 + ad;
            v0 = v0 > 0.f ? v0 : 0.2f * v0;
            v1 = v1 > 0.f ? v1 : 0.2f * v1;
            v2 = v2 > 0.f ? v2 : 0.2f * v2;
            v3 = v3 > 0.f ? v3 : 0.2f * v3;
            float x0 = __expf(v0), x1 = __expf(v1);
            float x2 = __expf(v2), x3 = __expf(v3);
            den += (x0 + x1) + (x2 + x3);
            float2 p0 = __half22float2(*(__half2*)&u0.x);
            float2 q0 = __half22float2(*(__half2*)&u0.y);
            float2 p1 = __half22float2(*(__half2*)&u1.x);
            float2 q1 = __half22float2(*(__half2*)&u1.y);
            float2 p2 = __half22float2(*(__half2*)&u2.x);
            float2 q2 = __half22float2(*(__half2*)&u2.y);
            float2 p3 = __half22float2(*(__half2*)&u3.x);
            float2 q3 = __half22float2(*(__half2*)&u3.y);
            ax += x0 * p0.x + x1 * p1.x + x2 * p2.x + x3 * p3.x;
            ay += x0 * p0.y + x1 * p1.y + x2 * p2.y + x3 * p3.y;
            az += x0 * q0.x + x1 * q1.x + x2 * q2.x + x3 * q3.x;
            aw += x0 * q0.y + x1 * q1.y + x2 * q2.y + x3 * q3.y;
        }
        for (; e < e1; e++) {
            int s = g_col[e];
            float v = g_asrc[s * HH + h] + ad;
            v = v > 0.f ? v : 0.2f * v;
            float ex = __expf(v);
            den += ex;
            uint2 u = *(const uint2*)(g_hh + (size_t)s * F + c);
            float2 f0 = __half22float2(*(__half2*)&u.x);
            float2 f1 = __half22float2(*(__half2*)&u.y);
            ax += ex * f0.x; ay += ex * f0.y;
            az += ex * f1.x; aw += ex * f1.y;
        }
        float inv = __fdividef(1.f, den);
        float4 xr = *(const float4*)(xin + (size_t)d * F + c);
        float o[4];
        o[0] = ax * inv + bias.x; o[1] = ay * inv + bias.y;
        o[2] = az * inv + bias.z; o[3] = aw * inv + bias.w;
#pragma unroll
        for (int j = 0; j < 4; j++) o[j] = o[j] > 0.f ? o[j] : expm1f(o[j]);
        o[0] += xr.x * scv + shv; o[1] += xr.y * scy + shy;
        o[2] += xr.z * scz + shz; o[3] += xr.w * scw + shw;
        if (do_pool) {
            int gb = bat[d];
            if (gb != curg) {
                if (curg >= 0)
                    red4(&g_pool[curg * F + c], pa[0], pa[1], pa[2], pa[3]);
                curg = gb;
                pa[0] = pa[1] = pa[2] = pa[3] = 0.f;
            }
#pragma unroll
            for (int j = 0; j < 4; j++) pa[j] += o[j];
        } else {
            *(float4*)(y + (size_t)d * F + c) = make_float4(o[0], o[1], o[2], o[3]);
        }
#pragma unroll
        for (int j = 0; j < 4; j++) { ss[j] += o[j]; sq[j] += o[j] * o[j]; }
    }
    if (do_pool && curg >= 0)
        red4(&g_pool[curg * F + c], pa[0], pa[1], pa[2], pa[3]);
#pragma unroll
    for (int j = 0; j < 4; j++) {
        atomicAdd(&bsum[c + j], ss[j]);
        atomicAdd(&bsq[c + j],  sq[j]);
    }
    __syncthreads();
    atomicAdd(&g_sum[t],   bsum[t]);
    atomicAdd(&g_sumsq[t], bsq[t]);
}

__global__ void bn_final(const float* __restrict__ gm, const float* __restrict__ bt,
                         float* __restrict__ sc_out, float* __restrict__ sh_out) {
    int f = threadIdx.x;
    float mu  = g_sum[f] / (float)NN;
    float var = g_sumsq[f] / (float)NN - mu * mu;
    float sc  = gm[f] * rsqrtf(var + 1e-5f);
    sc_out[f] = sc;
    sh_out[f] = bt[f] - mu * sc;
    g_sum[f] = 0.f; g_sumsq[f] = 0.f;
}

// ---------- MLP head: BN2 affine on pooled raw sums + log softmax ------------
__global__ void mlp_head(const float* __restrict__ fc1w, const float* __restrict__ fc1b,
                         const float* __restrict__ fc2w, const float* __restrict__ fc2b,
                         float* __restrict__ out) {
    __shared__ float p[F];
    __shared__ float z[CC];
    __shared__ float l[NCLS];
    __shared__ float red[2];
    int g = blockIdx.x;
    int t = threadIdx.x;   // 64
    float cnt = fmaxf(g_cnt[g], 1.f);
    float inv = 1.f / cnt;
    for (int k = t; k < F; k += 64)
        p[k] = (g_sc2[k] * g_pool[g * F + k] + g_sh2[k] * cnt) * inv;
    __syncthreads();
    float acc = fc1b[t];
    for (int k = 0; k < F; k++) acc += p[k] * fc1w[k * CC + t];
    z[t] = fmaxf(acc, 0.f);
    __syncthreads();
    if (t < NCLS) {
        float a = fc2b[t];
        for (int k = 0; k < CC; k++) a += z[k] * fc2w[k * NCLS + t];
        l[t] = a;
    }
    __syncthreads();
    if (t == 0) {
        float m = l[0];
        for (int i = 1; i < NCLS; i++) m = fmaxf(m, l[i]);
        float s = 0.f;
        for (int i = 0; i < NCLS; i++) s += expf(l[i] - m);
        red[0] = m; red[1] = logf(s);
    }
    __syncthreads();
    if (t < NCLS) out[g * NCLS + t] = l[t] - red[0] - red[1];
}

// ---------------------------------- launch ----------------------------------
extern "C" void kernel_launch(void* const* d_in, const int* in_sizes, int n_in,
                              void* d_out, int out_size) {
    const float* x    = (const float*)d_in[0];
    const int*   ei   = (const int*)  d_in[1];
    const int*   bat  = (const int*)  d_in[2];
    const float* W1   = (const float*)d_in[3];
    const float* as1  = (const float*)d_in[4];
    const float* ad1  = (const float*)d_in[5];
    const float* b1   = (const float*)d_in[6];
    const float* gm1  = (const float*)d_in[7];
    const float* be1  = (const float*)d_in[8];
    const float* W2   = (const float*)d_in[9];
    const float* as2  = (const float*)d_in[10];
    const float* ad2  = (const float*)d_in[11];
    const float* b2   = (const float*)d_in[12];
    const float* gm2  = (const float*)d_in[13];
    const float* be2  = (const float*)d_in[14];
    const float* fc1w = (const float*)d_in[15];
    const float* fc1b = (const float*)d_in[16];
    const float* fc2w = (const float*)d_in[17];
    const float* fc2b = (const float*)d_in[18];
    float* out = (float*)d_out;

    __half* phh;
    float *py1, *psc1, *psh1, *psc2, *psh2;
    cudaGetSymbolAddress((void**)&phh,  g_hh);
    cudaGetSymbolAddress((void**)&py1,  g_y1);
    cudaGetSymbolAddress((void**)&psc1, g_sc1);
    cudaGetSymbolAddress((void**)&psh1, g_sh1);
    cudaGetSymbolAddress((void**)&psc2, g_sc2);
    cudaGetSymbolAddress((void**)&psh2, g_sh2);

    const int TPB = 256;
    const int nET = (ET + TPB - 1) / TPB;
    const int nNN = (NN + TPB - 1) / TPB;
    dim3 mmGrid((NN + 127) / 128, 2);
    const int nAGG  = (2 * NN + 8 * RPW - 1) / (8 * RPW);
    const int nZERO = (GG * F + TPB - 1) / TPB > nNN
                      ? (GG * F + TPB - 1) / TPB : nNN;

    // ---------------- CSR build + counts ----------------
    csr_zero<<<nZERO, TPB>>>();
    csr_hist<<<nET, TPB>>>(ei);
    cnt_hist<<<nNN, TPB>>>(bat);
    scan_p1<<<SCAN_NB, 256>>>();
    scan_p2<<<1, 256>>>();
    scan_p3<<<SCAN_NB, 256>>>();
    csr_scatter<<<nET, TPB>>>(ei);

    // ---------------- layer 1 ----------------
    conv_B<<<256, 256>>>(W1);
    gemm_bf16<<<mmGrid, 256>>>(x, phh, NN, NULL, NULL, as1, ad1);
    gat_agg<<<nAGG, 256>>>(b1, x, NULL, NULL, py1, bat, 0);
    bn_final<<<1, F>>>(gm1, be1, psc1, psh1);

    // ---------------- layer 2 (pooling fused; y2 never materialized) --------
    conv_B<<<256, 256>>>(W2);
    gemm_bf16<<<mmGrid, 256>>>(py1, phh, NN, psc1, psh1, as2, ad2);
    gat_agg<<<nAGG, 256>>>(b2, py1, psc1, psh1, NULL, bat, 1);
    bn_final<<<1, F>>>(gm2, be2, psc2, psh2);

    // ---------------- head ----------------
    mlp_head<<<GG, 64>>>(fc1w, fc1b, fc2w, fc2b, out);
}

// round 11
// speedup vs baseline: 3.7215x; 1.0484x over previous
#include <cuda_runtime.h>
#include <cuda_bf16.h>
#include <cuda_fp16.h>
#include <math.h>
#include <stdint.h>

#define NN   50000
#define EE   400000
#define ET   (EE + NN)
#define F    256
#define HH   4
#define CC   64
#define GG   64
#define NCLS 10

// ---------------- scratch (static device globals; no allocations) -----------
__device__ __align__(16) __half g_hh[(size_t)NN * F];   // h = A' @ W, fp16
__device__ float g_y1[NN * F];
__device__ float g_asrc[NN * HH];
__device__ float g_adst[NN * HH];
__device__ float g_sum[F], g_sumsq[F];
__device__ float g_sc1[F], g_sh1[F];
__device__ float g_sc2[F], g_sh2[F];
__device__ float g_pool[GG * F];        // raw sums of layer-2 output (pre-BN2)
__device__ float g_cnt[GG];
__device__ __align__(16) __nv_bfloat16 g_Bp[768 * 256];   // split W, stage-ordered
// CSR
__device__ int   g_cnt_n[NN];
__device__ int   g_rp[NN + 1];
__device__ int   g_col[ET];
#define SCAN_NB ((NN + 255) / 256)      // 196
__device__ int   g_blk[256];            // per-block sums (padded)

// ---------------- bf16 pack helpers ------------------------------------------
__device__ __forceinline__ uint32_t pack_hi(float a, float b) {
    __nv_bfloat162 h = __floats2bfloat162_rn(a, b);
    return *(uint32_t*)&h;
}
__device__ __forceinline__ uint32_t pack_lo(float a, float b, uint32_t hi) {
    __nv_bfloat162 h = *(__nv_bfloat162*)&hi;
    __nv_bfloat162 l = __floats2bfloat162_rn(a - __bfloat162float(h.x),
                                             b - __bfloat162float(h.y));
    return *(uint32_t*)&l;
}
__device__ __forceinline__ void red4(float* p, float a, float b, float c, float d) {
    asm volatile("red.global.add.v4.f32 [%0], {%1,%2,%3,%4};"
                 :: "l"(p), "f"(a), "f"(b), "f"(c), "f"(d) : "memory");
}

// ---- conv_B: W[256][256] -> B'[768][256], per 64-block j, per 32-half:
// rows [hi, hi, lo] so stages pair (A_hi*Bh, A_lo*Bh, A_hi*Bl) ------------------
__global__ void conv_B(const float* __restrict__ W) {
    int k = blockIdx.x, n = threadIdx.x;
    float v = W[k * 256 + n];
    __nv_bfloat16 hi = __float2bfloat16_rn(v);
    __nv_bfloat16 lo = __float2bfloat16_rn(v - __bfloat162float(hi));
    int j = k >> 6, kl = k & 63, half = kl >> 5, i = kl & 31;
    int base = j * 192 + half * 96 + i;
    g_Bp[(size_t)(base)      * 256 + n] = hi;
    g_Bp[(size_t)(base + 32) * 256 + n] = hi;
    g_Bp[(size_t)(base + 64) * 256 + n] = lo;
}

// ============ bf16 mma.sync GEMM, K'=768, inline A split, fused attn =========
#define PA 80
#define PB 272
#define ABUF (128 * PA)
#define BBUF (32 * PB)
#define STG  (ABUF + BBUF)

__device__ __forceinline__ uint32_t smem_u32(const void* p) {
    uint32_t a;
    asm("{ .reg .u64 t; cvta.to.shared.u64 t, %1; cvt.u32.u64 %0, t; }"
        : "=r"(a) : "l"(p));
    return a;
}
__device__ __forceinline__ void ldsm_x4(uint32_t* a, uint32_t addr) {
    asm volatile("ldmatrix.sync.aligned.m8n8.x4.shared.b16 {%0,%1,%2,%3}, [%4];"
                 : "=r"(a[0]), "=r"(a[1]), "=r"(a[2]), "=r"(a[3]) : "r"(addr));
}
__device__ __forceinline__ void ldsm_x2t(uint32_t* b, uint32_t addr) {
    asm volatile("ldmatrix.sync.aligned.m8n8.x2.trans.shared.b16 {%0,%1}, [%2];"
                 : "=r"(b[0]), "=r"(b[1]) : "r"(addr));
}
__device__ __forceinline__ void mma16816(float* d, const uint32_t* a,
                                         const uint32_t* b) {
    asm volatile(
        "mma.sync.aligned.m16n8k16.row.col.f32.bf16.bf16.f32 "
        "{%0,%1,%2,%3}, {%4,%5,%6,%7}, {%8,%9}, {%0,%1,%2,%3};"
        : "+f"(d[0]), "+f"(d[1]), "+f"(d[2]), "+f"(d[3])
        : "r"(a[0]), "r"(a[1]), "r"(a[2]), "r"(a[3]), "r"(b[0]), "r"(b[1]));
}
__device__ __forceinline__ void load_split(const float* agp32, int kbase, int sidx,
                                           const float* scale, const float* shift,
                                           bool ok, float* e, uint32_t* hp) {
    if (ok) {
#pragma unroll
        for (int i = 0; i < 4; i++) {
            float4 v = *(const float4*)(agp32 + kbase + i * 4);
            e[i * 4 + 0] = v.x; e[i * 4 + 1] = v.y;
            e[i * 4 + 2] = v.z; e[i * 4 + 3] = v.w;
        }
        if (scale) {
#pragma unroll
            for (int i = 0; i < 16; i++)
                e[i] = e[i] * scale[sidx + i] + shift[sidx + i];
        }
    } else {
#pragma unroll
        for (int i = 0; i < 16; i++) e[i] = 0.f;
    }
#pragma unroll
    for (int p = 0; p < 8; p++) hp[p] = pack_hi(e[2 * p], e[2 * p + 1]);
}

__global__ __launch_bounds__(256)
void gemm_bf16(const float* __restrict__ A, __half* __restrict__ C, int M,
               const float* __restrict__ scale, const float* __restrict__ shift,
               const float* __restrict__ atts, const float* __restrict__ attd) {
    __shared__ __align__(16) char sm[2 * STG];
    const int t = threadIdx.x, lane = t & 31, w = t >> 5;
    const int wm = w & 1, wn = w >> 1;
    const int row0 = blockIdx.x * 128, col0 = blockIdx.y * 128;
    const uint32_t sb = smem_u32(sm);

    float acc[4][4][4];
#pragma unroll
    for (int i = 0; i < 4; i++)
#pragma unroll
        for (int j = 0; j < 4; j++)
#pragma unroll
            for (int k = 0; k < 4; k++) acc[i][j][k] = 0.f;

    const int ar = t >> 1, apart = t & 1;
    const bool a_ok = (row0 + ar) < M;
    const float* agp32 = A + (size_t)(row0 + ar) * 256 + apart * 16;
    const int br = t >> 3, bseg = t & 7;
    const __nv_bfloat16* bgp = g_Bp + (size_t)br * 256 + col0 + bseg * 16;

    float e[16];
    uint32_t hp[8];

    load_split(agp32, 0, apart * 16, scale, shift, a_ok, e, hp);
    {
        char* pa = sm + ar * PA + apart * 32;
        *(uint4*)pa = *(uint4*)&hp[0];
        *(uint4*)(pa + 16) = *(uint4*)&hp[4];
        uint4 lb0 = *(const uint4*)(bgp);
        uint4 lb1 = *(const uint4*)(bgp + 8);
        char* pb = sm + ABUF + br * PB + bseg * 32;
        *(uint4*)pb = lb0; *(uint4*)(pb + 16) = lb1;
    }
    __syncthreads();

    for (int s = 0; s < 24; s++) {
        const int buf = s & 1;
        const uint32_t sba = sb + buf * STG;
        const int sn = s + 1;
        const int rn = sn % 6;
        uint4 lb0, lb1;
        if (s < 23) {
            lb0 = *(const uint4*)(bgp + (size_t)(sn * 32) * 256);
            lb1 = *(const uint4*)(bgp + (size_t)(sn * 32) * 256 + 8);
            if (rn == 0 || rn == 3) {
                int kbase = (sn / 6) * 64 + (rn == 3 ? 32 : 0);
                load_split(agp32, kbase, kbase + apart * 16, scale, shift,
                           a_ok, e, hp);
            }
        }
#pragma unroll
        for (int kh = 0; kh < 2; kh++) {
            uint32_t afr[4][4], bfr[4][2];
#pragma unroll
            for (int mi = 0; mi < 4; mi++) {
                uint32_t addr = sba + (uint32_t)(wm * 64 + mi * 16 + (lane & 15)) * PA
                              + kh * 32 + (lane >> 4) * 16;
                ldsm_x4(afr[mi], addr);
            }
#pragma unroll
            for (int nf = 0; nf < 4; nf++) {
                uint32_t addr = sba + ABUF + (uint32_t)(kh * 16 + (lane & 15)) * PB
                              + (wn * 32 + nf * 8) * 2;
                ldsm_x2t(bfr[nf], addr);
            }
#pragma unroll
            for (int mi = 0; mi < 4; mi++)
#pragma unroll
                for (int nf = 0; nf < 4; nf++)
                    mma16816(acc[mi][nf], afr[mi], bfr[nf]);
        }
        if (s < 23) {
            char* base = sm + (buf ^ 1) * STG;
            char* pb = base + ABUF + br * PB + bseg * 32;
            *(uint4*)pb = lb0; *(uint4*)(pb + 16) = lb1;
            if (rn == 0 || rn == 3) {
                char* pa = base + ar * PA + apart * 32;
                *(uint4*)pa = *(uint4*)&hp[0];
                *(uint4*)(pa + 16) = *(uint4*)&hp[4];
            } else if (rn == 1 || rn == 4) {
                uint32_t lp[8];
#pragma unroll
                for (int p = 0; p < 8; p++)
                    lp[p] = pack_lo(e[2 * p], e[2 * p + 1], hp[p]);
                char* pa = base + ar * PA + apart * 32;
                *(uint4*)pa = *(uint4*)&lp[0];
                *(uint4*)(pa + 16) = *(uint4*)&lp[4];
            }
        }
        __syncthreads();
    }

    // ---- epilogue: store C (fp16), per-warp att partials -> smem, combine ---
    float* part = (float*)sm;
#pragma unroll
    for (int mi = 0; mi < 4; mi++) {
        int lr_lo = wm * 64 + mi * 16 + (lane >> 2);
        int lr_hi = lr_lo + 8;
        int r_lo = row0 + lr_lo, r_hi = row0 + lr_hi;
        float ds0 = 0.f, dd0 = 0.f, ds1 = 0.f, dd1 = 0.f;
#pragma unroll
        for (int nf = 0; nf < 4; nf++) {
            int c = col0 + wn * 32 + nf * 8 + (lane & 3) * 2;
            float v0 = acc[mi][nf][0], v1 = acc[mi][nf][1];
            float v2 = acc[mi][nf][2], v3 = acc[mi][nf][3];
            if (r_lo < M) *(__half2*)(C + (size_t)r_lo * 256 + c) = __floats2half2_rn(v0, v1);
            if (r_hi < M) *(__half2*)(C + (size_t)r_hi * 256 + c) = __floats2half2_rn(v2, v3);
            float s0 = atts[c], s1 = atts[c + 1];
            float d0 = attd[c], d1 = attd[c + 1];
            ds0 += v0 * s0 + v1 * s1; dd0 += v0 * d0 + v1 * d1;
            ds1 += v2 * s0 + v3 * s1; dd1 += v2 * d0 + v3 * d1;
        }
#pragma unroll
        for (int o = 1; o <= 2; o <<= 1) {
            ds0 += __shfl_xor_sync(0xFFFFFFFFu, ds0, o);
            dd0 += __shfl_xor_sync(0xFFFFFFFFu, dd0, o);
            ds1 += __shfl_xor_sync(0xFFFFFFFFu, ds1, o);
            dd1 += __shfl_xor_sync(0xFFFFFFFFu, dd1, o);
        }
        if ((lane & 3) == 0) {
            part[(lr_lo * 4 + wn) * 2 + 0] = ds0;
            part[(lr_lo * 4 + wn) * 2 + 1] = dd0;
            part[(lr_hi * 4 + wn) * 2 + 0] = ds1;
            part[(lr_hi * 4 + wn) * 2 + 1] = dd1;
        }
    }
    __syncthreads();
    {
        int lr = t & 127, sd = t >> 7;
        int gr = row0 + lr;
        if (gr < M) {
            float* dst = sd ? g_adst : g_asrc;
#pragma unroll
            for (int hl = 0; hl < 2; hl++) {
                float v = part[(lr * 4 + 2 * hl) * 2 + sd]
                        + part[(lr * 4 + 2 * hl + 1) * 2 + sd];
                dst[gr * HH + (col0 >> 6) + hl] = v;
            }
        }
    }
}

// ------------------------------ CSR build -----------------------------------
__global__ void csr_zero() {
    int i = blockIdx.x * blockDim.x + threadIdx.x;
    if (i < NN) g_cnt_n[i] = 0;
    if (i < F)  { g_sum[i] = 0.f; g_sumsq[i] = 0.f; }
    if (i < GG * F) g_pool[i] = 0.f;
    if (i < GG) g_cnt[i] = 0.f;
}
__global__ void csr_hist(const int* __restrict__ ei) {
    int e = blockIdx.x * blockDim.x + threadIdx.x;
    if (e >= ET) return;
    int d = (e < EE) ? ei[EE + e] : e - EE;
    atomicAdd(&g_cnt_n[d], 1);
}
// per-graph node counts (64 bins, smem histogram)
__global__ void cnt_hist(const int* __restrict__ bt) {
    __shared__ int hcnt[GG];
    int t = threadIdx.x;
    if (t < GG) hcnt[t] = 0;
    __syncthreads();
    int i = blockIdx.x * blockDim.x + t;
    if (i < NN) atomicAdd(&hcnt[bt[i]], 1);
    __syncthreads();
    if (t < GG && hcnt[t]) atomicAdd(&g_cnt[t], (float)hcnt[t]);
}

// ---------- multi-block exclusive scan of g_cnt_n -> g_rp + cursor ----------
__global__ void scan_p1() {
    __shared__ int ps[256];
    int t = threadIdx.x, i = blockIdx.x * 256 + t;
    int v = (i < NN) ? g_cnt_n[i] : 0;
    ps[t] = v;
    __syncthreads();
#pragma unroll
    for (int off = 128; off; off >>= 1) {
        if (t < off) ps[t] += ps[t + off];
        __syncthreads();
    }
    if (t == 0) g_blk[blockIdx.x] = ps[0];
}
__global__ void scan_p2() {
    __shared__ int ps[256];
    int t = threadIdx.x;
    ps[t] = (t < SCAN_NB) ? g_blk[t] : 0;
    __syncthreads();
#pragma unroll
    for (int off = 1; off < 256; off <<= 1) {
        int v = (t >= off) ? ps[t - off] : 0;
        __syncthreads();
        ps[t] += v;
        __syncthreads();
    }
    g_blk[t] = ps[t];
}
__global__ void scan_p3() {
    __shared__ int ps[256];
    int t = threadIdx.x, b = blockIdx.x, i = b * 256 + t;
    int v = (i < NN) ? g_cnt_n[i] : 0;
    ps[t] = v;
    __syncthreads();
#pragma unroll
    for (int off = 1; off < 256; off <<= 1) {
        int u = (t >= off) ? ps[t - off] : 0;
        __syncthreads();
        ps[t] += u;
        __syncthreads();
    }
    int base = b ? g_blk[b - 1] : 0;
    int excl = base + ps[t] - v;
    if (i < NN) {
        g_rp[i] = excl;
        g_cnt_n[i] = excl;
        if (i == NN - 1) g_rp[NN] = excl + v;
    }
}
__global__ void csr_scatter(const int* __restrict__ ei) {
    int e = blockIdx.x * blockDim.x + threadIdx.x;
    if (e >= ET) return;
    int s, d;
    if (e < EE) { s = ei[e]; d = ei[EE + e]; }
    else        { s = d = e - EE; }
    int pos = atomicAdd(&g_cnt_n[d], 1);
    g_col[pos] = s;
}

// ----- fused GAT aggregate + bias + ELU + residual(+BN) + BN stats -----------
#define RPW 4
__global__ __launch_bounds__(256)
void gat_agg(const float* __restrict__ b,
             const float* __restrict__ xin,
             const float* __restrict__ rscale,
             const float* __restrict__ rshift,
             float* __restrict__ y,
             const int* __restrict__ bat, int do_pool) {
    __shared__ float bsum[F], bsq[F];
    int t = threadIdx.x;
    bsum[t] = 0.f; bsq[t] = 0.f;
    __syncthreads();

    int lane = t & 31;
    int gwarp = blockIdx.x * 8 + (t >> 5);
    int hf = gwarp & 1;
    int d0 = (gwarp >> 1) * RPW;
    int c = hf * 128 + (lane << 2);
    int h = hf * 2 + (lane >> 4);

    float4 bias = *(const float4*)(b + c);
    float scv = rscale ? rscale[c] : 1.f,     shv = rshift ? rshift[c] : 0.f;
    float scy = rscale ? rscale[c + 1] : 1.f, shy = rshift ? rshift[c + 1] : 0.f;
    float scz = rscale ? rscale[c + 2] : 1.f, shz = rshift ? rshift[c + 2] : 0.f;
    float scw = rscale ? rscale[c + 3] : 1.f, shw = rshift ? rshift[c + 3] : 0.f;

    float ss[4] = {0, 0, 0, 0};
    float sq[4] = {0, 0, 0, 0};
    float pa[4] = {0, 0, 0, 0};
    int curg = -1;

#pragma unroll
    for (int rr = 0; rr < RPW; rr++) {
        int d = d0 + rr;
        if (d >= NN) break;
        float ad = g_adst[d * HH + h];
        float ax = 0.f, ay = 0.f, az = 0.f, aw = 0.f;
        float den = 0.f;
        int e0 = g_rp[d], e1 = g_rp[d + 1];
        int e = e0;
        for (; e + 4 <= e1; e += 4) {
            int s0 = g_col[e], s1 = g_col[e + 1];
            int s2 = g_col[e + 2], s3 = g_col[e + 3];
            float a0 = g_asrc[s0 * HH + h], a1 = g_asrc[s1 * HH + h];
            float a2 = g_asrc[s2 * HH + h], a3 = g_asrc[s3 * HH + h];
            uint2 u0 = *(const uint2*)(g_hh + (size_t)s0 * F + c);
            uint2 u1 = *(const uint2*)(g_hh + (size_t)s1 * F + c);
            uint2 u2 = *(const uint2*)(g_hh + (size_t)s2 * F + c);
            uint2 u3 = *(const uint2*)(g_hh + (size_t)s3 * F + c);
            float v0 = a0 + ad, v1 = a1 + ad, v2 = a2 + ad, v3 = a3 + ad;
            v0 = v0 > 0.f ? v0 : 0.2f * v0;
            v1 = v1 > 0.f ? v1 : 0.2f * v1;
            v2 = v2 > 0.f ? v2 : 0.2f * v2;
            v3 = v3 > 0.f ? v3 : 0.2f * v3;
            float x0 = __expf(v0), x1 = __expf(v1);
            float x2 = __expf(v2), x3 = __expf(v3);
            den += (x0 + x1) + (x2 + x3);
            float2 p0 = __half22float2(*(__half2*)&u0.x);
            float2 q0 = __half22float2(*(__half2*)&u0.y);
            float2 p1 = __half22float2(*(__half2*)&u1.x);
            float2 q1 = __half22float2(*(__half2*)&u1.y);
            float2 p2 = __half22float2(*(__half2*)&u2.x);
            float2 q2 = __half22float2(*(__half2*)&u2.y);
            float2 p3 = __half22float2(*(__half2*)&u3.x);
            float2 q3 = __half22float2(*(__half2*)&u3.y);
            ax += x0 * p0.x + x1 * p1.x + x2 * p2.x + x3 * p3.x;
            ay += x0 * p0.y + x1 * p1.y + x2 * p2.y + x3 * p3.y;
            az += x0 * q0.x + x1 * q1.x + x2 * q2.x + x3 * q3.x;
            aw += x0 * q0.y + x1 * q1.y + x2 * q2.y + x3 * q3.y;
        }
        for (; e < e1; e++) {
            int s = g_col[e];
            float v = g_asrc[s * HH + h] + ad;
            v = v > 0.f ? v : 0.2f * v;
            float ex = __expf(v);
            den += ex;
            uint2 u = *(const uint2*)(g_hh + (size_t)s * F + c);
            float2 f0 = __half22float2(*(__half2*)&u.x);
            float2 f1 = __half22float2(*(__half2*)&u.y);
            ax += ex * f0.x; ay += ex * f0.y;
            az += ex * f1.x; aw += ex * f1.y;
        }
        float inv = __fdividef(1.f, den);
        float4 xr = *(const float4*)(xin + (size_t)d * F + c);
        float o[4];
        o[0] = ax * inv + bias.x; o[1] = ay * inv + bias.y;
        o[2] = az * inv + bias.z; o[3] = aw * inv + bias.w;
#pragma unroll
        for (int j = 0; j < 4; j++) o[j] = o[j] > 0.f ? o[j] : expm1f(o[j]);
        o[0] += xr.x * scv + shv; o[1] += xr.y * scy + shy;
        o[2] += xr.z * scz + shz; o[3] += xr.w * scw + shw;
        if (do_pool) {
            int gb = bat[d];
            if (gb != curg) {
                if (curg >= 0)
                    red4(&g_pool[curg * F + c], pa[0], pa[1], pa[2], pa[3]);
                curg = gb;
                pa[0] = pa[1] = pa[2] = pa[3] = 0.f;
            }
#pragma unroll
            for (int j = 0; j < 4; j++) pa[j] += o[j];
        } else {
            *(float4*)(y + (size_t)d * F + c) = make_float4(o[0], o[1], o[2], o[3]);
        }
#pragma unroll
        for (int j = 0; j < 4; j++) { ss[j] += o[j]; sq[j] += o[j] * o[j]; }
    }
    if (do_pool && curg >= 0)
        red4(&g_pool[curg * F + c], pa[0], pa[1], pa[2], pa[3]);
#pragma unroll
    for (int j = 0; j < 4; j++) {
        atomicAdd(&bsum[c + j], ss[j]);
        atomicAdd(&bsq[c + j],  sq[j]);
    }
    __syncthreads();
    atomicAdd(&g_sum[t],   bsum[t]);
    atomicAdd(&g_sumsq[t], bsq[t]);
}

__global__ void bn_final(const float* __restrict__ gm, const float* __restrict__ bt,
                         float* __restrict__ sc_out, float* __restrict__ sh_out) {
    int f = threadIdx.x;
    float mu  = g_sum[f] / (float)NN;
    float var = g_sumsq[f] / (float)NN - mu * mu;
    float sc  = gm[f] * rsqrtf(var + 1e-5f);
    sc_out[f] = sc;
    sh_out[f] = bt[f] - mu * sc;
    g_sum[f] = 0.f; g_sumsq[f] = 0.f;
}

// ---------- MLP head: BN2 affine on pooled raw sums + log softmax ------------
__global__ void mlp_head(const float* __restrict__ fc1w, const float* __restrict__ fc1b,
                         const float* __restrict__ fc2w, const float* __restrict__ fc2b,
                         float* __restrict__ out) {
    __shared__ float p[F];
    __shared__ float z[CC];
    __shared__ float l[NCLS];
    __shared__ float red[2];
    int g = blockIdx.x;
    int t = threadIdx.x;   // 64
    float cnt = fmaxf(g_cnt[g], 1.f);
    float inv = 1.f / cnt;
    for (int k = t; k < F; k += 64)
        p[k] = (g_sc2[k] * g_pool[g * F + k] + g_sh2[k] * cnt) * inv;
    __syncthreads();
    float acc = fc1b[t];
    for (int k = 0; k < F; k++) acc += p[k] * fc1w[k * CC + t];
    z[t] = fmaxf(acc, 0.f);
    __syncthreads();
    if (t < NCLS) {
        float a = fc2b[t];
        for (int k = 0; k < CC; k++) a += z[k] * fc2w[k * NCLS + t];
        l[t] = a;
    }
    __syncthreads();
    if (t == 0) {
        float m = l[0];
        for (int i = 1; i < NCLS; i++) m = fmaxf(m, l[i]);
        float s = 0.f;
        for (int i = 0; i < NCLS; i++) s += expf(l[i] - m);
        red[0] = m; red[1] = logf(s);
    }
    __syncthreads();
    if (t < NCLS) out[g * NCLS + t] = l[t] - red[0] - red[1];
}

// ---------------------------------- launch ----------------------------------
extern "C" void kernel_launch(void* const* d_in, const int* in_sizes, int n_in,
                              void* d_out, int out_size) {
    const float* x    = (const float*)d_in[0];
    const int*   ei   = (const int*)  d_in[1];
    const int*   bat  = (const int*)  d_in[2];
    const float* W1   = (const float*)d_in[3];
    const float* as1  = (const float*)d_in[4];
    const float* ad1  = (const float*)d_in[5];
    const float* b1   = (const float*)d_in[6];
    const float* gm1  = (const float*)d_in[7];
    const float* be1  = (const float*)d_in[8];
    const float* W2   = (const float*)d_in[9];
    const float* as2  = (const float*)d_in[10];
    const float* ad2  = (const float*)d_in[11];
    const float* b2   = (const float*)d_in[12];
    const float* gm2  = (const float*)d_in[13];
    const float* be2  = (const float*)d_in[14];
    const float* fc1w = (const float*)d_in[15];
    const float* fc1b = (const float*)d_in[16];
    const float* fc2w = (const float*)d_in[17];
    const float* fc2b = (const float*)d_in[18];
    float* out = (float*)d_out;

    __half* phh;
    float *py1, *psc1, *psh1, *psc2, *psh2;
    cudaGetSymbolAddress((void**)&phh,  g_hh);
    cudaGetSymbolAddress((void**)&py1,  g_y1);
    cudaGetSymbolAddress((void**)&psc1, g_sc1);
    cudaGetSymbolAddress((void**)&psh1, g_sh1);
    cudaGetSymbolAddress((void**)&psc2, g_sc2);
    cudaGetSymbolAddress((void**)&psh2, g_sh2);

    // side stream + events (created once, outside graph capture)
    static cudaStream_t s2 = nullptr;
    static cudaEvent_t evFork = nullptr, evCsr = nullptr,
                       evGemm1 = nullptr, evConvB2 = nullptr;
    if (!s2) {
        cudaStreamCreateWithFlags(&s2, cudaStreamNonBlocking);
        cudaEventCreateWithFlags(&evFork,   cudaEventDisableTiming);
        cudaEventCreateWithFlags(&evCsr,    cudaEventDisableTiming);
        cudaEventCreateWithFlags(&evGemm1,  cudaEventDisableTiming);
        cudaEventCreateWithFlags(&evConvB2, cudaEventDisableTiming);
    }

    const int TPB = 256;
    const int nET = (ET + TPB - 1) / TPB;
    const int nNN = (NN + TPB - 1) / TPB;
    dim3 mmGrid((NN + 127) / 128, 2);
    const int nAGG  = (2 * NN + 8 * RPW - 1) / (8 * RPW);
    const int nZERO = (GG * F + TPB - 1) / TPB > nNN
                      ? (GG * F + TPB - 1) / TPB : nNN;

    // ---- fork: CSR build chain on side stream, GEMM path on main -----------
    cudaEventRecord(evFork, 0);
    cudaStreamWaitEvent(s2, evFork, 0);

    csr_zero<<<nZERO, TPB, 0, s2>>>();
    csr_hist<<<nET, TPB, 0, s2>>>(ei);
    cnt_hist<<<nNN, TPB, 0, s2>>>(bat);
    scan_p1<<<SCAN_NB, 256, 0, s2>>>();
    scan_p2<<<1, 256, 0, s2>>>();
    scan_p3<<<SCAN_NB, 256, 0, s2>>>();
    csr_scatter<<<nET, TPB, 0, s2>>>(ei);
    cudaEventRecord(evCsr, s2);

    // main: layer-1 GEMM (independent of CSR)
    conv_B<<<256, 256>>>(W1);
    gemm_bf16<<<mmGrid, 256>>>(x, phh, NN, NULL, NULL, as1, ad1);
    cudaEventRecord(evGemm1, 0);

    // side: conv_B(W2) after gemm1 released g_Bp, overlapping gat_agg1
    cudaStreamWaitEvent(s2, evGemm1, 0);
    conv_B<<<256, 256, 0, s2>>>(W2);
    cudaEventRecord(evConvB2, s2);

    // main: join CSR, run layer-1 aggregation
    cudaStreamWaitEvent(0, evCsr, 0);
    gat_agg<<<nAGG, 256>>>(b1, x, NULL, NULL, py1, bat, 0);
    bn_final<<<1, F>>>(gm1, be1, psc1, psh1);

    // main: join conv_B(W2), run layer 2 (pooling fused)
    cudaStreamWaitEvent(0, evConvB2, 0);
    gemm_bf16<<<mmGrid, 256>>>(py1, phh, NN, psc1, psh1, as2, ad2);
    gat_agg<<<nAGG, 256>>>(b2, py1, psc1, psh1, NULL, bat, 1);
    bn_final<<<1, F>>>(gm2, be2, psc2, psh2);

    // ---- head ----
    mlp_head<<<GG, 64>>>(fc1w, fc1b, fc2w, fc2b, out);
}

// round 12
// speedup vs baseline: 4.0824x; 1.0970x over previous
#include <cuda_runtime.h>
#include <cuda_fp16.h>
#include <math.h>
#include <stdint.h>

#define NN   50000
#define EE   400000
#define ET   (EE + NN)
#define F    256
#define HH   4
#define CC   64
#define GG   64
#define NCLS 10

// ---------------- scratch (static device globals; no allocations) -----------
__device__ __align__(16) __half g_hh[(size_t)NN * F];   // h = A' @ W, fp16
__device__ float g_y1[NN * F];
__device__ float g_asrc[NN * HH];
__device__ float g_adst[NN * HH];
__device__ float g_sum[F], g_sumsq[F];
__device__ float g_sc1[F], g_sh1[F];
__device__ float g_sc2[F], g_sh2[F];
__device__ float g_pool[GG * F];        // raw sums of layer-2 output (pre-BN2)
__device__ float g_cnt[GG];
__device__ __align__(16) __half g_Bp[512 * 256];   // fp16 W, rows duplicated in pairs
// CSR
__device__ int   g_cnt_n[NN];
__device__ int   g_rp[NN + 1];
__device__ int   g_col[ET];
#define SCAN_NB ((NN + 255) / 256)      // 196
__device__ int   g_blk[256];

// ---------------- fp16 pack helpers ------------------------------------------
__device__ __forceinline__ uint32_t pack_hi16(float a, float b) {
    __half2 h = __floats2half2_rn(a, b);
    return *(uint32_t*)&h;
}
__device__ __forceinline__ uint32_t pack_lo16(float a, float b, uint32_t hi) {
    __half2 h = *(__half2*)&hi;
    __half2 l = __floats2half2_rn(a - __half2float(h.x), b - __half2float(h.y));
    return *(uint32_t*)&l;
}
__device__ __forceinline__ void red4(float* p, float a, float b, float c, float d) {
    asm volatile("red.global.add.v4.f32 [%0], {%1,%2,%3,%4};"
                 :: "l"(p), "f"(a), "f"(b), "f"(c), "f"(d) : "memory");
}

// ---- conv_B: W[256][256] -> B'[512][256] fp16; per 32-col group g:
// rows [g*64 + i] = [g*64 + 32 + i] = fp16(W[g*32+i][n])  (pairs A_hi / A_lo) --
__global__ void conv_B(const float* __restrict__ W) {
    int k = blockIdx.x, n = threadIdx.x;
    __half h = __float2half_rn(W[k * 256 + n]);
    int g = k >> 5, i = k & 31;
    int base = g * 64 + i;
    g_Bp[(size_t)base * 256 + n]        = h;
    g_Bp[(size_t)(base + 32) * 256 + n] = h;
}

// ============ fp16 mma.sync GEMM, K'=512, inline A split, fused attn =========
#define PA 80
#define PB 272
#define ABUF (128 * PA)
#define BBUF (32 * PB)
#define STG  (ABUF + BBUF)

__device__ __forceinline__ uint32_t smem_u32(const void* p) {
    uint32_t a;
    asm("{ .reg .u64 t; cvta.to.shared.u64 t, %1; cvt.u32.u64 %0, t; }"
        : "=r"(a) : "l"(p));
    return a;
}
__device__ __forceinline__ void ldsm_x4(uint32_t* a, uint32_t addr) {
    asm volatile("ldmatrix.sync.aligned.m8n8.x4.shared.b16 {%0,%1,%2,%3}, [%4];"
                 : "=r"(a[0]), "=r"(a[1]), "=r"(a[2]), "=r"(a[3]) : "r"(addr));
}
__device__ __forceinline__ void ldsm_x2t(uint32_t* b, uint32_t addr) {
    asm volatile("ldmatrix.sync.aligned.m8n8.x2.trans.shared.b16 {%0,%1}, [%2];"
                 : "=r"(b[0]), "=r"(b[1]) : "r"(addr));
}
__device__ __forceinline__ void mma16816(float* d, const uint32_t* a,
                                         const uint32_t* b) {
    asm volatile(
        "mma.sync.aligned.m16n8k16.row.col.f32.f16.f16.f32 "
        "{%0,%1,%2,%3}, {%4,%5,%6,%7}, {%8,%9}, {%0,%1,%2,%3};"
        : "+f"(d[0]), "+f"(d[1]), "+f"(d[2]), "+f"(d[3])
        : "r"(a[0]), "r"(a[1]), "r"(a[2]), "r"(a[3]), "r"(b[0]), "r"(b[1]));
}
__device__ __forceinline__ void load_split(const float* agp32, int kbase, int sidx,
                                           const float* scale, const float* shift,
                                           bool ok, float* e, uint32_t* hp) {
    if (ok) {
#pragma unroll
        for (int i = 0; i < 4; i++) {
            float4 v = *(const float4*)(agp32 + kbase + i * 4);
            e[i * 4 + 0] = v.x; e[i * 4 + 1] = v.y;
            e[i * 4 + 2] = v.z; e[i * 4 + 3] = v.w;
        }
        if (scale) {
#pragma unroll
            for (int i = 0; i < 16; i++)
                e[i] = e[i] * scale[sidx + i] + shift[sidx + i];
        }
    } else {
#pragma unroll
        for (int i = 0; i < 16; i++) e[i] = 0.f;
    }
#pragma unroll
    for (int p = 0; p < 8; p++) hp[p] = pack_hi16(e[2 * p], e[2 * p + 1]);
}

__global__ __launch_bounds__(256)
void gemm_fp16(const float* __restrict__ A, __half* __restrict__ C, int M,
               const float* __restrict__ scale, const float* __restrict__ shift,
               const float* __restrict__ atts, const float* __restrict__ attd) {
    __shared__ __align__(16) char sm[2 * STG];
    const int t = threadIdx.x, lane = t & 31, w = t >> 5;
    const int wm = w & 1, wn = w >> 1;
    const int row0 = blockIdx.x * 128, col0 = blockIdx.y * 128;
    const uint32_t sb = smem_u32(sm);

    float acc[4][4][4];
#pragma unroll
    for (int i = 0; i < 4; i++)
#pragma unroll
        for (int j = 0; j < 4; j++)
#pragma unroll
            for (int k = 0; k < 4; k++) acc[i][j][k] = 0.f;

    const int ar = t >> 1, apart = t & 1;
    const bool a_ok = (row0 + ar) < M;
    const float* agp32 = A + (size_t)(row0 + ar) * 256 + apart * 16;
    const int br = t >> 3, bseg = t & 7;
    const __half* bgp = g_Bp + (size_t)br * 256 + col0 + bseg * 16;

    float e[16];
    uint32_t hp[8];

    // prologue: stage 0 = hi of cols 0..31
    load_split(agp32, 0, apart * 16, scale, shift, a_ok, e, hp);
    {
        char* pa = sm + ar * PA + apart * 32;
        *(uint4*)pa = *(uint4*)&hp[0];
        *(uint4*)(pa + 16) = *(uint4*)&hp[4];
        uint4 lb0 = *(const uint4*)(bgp);
        uint4 lb1 = *(const uint4*)(bgp + 8);
        char* pb = sm + ABUF + br * PB + bseg * 32;
        *(uint4*)pb = lb0; *(uint4*)(pb + 16) = lb1;
    }
    __syncthreads();

    for (int s = 0; s < 16; s++) {
        const int buf = s & 1;
        const uint32_t sba = sb + buf * STG;
        const int sn = s + 1;
        uint4 lb0, lb1;
        if (s < 15) {
            lb0 = *(const uint4*)(bgp + (size_t)(sn * 32) * 256);
            lb1 = *(const uint4*)(bgp + (size_t)(sn * 32) * 256 + 8);
            if (!(sn & 1)) {                 // next stage is fresh hi
                int kbase = (sn >> 1) * 32;
                load_split(agp32, kbase, kbase + apart * 16, scale, shift,
                           a_ok, e, hp);
            }
        }
#pragma unroll
        for (int kh = 0; kh < 2; kh++) {
            uint32_t afr[4][4], bfr[4][2];
#pragma unroll
            for (int mi = 0; mi < 4; mi++) {
                uint32_t addr = sba + (uint32_t)(wm * 64 + mi * 16 + (lane & 15)) * PA
                              + kh * 32 + (lane >> 4) * 16;
                ldsm_x4(afr[mi], addr);
            }
#pragma unroll
            for (int nf = 0; nf < 4; nf++) {
                uint32_t addr = sba + ABUF + (uint32_t)(kh * 16 + (lane & 15)) * PB
                              + (wn * 32 + nf * 8) * 2;
                ldsm_x2t(bfr[nf], addr);
            }
#pragma unroll
            for (int mi = 0; mi < 4; mi++)
#pragma unroll
                for (int nf = 0; nf < 4; nf++)
                    mma16816(acc[mi][nf], afr[mi], bfr[nf]);
        }
        if (s < 15) {
            char* base = sm + (buf ^ 1) * STG;
            char* pb = base + ABUF + br * PB + bseg * 32;
            *(uint4*)pb = lb0; *(uint4*)(pb + 16) = lb1;
            char* pa = base + ar * PA + apart * 32;
            if (!(sn & 1)) {                 // fresh hi
                *(uint4*)pa = *(uint4*)&hp[0];
                *(uint4*)(pa + 16) = *(uint4*)&hp[4];
            } else {                         // lo from kept fp32
                uint32_t lp[8];
#pragma unroll
                for (int p = 0; p < 8; p++)
                    lp[p] = pack_lo16(e[2 * p], e[2 * p + 1], hp[p]);
                *(uint4*)pa = *(uint4*)&lp[0];
                *(uint4*)(pa + 16) = *(uint4*)&lp[4];
            }
        }
        __syncthreads();
    }

    // ---- epilogue: store C (fp16), per-warp att partials -> smem, combine ---
    float* part = (float*)sm;
#pragma unroll
    for (int mi = 0; mi < 4; mi++) {
        int lr_lo = wm * 64 + mi * 16 + (lane >> 2);
        int lr_hi = lr_lo + 8;
        int r_lo = row0 + lr_lo, r_hi = row0 + lr_hi;
        float ds0 = 0.f, dd0 = 0.f, ds1 = 0.f, dd1 = 0.f;
#pragma unroll
        for (int nf = 0; nf < 4; nf++) {
            int c = col0 + wn * 32 + nf * 8 + (lane & 3) * 2;
            float v0 = acc[mi][nf][0], v1 = acc[mi][nf][1];
            float v2 = acc[mi][nf][2], v3 = acc[mi][nf][3];
            if (r_lo < M) *(__half2*)(C + (size_t)r_lo * 256 + c) = __floats2half2_rn(v0, v1);
            if (r_hi < M) *(__half2*)(C + (size_t)r_hi * 256 + c) = __floats2half2_rn(v2, v3);
            float s0 = atts[c], s1 = atts[c + 1];
            float d0 = attd[c], d1 = attd[c + 1];
            ds0 += v0 * s0 + v1 * s1; dd0 += v0 * d0 + v1 * d1;
            ds1 += v2 * s0 + v3 * s1; dd1 += v2 * d0 + v3 * d1;
        }
#pragma unroll
        for (int o = 1; o <= 2; o <<= 1) {
            ds0 += __shfl_xor_sync(0xFFFFFFFFu, ds0, o);
            dd0 += __shfl_xor_sync(0xFFFFFFFFu, dd0, o);
            ds1 += __shfl_xor_sync(0xFFFFFFFFu, ds1, o);
            dd1 += __shfl_xor_sync(0xFFFFFFFFu, dd1, o);
        }
        if ((lane & 3) == 0) {
            part[(lr_lo * 4 + wn) * 2 + 0] = ds0;
            part[(lr_lo * 4 + wn) * 2 + 1] = dd0;
            part[(lr_hi * 4 + wn) * 2 + 0] = ds1;
            part[(lr_hi * 4 + wn) * 2 + 1] = dd1;
        }
    }
    __syncthreads();
    {
        int lr = t & 127, sd = t >> 7;
        int gr = row0 + lr;
        if (gr < M) {
            float* dst = sd ? g_adst : g_asrc;
#pragma unroll
            for (int hl = 0; hl < 2; hl++) {
                float v = part[(lr * 4 + 2 * hl) * 2 + sd]
                        + part[(lr * 4 + 2 * hl + 1) * 2 + sd];
                dst[gr * HH + (col0 >> 6) + hl] = v;
            }
        }
    }
}

// ------------------------------ CSR build -----------------------------------
__global__ void csr_zero() {
    int i = blockIdx.x * blockDim.x + threadIdx.x;
    if (i < NN) g_cnt_n[i] = 0;
    if (i < F)  { g_sum[i] = 0.f; g_sumsq[i] = 0.f; }
    if (i < GG * F) g_pool[i] = 0.f;
    if (i < GG) g_cnt[i] = 0.f;
}
__global__ void csr_hist(const int* __restrict__ ei) {
    int e = blockIdx.x * blockDim.x + threadIdx.x;
    if (e >= ET) return;
    int d = (e < EE) ? ei[EE + e] : e - EE;
    atomicAdd(&g_cnt_n[d], 1);
}
__global__ void cnt_hist(const int* __restrict__ bt) {
    __shared__ int hcnt[GG];
    int t = threadIdx.x;
    if (t < GG) hcnt[t] = 0;
    __syncthreads();
    int i = blockIdx.x * blockDim.x + t;
    if (i < NN) atomicAdd(&hcnt[bt[i]], 1);
    __syncthreads();
    if (t < GG && hcnt[t]) atomicAdd(&g_cnt[t], (float)hcnt[t]);
}
__global__ void scan_p1() {
    __shared__ int ps[256];
    int t = threadIdx.x, i = blockIdx.x * 256 + t;
    int v = (i < NN) ? g_cnt_n[i] : 0;
    ps[t] = v;
    __syncthreads();
#pragma unroll
    for (int off = 128; off; off >>= 1) {
        if (t < off) ps[t] += ps[t + off];
        __syncthreads();
    }
    if (t == 0) g_blk[blockIdx.x] = ps[0];
}
__global__ void scan_p2() {
    __shared__ int ps[256];
    int t = threadIdx.x;
    ps[t] = (t < SCAN_NB) ? g_blk[t] : 0;
    __syncthreads();
#pragma unroll
    for (int off = 1; off < 256; off <<= 1) {
        int v = (t >= off) ? ps[t - off] : 0;
        __syncthreads();
        ps[t] += v;
        __syncthreads();
    }
    g_blk[t] = ps[t];
}
__global__ void scan_p3() {
    __shared__ int ps[256];
    int t = threadIdx.x, b = blockIdx.x, i = b * 256 + t;
    int v = (i < NN) ? g_cnt_n[i] : 0;
    ps[t] = v;
    __syncthreads();
#pragma unroll
    for (int off = 1; off < 256; off <<= 1) {
        int u = (t >= off) ? ps[t - off] : 0;
        __syncthreads();
        ps[t] += u;
        __syncthreads();
    }
    int base = b ? g_blk[b - 1] : 0;
    int excl = base + ps[t] - v;
    if (i < NN) {
        g_rp[i] = excl;
        g_cnt_n[i] = excl;
        if (i == NN - 1) g_rp[NN] = excl + v;
    }
}
__global__ void csr_scatter(const int* __restrict__ ei) {
    int e = blockIdx.x * blockDim.x + threadIdx.x;
    if (e >= ET) return;
    int s, d;
    if (e < EE) { s = ei[e]; d = ei[EE + e]; }
    else        { s = d = e - EE; }
    int pos = atomicAdd(&g_cnt_n[d], 1);
    g_col[pos] = s;
}

// ----- fused GAT aggregate + bias + ELU + residual(+BN) + BN stats -----------
#define RPW 4
__global__ __launch_bounds__(256)
void gat_agg(const float* __restrict__ b,
             const float* __restrict__ xin,
             const float* __restrict__ rscale,
             const float* __restrict__ rshift,
             float* __restrict__ y,
             const int* __restrict__ bat, int do_pool) {
    __shared__ float bsum[F], bsq[F];
    int t = threadIdx.x;
    bsum[t] = 0.f; bsq[t] = 0.f;
    __syncthreads();

    int lane = t & 31;
    int gwarp = blockIdx.x * 8 + (t >> 5);
    int hf = gwarp & 1;
    int d0 = (gwarp >> 1) * RPW;
    int c = hf * 128 + (lane << 2);
    int h = hf * 2 + (lane >> 4);

    float4 bias = *(const float4*)(b + c);
    float scv = rscale ? rscale[c] : 1.f,     shv = rshift ? rshift[c] : 0.f;
    float scy = rscale ? rscale[c + 1] : 1.f, shy = rshift ? rshift[c + 1] : 0.f;
    float scz = rscale ? rscale[c + 2] : 1.f, shz = rshift ? rshift[c + 2] : 0.f;
    float scw = rscale ? rscale[c + 3] : 1.f, shw = rshift ? rshift[c + 3] : 0.f;

    float ss[4] = {0, 0, 0, 0};
    float sq[4] = {0, 0, 0, 0};
    float pa[4] = {0, 0, 0, 0};
    int curg = -1;

#pragma unroll
    for (int rr = 0; rr < RPW; rr++) {
        int d = d0 + rr;
        if (d >= NN) break;
        float ad = g_adst[d * HH + h];
        float ax = 0.f, ay = 0.f, az = 0.f, aw = 0.f;
        float den = 0.f;
        int e0 = g_rp[d], e1 = g_rp[d + 1];
        int e = e0;
        for (; e + 4 <= e1; e += 4) {
            int s0 = g_col[e], s1 = g_col[e + 1];
            int s2 = g_col[e + 2], s3 = g_col[e + 3];
            float a0 = g_asrc[s0 * HH + h], a1 = g_asrc[s1 * HH + h];
            float a2 = g_asrc[s2 * HH + h], a3 = g_asrc[s3 * HH + h];
            uint2 u0 = *(const uint2*)(g_hh + (size_t)s0 * F + c);
            uint2 u1 = *(const uint2*)(g_hh + (size_t)s1 * F + c);
            uint2 u2 = *(const uint2*)(g_hh + (size_t)s2 * F + c);
            uint2 u3 = *(const uint2*)(g_hh + (size_t)s3 * F + c);
            float v0 = a0 + ad, v1 = a1 + ad, v2 = a2 + ad, v3 = a3 + ad;
            v0 = v0 > 0.f ? v0 : 0.2f * v0;
            v1 = v1 > 0.f ? v1 : 0.2f * v1;
            v2 = v2 > 0.f ? v2 : 0.2f * v2;
            v3 = v3 > 0.f ? v3 : 0.2f * v3;
            float x0 = __expf(v0), x1 = __expf(v1);
            float x2 = __expf(v2), x3 = __expf(v3);
            den += (x0 + x1) + (x2 + x3);
            float2 p0 = __half22float2(*(__half2*)&u0.x);
            float2 q0 = __half22float2(*(__half2*)&u0.y);
            float2 p1 = __half22float2(*(__half2*)&u1.x);
            float2 q1 = __half22float2(*(__half2*)&u1.y);
            float2 p2 = __half22float2(*(__half2*)&u2.x);
            float2 q2 = __half22float2(*(__half2*)&u2.y);
            float2 p3 = __half22float2(*(__half2*)&u3.x);
            float2 q3 = __half22float2(*(__half2*)&u3.y);
            ax += x0 * p0.x + x1 * p1.x + x2 * p2.x + x3 * p3.x;
            ay += x0 * p0.y + x1 * p1.y + x2 * p2.y + x3 * p3.y;
            az += x0 * q0.x + x1 * q1.x + x2 * q2.x + x3 * q3.x;
            aw += x0 * q0.y + x1 * q1.y + x2 * q2.y + x3 * q3.y;
        }
        for (; e < e1; e++) {
            int s = g_col[e];
            float v = g_asrc[s * HH + h] + ad;
            v = v > 0.f ? v : 0.2f * v;
            float ex = __expf(v);
            den += ex;
            uint2 u = *(const uint2*)(g_hh + (size_t)s * F + c);
            float2 f0 = __half22float2(*(__half2*)&u.x);
            float2 f1 = __half22float2(*(__half2*)&u.y);
            ax += ex * f0.x; ay += ex * f0.y;
            az += ex * f1.x; aw += ex * f1.y;
        }
        float inv = __fdividef(1.f, den);
        float4 xr = *(const float4*)(xin + (size_t)d * F + c);
        float o[4];
        o[0] = ax * inv + bias.x; o[1] = ay * inv + bias.y;
        o[2] = az * inv + bias.z; o[3] = aw * inv + bias.w;
#pragma unroll
        for (int j = 0; j < 4; j++) o[j] = o[j] > 0.f ? o[j] : expm1f(o[j]);
        o[0] += xr.x * scv + shv; o[1] += xr.y * scy + shy;
        o[2] += xr.z * scz + shz; o[3] += xr.w * scw + shw;
        if (do_pool) {
            int gb = bat[d];
            if (gb != curg) {
                if (curg >= 0)
                    red4(&g_pool[curg * F + c], pa[0], pa[1], pa[2], pa[3]);
                curg = gb;
                pa[0] = pa[1] = pa[2] = pa[3] = 0.f;
            }
#pragma unroll
            for (int j = 0; j < 4; j++) pa[j] += o[j];
        } else {
            *(float4*)(y + (size_t)d * F + c) = make_float4(o[0], o[1], o[2], o[3]);
        }
#pragma unroll
        for (int j = 0; j < 4; j++) { ss[j] += o[j]; sq[j] += o[j] * o[j]; }
    }
    if (do_pool && curg >= 0)
        red4(&g_pool[curg * F + c], pa[0], pa[1], pa[2], pa[3]);
#pragma unroll
    for (int j = 0; j < 4; j++) {
        atomicAdd(&bsum[c + j], ss[j]);
        atomicAdd(&bsq[c + j],  sq[j]);
    }
    __syncthreads();
    atomicAdd(&g_sum[t],   bsum[t]);
    atomicAdd(&g_sumsq[t], bsq[t]);
}

__global__ void bn_final(const float* __restrict__ gm, const float* __restrict__ bt,
                         float* __restrict__ sc_out, float* __restrict__ sh_out) {
    int f = threadIdx.x;
    float mu  = g_sum[f] / (float)NN;
    float var = g_sumsq[f] / (float)NN - mu * mu;
    float sc  = gm[f] * rsqrtf(var + 1e-5f);
    sc_out[f] = sc;
    sh_out[f] = bt[f] - mu * sc;
    g_sum[f] = 0.f; g_sumsq[f] = 0.f;
}

// ---------- MLP head: BN2 affine on pooled raw sums + log softmax ------------
__global__ void mlp_head(const float* __restrict__ fc1w, const float* __restrict__ fc1b,
                         const float* __restrict__ fc2w, const float* __restrict__ fc2b,
                         float* __restrict__ out) {
    __shared__ float p[F];
    __shared__ float z[CC];
    __shared__ float l[NCLS];
    __shared__ float red[2];
    int g = blockIdx.x;
    int t = threadIdx.x;   // 64
    float cnt = fmaxf(g_cnt[g], 1.f);
    float inv = 1.f / cnt;
    for (int k = t; k < F; k += 64)
        p[k] = (g_sc2[k] * g_pool[g * F + k] + g_sh2[k] * cnt) * inv;
    __syncthreads();
    float acc = fc1b[t];
    for (int k = 0; k < F; k++) acc += p[k] * fc1w[k * CC + t];
    z[t] = fmaxf(acc, 0.f);
    __syncthreads();
    if (t < NCLS) {
        float a = fc2b[t];
        for (int k = 0; k < CC; k++) a += z[k] * fc2w[k * NCLS + t];
        l[t] = a;
    }
    __syncthreads();
    if (t == 0) {
        float m = l[0];
        for (int i = 1; i < NCLS; i++) m = fmaxf(m, l[i]);
        float s = 0.f;
        for (int i = 0; i < NCLS; i++) s += expf(l[i] - m);
        red[0] = m; red[1] = logf(s);
    }
    __syncthreads();
    if (t < NCLS) out[g * NCLS + t] = l[t] - red[0] - red[1];
}

// ---------------------------------- launch ----------------------------------
extern "C" void kernel_launch(void* const* d_in, const int* in_sizes, int n_in,
                              void* d_out, int out_size) {
    const float* x    = (const float*)d_in[0];
    const int*   ei   = (const int*)  d_in[1];
    const int*   bat  = (const int*)  d_in[2];
    const float* W1   = (const float*)d_in[3];
    const float* as1  = (const float*)d_in[4];
    const float* ad1  = (const float*)d_in[5];
    const float* b1   = (const float*)d_in[6];
    const float* gm1  = (const float*)d_in[7];
    const float* be1  = (const float*)d_in[8];
    const float* W2   = (const float*)d_in[9];
    const float* as2  = (const float*)d_in[10];
    const float* ad2  = (const float*)d_in[11];
    const float* b2   = (const float*)d_in[12];
    const float* gm2  = (const float*)d_in[13];
    const float* be2  = (const float*)d_in[14];
    const float* fc1w = (const float*)d_in[15];
    const float* fc1b = (const float*)d_in[16];
    const float* fc2w = (const float*)d_in[17];
    const float* fc2b = (const float*)d_in[18];
    float* out = (float*)d_out;

    __half* phh;
    float *py1, *psc1, *psh1, *psc2, *psh2;
    cudaGetSymbolAddress((void**)&phh,  g_hh);
    cudaGetSymbolAddress((void**)&py1,  g_y1);
    cudaGetSymbolAddress((void**)&psc1, g_sc1);
    cudaGetSymbolAddress((void**)&psh1, g_sh1);
    cudaGetSymbolAddress((void**)&psc2, g_sc2);
    cudaGetSymbolAddress((void**)&psh2, g_sh2);

    // side stream + events (created once, outside graph capture)
    static cudaStream_t s2 = nullptr;
    static cudaEvent_t evFork = nullptr, evCsr = nullptr,
                       evGemm1 = nullptr, evConvB2 = nullptr;
    if (!s2) {
        cudaStreamCreateWithFlags(&s2, cudaStreamNonBlocking);
        cudaEventCreateWithFlags(&evFork,   cudaEventDisableTiming);
        cudaEventCreateWithFlags(&evCsr,    cudaEventDisableTiming);
        cudaEventCreateWithFlags(&evGemm1,  cudaEventDisableTiming);
        cudaEventCreateWithFlags(&evConvB2, cudaEventDisableTiming);
    }

    const int TPB = 256;
    const int nET = (ET + TPB - 1) / TPB;
    const int nNN = (NN + TPB - 1) / TPB;
    dim3 mmGrid((NN + 127) / 128, 2);
    const int nAGG  = (2 * NN + 8 * RPW - 1) / (8 * RPW);
    const int nZERO = (GG * F + TPB - 1) / TPB > nNN
                      ? (GG * F + TPB - 1) / TPB : nNN;

    // ---- fork: CSR build chain on side stream, GEMM path on main -----------
    cudaEventRecord(evFork, 0);
    cudaStreamWaitEvent(s2, evFork, 0);

    csr_zero<<<nZERO, TPB, 0, s2>>>();
    csr_hist<<<nET, TPB, 0, s2>>>(ei);
    cnt_hist<<<nNN, TPB, 0, s2>>>(bat);
    scan_p1<<<SCAN_NB, 256, 0, s2>>>();
    scan_p2<<<1, 256, 0, s2>>>();
    scan_p3<<<SCAN_NB, 256, 0, s2>>>();
    csr_scatter<<<nET, TPB, 0, s2>>>(ei);
    cudaEventRecord(evCsr, s2);

    // main: layer-1 GEMM (independent of CSR)
    conv_B<<<256, 256>>>(W1);
    gemm_fp16<<<mmGrid, 256>>>(x, phh, NN, NULL, NULL, as1, ad1);
    cudaEventRecord(evGemm1, 0);

    // side: conv_B(W2) after gemm1 released g_Bp, overlapping gat_agg1
    cudaStreamWaitEvent(s2, evGemm1, 0);
    conv_B<<<256, 256, 0, s2>>>(W2);
    cudaEventRecord(evConvB2, s2);

    // main: join CSR, run layer-1 aggregation
    cudaStreamWaitEvent(0, evCsr, 0);
    gat_agg<<<nAGG, 256>>>(b1, x, NULL, NULL, py1, bat, 0);
    bn_final<<<1, F>>>(gm1, be1, psc1, psh1);

    // main: join conv_B(W2), run layer 2 (pooling fused)
    cudaStreamWaitEvent(0, evConvB2, 0);
    gemm_fp16<<<mmGrid, 256>>>(py1, phh, NN, psc1, psh1, as2, ad2);
    gat_agg<<<nAGG, 256>>>(b2, py1, psc1, psh1, NULL, bat, 1);
    bn_final<<<1, F>>>(gm2, be2, psc2, psh2);

    // ---- head ----
    mlp_head<<<GG, 64>>>(fc1w, fc1b, fc2w, fc2b, out);
}

// round 13
// speedup vs baseline: 4.7126x; 1.1544x over previous
#include <cuda_runtime.h>
#include <cuda_fp16.h>
#include <math.h>
#include <stdint.h>

#define NN   50000
#define EE   400000
#define ET   (EE + NN)
#define F    256
#define HH   4
#define CC   64
#define GG   64
#define NCLS 10

// ---------------- scratch (static device globals; no allocations) -----------
__device__ __align__(16) __half g_hh[(size_t)NN * F];   // h = A' @ W, fp16
__device__ float g_y1[NN * F];
__device__ float g_asrc[NN * HH];
__device__ float g_adst[NN * HH];
__device__ float g_sum[F], g_sumsq[F];
__device__ float g_sc1[F], g_sh1[F];
__device__ float g_sc2[F], g_sh2[F];
__device__ float g_pool[GG * F];        // raw sums of layer-2 output (pre-BN2)
__device__ float g_cnt[GG];
__device__ __align__(16) __half g_Bp[256 * 256];   // fp16 W
// CSR
__device__ int   g_cnt_n[NN];
__device__ int   g_rp[NN + 1];
__device__ int   g_col[ET];
#define SCAN_NB ((NN + 255) / 256)      // 196
__device__ int   g_blk[256];

// ---------------- helpers -----------------------------------------------------
__device__ __forceinline__ uint32_t pack_h2(float a, float b) {
    __half2 h = __floats2half2_rn(a, b);
    return *(uint32_t*)&h;
}
__device__ __forceinline__ void red4(float* p, float a, float b, float c, float d) {
    asm volatile("red.global.add.v4.f32 [%0], {%1,%2,%3,%4};"
                 :: "l"(p), "f"(a), "f"(b), "f"(c), "f"(d) : "memory");
}

// ---- conv_B: W[256][256] fp32 -> fp16, same layout -------------------------
__global__ void conv_B(const float* __restrict__ W) {
    int k = blockIdx.x, n = threadIdx.x;
    g_Bp[(size_t)k * 256 + n] = __float2half_rn(W[k * 256 + n]);
}

// ============ fp16 mma.sync GEMM, K=256, inline convert, fused attn ==========
#define PA 80
#define PB 272
#define ABUF (128 * PA)
#define BBUF (32 * PB)
#define STG  (ABUF + BBUF)

__device__ __forceinline__ uint32_t smem_u32(const void* p) {
    uint32_t a;
    asm("{ .reg .u64 t; cvta.to.shared.u64 t, %1; cvt.u32.u64 %0, t; }"
        : "=r"(a) : "l"(p));
    return a;
}
__device__ __forceinline__ void ldsm_x4(uint32_t* a, uint32_t addr) {
    asm volatile("ldmatrix.sync.aligned.m8n8.x4.shared.b16 {%0,%1,%2,%3}, [%4];"
                 : "=r"(a[0]), "=r"(a[1]), "=r"(a[2]), "=r"(a[3]) : "r"(addr));
}
__device__ __forceinline__ void ldsm_x2t(uint32_t* b, uint32_t addr) {
    asm volatile("ldmatrix.sync.aligned.m8n8.x2.trans.shared.b16 {%0,%1}, [%2];"
                 : "=r"(b[0]), "=r"(b[1]) : "r"(addr));
}
__device__ __forceinline__ void mma16816(float* d, const uint32_t* a,
                                         const uint32_t* b) {
    asm volatile(
        "mma.sync.aligned.m16n8k16.row.col.f32.f16.f16.f32 "
        "{%0,%1,%2,%3}, {%4,%5,%6,%7}, {%8,%9}, {%0,%1,%2,%3};"
        : "+f"(d[0]), "+f"(d[1]), "+f"(d[2]), "+f"(d[3])
        : "r"(a[0]), "r"(a[1]), "r"(a[2]), "r"(a[3]), "r"(b[0]), "r"(b[1]));
}
// load 16 fp32 A elements (opt. BN apply), convert to 8 packed fp16 pairs
__device__ __forceinline__ void load_conv(const float* agp32, int kbase,
                                          const float* scale, const float* shift,
                                          bool ok, int sidx, uint32_t* hp) {
    float e[16];
    if (ok) {
#pragma unroll
        for (int i = 0; i < 4; i++) {
            float4 v = *(const float4*)(agp32 + kbase + i * 4);
            e[i * 4 + 0] = v.x; e[i * 4 + 1] = v.y;
            e[i * 4 + 2] = v.z; e[i * 4 + 3] = v.w;
        }
        if (scale) {
#pragma unroll
            for (int i = 0; i < 16; i++)
                e[i] = e[i] * scale[sidx + i] + shift[sidx + i];
        }
    } else {
#pragma unroll
        for (int i = 0; i < 16; i++) e[i] = 0.f;
    }
#pragma unroll
    for (int p = 0; p < 8; p++) hp[p] = pack_h2(e[2 * p], e[2 * p + 1]);
}

__global__ __launch_bounds__(256, 2)
void gemm_fp16(const float* __restrict__ A, __half* __restrict__ C, int M,
               const float* __restrict__ scale, const float* __restrict__ shift,
               const float* __restrict__ atts, const float* __restrict__ attd) {
    __shared__ __align__(16) char sm[2 * STG];
    const int t = threadIdx.x, lane = t & 31, w = t >> 5;
    const int wm = w & 1, wn = w >> 1;
    const int row0 = blockIdx.x * 128, col0 = blockIdx.y * 128;
    const uint32_t sb = smem_u32(sm);

    float acc[4][4][4];
#pragma unroll
    for (int i = 0; i < 4; i++)
#pragma unroll
        for (int j = 0; j < 4; j++)
#pragma unroll
            for (int k = 0; k < 4; k++) acc[i][j][k] = 0.f;

    const int ar = t >> 1, apart = t & 1;
    const bool a_ok = (row0 + ar) < M;
    const float* agp32 = A + (size_t)(row0 + ar) * 256 + apart * 16;
    const int br = t >> 3, bseg = t & 7;
    const __half* bgp = g_Bp + (size_t)br * 256 + col0 + bseg * 16;

    uint32_t hp[8];

    // prologue: stage 0 (cols 0..31)
    load_conv(agp32, 0, scale, shift, a_ok, apart * 16, hp);
    {
        char* pa = sm + ar * PA + apart * 32;
        *(uint4*)pa = *(uint4*)&hp[0];
        *(uint4*)(pa + 16) = *(uint4*)&hp[4];
        uint4 lb0 = *(const uint4*)(bgp);
        uint4 lb1 = *(const uint4*)(bgp + 8);
        char* pb = sm + ABUF + br * PB + bseg * 32;
        *(uint4*)pb = lb0; *(uint4*)(pb + 16) = lb1;
    }
    __syncthreads();

    for (int s = 0; s < 8; s++) {
        const int buf = s & 1;
        const uint32_t sba = sb + buf * STG;
        const int sn = s + 1;
        uint4 lb0, lb1;
        if (s < 7) {
            lb0 = *(const uint4*)(bgp + (size_t)(sn * 32) * 256);
            lb1 = *(const uint4*)(bgp + (size_t)(sn * 32) * 256 + 8);
            load_conv(agp32, sn * 32, scale, shift, a_ok,
                      sn * 32 + apart * 16, hp);
        }
#pragma unroll
        for (int kh = 0; kh < 2; kh++) {
            uint32_t afr[4][4], bfr[4][2];
#pragma unroll
            for (int mi = 0; mi < 4; mi++) {
                uint32_t addr = sba + (uint32_t)(wm * 64 + mi * 16 + (lane & 15)) * PA
                              + kh * 32 + (lane >> 4) * 16;
                ldsm_x4(afr[mi], addr);
            }
#pragma unroll
            for (int nf = 0; nf < 4; nf++) {
                uint32_t addr = sba + ABUF + (uint32_t)(kh * 16 + (lane & 15)) * PB
                              + (wn * 32 + nf * 8) * 2;
                ldsm_x2t(bfr[nf], addr);
            }
#pragma unroll
            for (int mi = 0; mi < 4; mi++)
#pragma unroll
                for (int nf = 0; nf < 4; nf++)
                    mma16816(acc[mi][nf], afr[mi], bfr[nf]);
        }
        if (s < 7) {
            char* base = sm + (buf ^ 1) * STG;
            char* pb = base + ABUF + br * PB + bseg * 32;
            *(uint4*)pb = lb0; *(uint4*)(pb + 16) = lb1;
            char* pa = base + ar * PA + apart * 32;
            *(uint4*)pa = *(uint4*)&hp[0];
            *(uint4*)(pa + 16) = *(uint4*)&hp[4];
        }
        __syncthreads();
    }

    // ---- epilogue: store C (fp16), per-warp att partials -> smem, combine ---
    float* part = (float*)sm;
#pragma unroll
    for (int mi = 0; mi < 4; mi++) {
        int lr_lo = wm * 64 + mi * 16 + (lane >> 2);
        int lr_hi = lr_lo + 8;
        int r_lo = row0 + lr_lo, r_hi = row0 + lr_hi;
        float ds0 = 0.f, dd0 = 0.f, ds1 = 0.f, dd1 = 0.f;
#pragma unroll
        for (int nf = 0; nf < 4; nf++) {
            int c = col0 + wn * 32 + nf * 8 + (lane & 3) * 2;
            float v0 = acc[mi][nf][0], v1 = acc[mi][nf][1];
            float v2 = acc[mi][nf][2], v3 = acc[mi][nf][3];
            if (r_lo < M) *(__half2*)(C + (size_t)r_lo * 256 + c) = __floats2half2_rn(v0, v1);
            if (r_hi < M) *(__half2*)(C + (size_t)r_hi * 256 + c) = __floats2half2_rn(v2, v3);
            float s0 = atts[c], s1 = atts[c + 1];
            float d0 = attd[c], d1 = attd[c + 1];
            ds0 += v0 * s0 + v1 * s1; dd0 += v0 * d0 + v1 * d1;
            ds1 += v2 * s0 + v3 * s1; dd1 += v2 * d0 + v3 * d1;
        }
#pragma unroll
        for (int o = 1; o <= 2; o <<= 1) {
            ds0 += __shfl_xor_sync(0xFFFFFFFFu, ds0, o);
            dd0 += __shfl_xor_sync(0xFFFFFFFFu, dd0, o);
            ds1 += __shfl_xor_sync(0xFFFFFFFFu, ds1, o);
            dd1 += __shfl_xor_sync(0xFFFFFFFFu, dd1, o);
        }
        if ((lane & 3) == 0) {
            part[(lr_lo * 4 + wn) * 2 + 0] = ds0;
            part[(lr_lo * 4 + wn) * 2 + 1] = dd0;
            part[(lr_hi * 4 + wn) * 2 + 0] = ds1;
            part[(lr_hi * 4 + wn) * 2 + 1] = dd1;
        }
    }
    __syncthreads();
    {
        int lr = t & 127, sd = t >> 7;
        int gr = row0 + lr;
        if (gr < M) {
            float* dst = sd ? g_adst : g_asrc;
#pragma unroll
            for (int hl = 0; hl < 2; hl++) {
                float v = part[(lr * 4 + 2 * hl) * 2 + sd]
                        + part[(lr * 4 + 2 * hl + 1) * 2 + sd];
                dst[gr * HH + (col0 >> 6) + hl] = v;
            }
        }
    }
}

// ------------------------------ CSR build -----------------------------------
__global__ void csr_zero() {
    int i = blockIdx.x * blockDim.x + threadIdx.x;
    if (i < NN) g_cnt_n[i] = 0;
    if (i < F)  { g_sum[i] = 0.f; g_sumsq[i] = 0.f; }
    if (i < GG * F) g_pool[i] = 0.f;
    if (i < GG) g_cnt[i] = 0.f;
}
__global__ void csr_hist(const int* __restrict__ ei) {
    int e = blockIdx.x * blockDim.x + threadIdx.x;
    if (e >= ET) return;
    int d = (e < EE) ? ei[EE + e] : e - EE;
    atomicAdd(&g_cnt_n[d], 1);
}
__global__ void cnt_hist(const int* __restrict__ bt) {
    __shared__ int hcnt[GG];
    int t = threadIdx.x;
    if (t < GG) hcnt[t] = 0;
    __syncthreads();
    int i = blockIdx.x * blockDim.x + t;
    if (i < NN) atomicAdd(&hcnt[bt[i]], 1);
    __syncthreads();
    if (t < GG && hcnt[t]) atomicAdd(&g_cnt[t], (float)hcnt[t]);
}
__global__ void scan_p1() {
    __shared__ int ps[256];
    int t = threadIdx.x, i = blockIdx.x * 256 + t;
    int v = (i < NN) ? g_cnt_n[i] : 0;
    ps[t] = v;
    __syncthreads();
#pragma unroll
    for (int off = 128; off; off >>= 1) {
        if (t < off) ps[t] += ps[t + off];
        __syncthreads();
    }
    if (t == 0) g_blk[blockIdx.x] = ps[0];
}
__global__ void scan_p2() {
    __shared__ int ps[256];
    int t = threadIdx.x;
    ps[t] = (t < SCAN_NB) ? g_blk[t] : 0;
    __syncthreads();
#pragma unroll
    for (int off = 1; off < 256; off <<= 1) {
        int v = (t >= off) ? ps[t - off] : 0;
        __syncthreads();
        ps[t] += v;
        __syncthreads();
    }
    g_blk[t] = ps[t];
}
__global__ void scan_p3() {
    __shared__ int ps[256];
    int t = threadIdx.x, b = blockIdx.x, i = b * 256 + t;
    int v = (i < NN) ? g_cnt_n[i] : 0;
    ps[t] = v;
    __syncthreads();
#pragma unroll
    for (int off = 1; off < 256; off <<= 1) {
        int u = (t >= off) ? ps[t - off] : 0;
        __syncthreads();
        ps[t] += u;
        __syncthreads();
    }
    int base = b ? g_blk[b - 1] : 0;
    int excl = base + ps[t] - v;
    if (i < NN) {
        g_rp[i] = excl;
        g_cnt_n[i] = excl;
        if (i == NN - 1) g_rp[NN] = excl + v;
    }
}
__global__ void csr_scatter(const int* __restrict__ ei) {
    int e = blockIdx.x * blockDim.x + threadIdx.x;
    if (e >= ET) return;
    int s, d;
    if (e < EE) { s = ei[e]; d = ei[EE + e]; }
    else        { s = d = e - EE; }
    int pos = atomicAdd(&g_cnt_n[d], 1);
    g_col[pos] = s;
}

// ----- fused GAT aggregate + bias + ELU + residual(+BN) + BN stats -----------
#define RPW 4
__global__ __launch_bounds__(256)
void gat_agg(const float* __restrict__ b,
             const float* __restrict__ xin,
             const float* __restrict__ rscale,
             const float* __restrict__ rshift,
             float* __restrict__ y,
             const int* __restrict__ bat, int do_pool) {
    __shared__ float bsum[F], bsq[F];
    int t = threadIdx.x;
    bsum[t] = 0.f; bsq[t] = 0.f;
    __syncthreads();

    int lane = t & 31;
    int gwarp = blockIdx.x * 8 + (t >> 5);
    int hf = gwarp & 1;
    int d0 = (gwarp >> 1) * RPW;
    int c = hf * 128 + (lane << 2);
    int h = hf * 2 + (lane >> 4);

    float4 bias = *(const float4*)(b + c);
    float scv = rscale ? rscale[c] : 1.f,     shv = rshift ? rshift[c] : 0.f;
    float scy = rscale ? rscale[c + 1] : 1.f, shy = rshift ? rshift[c + 1] : 0.f;
    float scz = rscale ? rscale[c + 2] : 1.f, shz = rshift ? rshift[c + 2] : 0.f;
    float scw = rscale ? rscale[c + 3] : 1.f, shw = rshift ? rshift[c + 3] : 0.f;

    float ss[4] = {0, 0, 0, 0};
    float sq[4] = {0, 0, 0, 0};
    float pa[4] = {0, 0, 0, 0};
    int curg = -1;

#pragma unroll
    for (int rr = 0; rr < RPW; rr++) {
        int d = d0 + rr;
        if (d >= NN) break;
        float ad = g_adst[d * HH + h];
        float ax = 0.f, ay = 0.f, az = 0.f, aw = 0.f;
        float den = 0.f;
        int e0 = g_rp[d], e1 = g_rp[d + 1];
        int e = e0;
        for (; e + 4 <= e1; e += 4) {
            int s0 = g_col[e], s1 = g_col[e + 1];
            int s2 = g_col[e + 2], s3 = g_col[e + 3];
            float a0 = g_asrc[s0 * HH + h], a1 = g_asrc[s1 * HH + h];
            float a2 = g_asrc[s2 * HH + h], a3 = g_asrc[s3 * HH + h];
            uint2 u0 = *(const uint2*)(g_hh + (size_t)s0 * F + c);
            uint2 u1 = *(const uint2*)(g_hh + (size_t)s1 * F + c);
            uint2 u2 = *(const uint2*)(g_hh + (size_t)s2 * F + c);
            uint2 u3 = *(const uint2*)(g_hh + (size_t)s3 * F + c);
            float v0 = a0 + ad, v1 = a1 + ad, v2 = a2 + ad, v3 = a3 + ad;
            v0 = v0 > 0.f ? v0 : 0.2f * v0;
            v1 = v1 > 0.f ? v1 : 0.2f * v1;
            v2 = v2 > 0.f ? v2 : 0.2f * v2;
            v3 = v3 > 0.f ? v3 : 0.2f * v3;
            float x0 = __expf(v0), x1 = __expf(v1);
            float x2 = __expf(v2), x3 = __expf(v3);
            den += (x0 + x1) + (x2 + x3);
            float2 p0 = __half22float2(*(__half2*)&u0.x);
            float2 q0 = __half22float2(*(__half2*)&u0.y);
            float2 p1 = __half22float2(*(__half2*)&u1.x);
            float2 q1 = __half22float2(*(__half2*)&u1.y);
            float2 p2 = __half22float2(*(__half2*)&u2.x);
            float2 q2 = __half22float2(*(__half2*)&u2.y);
            float2 p3 = __half22float2(*(__half2*)&u3.x);
            float2 q3 = __half22float2(*(__half2*)&u3.y);
            ax += x0 * p0.x + x1 * p1.x + x2 * p2.x + x3 * p3.x;
            ay += x0 * p0.y + x1 * p1.y + x2 * p2.y + x3 * p3.y;
            az += x0 * q0.x + x1 * q1.x + x2 * q2.x + x3 * q3.x;
            aw += x0 * q0.y + x1 * q1.y + x2 * q2.y + x3 * q3.y;
        }
        for (; e < e1; e++) {
            int s = g_col[e];
            float v = g_asrc[s * HH + h] + ad;
            v = v > 0.f ? v : 0.2f * v;
            float ex = __expf(v);
            den += ex;
            uint2 u = *(const uint2*)(g_hh + (size_t)s * F + c);
            float2 f0 = __half22float2(*(__half2*)&u.x);
            float2 f1 = __half22float2(*(__half2*)&u.y);
            ax += ex * f0.x; ay += ex * f0.y;
            az += ex * f1.x; aw += ex * f1.y;
        }
        float inv = __fdividef(1.f, den);
        float4 xr = *(const float4*)(xin + (size_t)d * F + c);
        float o[4];
        o[0] = ax * inv + bias.x; o[1] = ay * inv + bias.y;
        o[2] = az * inv + bias.z; o[3] = aw * inv + bias.w;
#pragma unroll
        for (int j = 0; j < 4; j++) o[j] = o[j] > 0.f ? o[j] : expm1f(o[j]);
        o[0] += xr.x * scv + shv; o[1] += xr.y * scy + shy;
        o[2] += xr.z * scz + shz; o[3] += xr.w * scw + shw;
        if (do_pool) {
            int gb = bat[d];
            if (gb != curg) {
                if (curg >= 0)
                    red4(&g_pool[curg * F + c], pa[0], pa[1], pa[2], pa[3]);
                curg = gb;
                pa[0] = pa[1] = pa[2] = pa[3] = 0.f;
            }
#pragma unroll
            for (int j = 0; j < 4; j++) pa[j] += o[j];
        } else {
            *(float4*)(y + (size_t)d * F + c) = make_float4(o[0], o[1], o[2], o[3]);
        }
#pragma unroll
        for (int j = 0; j < 4; j++) { ss[j] += o[j]; sq[j] += o[j] * o[j]; }
    }
    if (do_pool && curg >= 0)
        red4(&g_pool[curg * F + c], pa[0], pa[1], pa[2], pa[3]);
#pragma unroll
    for (int j = 0; j < 4; j++) {
        atomicAdd(&bsum[c + j], ss[j]);
        atomicAdd(&bsq[c + j],  sq[j]);
    }
    __syncthreads();
    atomicAdd(&g_sum[t],   bsum[t]);
    atomicAdd(&g_sumsq[t], bsq[t]);
}

__global__ void bn_final(const float* __restrict__ gm, const float* __restrict__ bt,
                         float* __restrict__ sc_out, float* __restrict__ sh_out) {
    int f = threadIdx.x;
    float mu  = g_sum[f] / (float)NN;
    float var = g_sumsq[f] / (float)NN - mu * mu;
    float sc  = gm[f] * rsqrtf(var + 1e-5f);
    sc_out[f] = sc;
    sh_out[f] = bt[f] - mu * sc;
    g_sum[f] = 0.f; g_sumsq[f] = 0.f;
}

// ---------- MLP head: BN2 affine on pooled raw sums + log softmax ------------
__global__ void mlp_head(const float* __restrict__ fc1w, const float* __restrict__ fc1b,
                         const float* __restrict__ fc2w, const float* __restrict__ fc2b,
                         float* __restrict__ out) {
    __shared__ float p[F];
    __shared__ float z[CC];
    __shared__ float l[NCLS];
    __shared__ float red[2];
    int g = blockIdx.x;
    int t = threadIdx.x;   // 64
    float cnt = fmaxf(g_cnt[g], 1.f);
    float inv = 1.f / cnt;
    for (int k = t; k < F; k += 64)
        p[k] = (g_sc2[k] * g_pool[g * F + k] + g_sh2[k] * cnt) * inv;
    __syncthreads();
    float acc = fc1b[t];
    for (int k = 0; k < F; k++) acc += p[k] * fc1w[k * CC + t];
    z[t] = fmaxf(acc, 0.f);
    __syncthreads();
    if (t < NCLS) {
        float a = fc2b[t];
        for (int k = 0; k < CC; k++) a += z[k] * fc2w[k * NCLS + t];
        l[t] = a;
    }
    __syncthreads();
    if (t == 0) {
        float m = l[0];
        for (int i = 1; i < NCLS; i++) m = fmaxf(m, l[i]);
        float s = 0.f;
        for (int i = 0; i < NCLS; i++) s += expf(l[i] - m);
        red[0] = m; red[1] = logf(s);
    }
    __syncthreads();
    if (t < NCLS) out[g * NCLS + t] = l[t] - red[0] - red[1];
}

// ---------------------------------- launch ----------------------------------
extern "C" void kernel_launch(void* const* d_in, const int* in_sizes, int n_in,
                              void* d_out, int out_size) {
    const float* x    = (const float*)d_in[0];
    const int*   ei   = (const int*)  d_in[1];
    const int*   bat  = (const int*)  d_in[2];
    const float* W1   = (const float*)d_in[3];
    const float* as1  = (const float*)d_in[4];
    const float* ad1  = (const float*)d_in[5];
    const float* b1   = (const float*)d_in[6];
    const float* gm1  = (const float*)d_in[7];
    const float* be1  = (const float*)d_in[8];
    const float* W2   = (const float*)d_in[9];
    const float* as2  = (const float*)d_in[10];
    const float* ad2  = (const float*)d_in[11];
    const float* b2   = (const float*)d_in[12];
    const float* gm2  = (const float*)d_in[13];
    const float* be2  = (const float*)d_in[14];
    const float* fc1w = (const float*)d_in[15];
    const float* fc1b = (const float*)d_in[16];
    const float* fc2w = (const float*)d_in[17];
    const float* fc2b = (const float*)d_in[18];
    float* out = (float*)d_out;

    __half* phh;
    float *py1, *psc1, *psh1, *psc2, *psh2;
    cudaGetSymbolAddress((void**)&phh,  g_hh);
    cudaGetSymbolAddress((void**)&py1,  g_y1);
    cudaGetSymbolAddress((void**)&psc1, g_sc1);
    cudaGetSymbolAddress((void**)&psh1, g_sh1);
    cudaGetSymbolAddress((void**)&psc2, g_sc2);
    cudaGetSymbolAddress((void**)&psh2, g_sh2);

    // side stream + events (created once, outside graph capture)
    static cudaStream_t s2 = nullptr;
    static cudaEvent_t evFork = nullptr, evCsr = nullptr,
                       evGemm1 = nullptr, evConvB2 = nullptr;
    if (!s2) {
        cudaStreamCreateWithFlags(&s2, cudaStreamNonBlocking);
        cudaEventCreateWithFlags(&evFork,   cudaEventDisableTiming);
        cudaEventCreateWithFlags(&evCsr,    cudaEventDisableTiming);
        cudaEventCreateWithFlags(&evGemm1,  cudaEventDisableTiming);
        cudaEventCreateWithFlags(&evConvB2, cudaEventDisableTiming);
    }

    const int TPB = 256;
    const int nET = (ET + TPB - 1) / TPB;
    const int nNN = (NN + TPB - 1) / TPB;
    dim3 mmGrid((NN + 127) / 128, 2);
    const int nAGG  = (2 * NN + 8 * RPW - 1) / (8 * RPW);
    const int nZERO = (GG * F + TPB - 1) / TPB > nNN
                      ? (GG * F + TPB - 1) / TPB : nNN;

    // ---- fork: CSR build chain on side stream, GEMM path on main -----------
    cudaEventRecord(evFork, 0);
    cudaStreamWaitEvent(s2, evFork, 0);

    csr_zero<<<nZERO, TPB, 0, s2>>>();
    csr_hist<<<nET, TPB, 0, s2>>>(ei);
    cnt_hist<<<nNN, TPB, 0, s2>>>(bat);
    scan_p1<<<SCAN_NB, 256, 0, s2>>>();
    scan_p2<<<1, 256, 0, s2>>>();
    scan_p3<<<SCAN_NB, 256, 0, s2>>>();
    csr_scatter<<<nET, TPB, 0, s2>>>(ei);
    cudaEventRecord(evCsr, s2);

    // main: layer-1 GEMM (independent of CSR)
    conv_B<<<256, 256>>>(W1);
    gemm_fp16<<<mmGrid, 256>>>(x, phh, NN, NULL, NULL, as1, ad1);
    cudaEventRecord(evGemm1, 0);

    // side: conv_B(W2) after gemm1 released g_Bp, overlapping gat_agg1
    cudaStreamWaitEvent(s2, evGemm1, 0);
    conv_B<<<256, 256, 0, s2>>>(W2);
    cudaEventRecord(evConvB2, s2);

    // main: join CSR, run layer-1 aggregation
    cudaStreamWaitEvent(0, evCsr, 0);
    gat_agg<<<nAGG, 256>>>(b1, x, NULL, NULL, py1, bat, 0);
    bn_final<<<1, F>>>(gm1, be1, psc1, psh1);

    // main: join conv_B(W2), run layer 2 (pooling fused)
    cudaStreamWaitEvent(0, evConvB2, 0);
    gemm_fp16<<<mmGrid, 256>>>(py1, phh, NN, psc1, psh1, as2, ad2);
    gat_agg<<<nAGG, 256>>>(b2, py1, psc1, psh1, NULL, bat, 1);
    bn_final<<<1, F>>>(gm2, be2, psc2, psh2);

    // ---- head ----
    mlp_head<<<GG, 64>>>(fc1w, fc1b, fc2w, fc2b, out);
}

// round 14
// speedup vs baseline: 5.0804x; 1.0780x over previous
#include <cuda_runtime.h>
#include <cuda_fp16.h>
#include <math.h>
#include <stdint.h>

#define NN   50000
#define EE   400000
#define ET   (EE + NN)
#define F    256
#define HH   4
#define CC   64
#define GG   64
#define NCLS 10

// ---------------- scratch (static device globals; no allocations) -----------
__device__ __align__(16) __half g_hh[(size_t)NN * F];    // h = A' @ W, fp16
__device__ __align__(16) __half g_y1h[(size_t)NN * F];   // layer-1 output, fp16
__device__ float g_asrc[NN * HH];
__device__ float g_adst[NN * HH];
__device__ float g_sum[F], g_sumsq[F];
__device__ float g_sc1[F], g_sh1[F];
__device__ float g_sc2[F], g_sh2[F];
__device__ float g_pool[GG * F];
__device__ float g_cnt[GG];
__device__ __align__(16) __half g_Bp[256 * 256];   // fp16 W
// CSR
__device__ int   g_cnt_n[NN];
__device__ int   g_rp[NN + 1];
__device__ int   g_col[ET];
#define SCAN_NB ((NN + 255) / 256)
__device__ int   g_blk[256];

// ---------------- helpers -----------------------------------------------------
__device__ __forceinline__ uint32_t pack_h2(float a, float b) {
    __half2 h = __floats2half2_rn(a, b);
    return *(uint32_t*)&h;
}
__device__ __forceinline__ void red4(float* p, float a, float b, float c, float d) {
    asm volatile("red.global.add.v4.f32 [%0], {%1,%2,%3,%4};"
                 :: "l"(p), "f"(a), "f"(b), "f"(c), "f"(d) : "memory");
}

// ---- conv_B: W[256][256] fp32 -> fp16 ---------------------------------------
__global__ void conv_B(const float* __restrict__ W) {
    int k = blockIdx.x, n = threadIdx.x;
    g_Bp[(size_t)k * 256 + n] = __float2half_rn(W[k * 256 + n]);
}

// ============ fp16 mma.sync GEMM, K=256, inline convert, fused attn ==========
#define PA 80
#define PB 272
#define ABUF (128 * PA)
#define BBUF (32 * PB)
#define STG  (ABUF + BBUF)

__device__ __forceinline__ uint32_t smem_u32(const void* p) {
    uint32_t a;
    asm("{ .reg .u64 t; cvta.to.shared.u64 t, %1; cvt.u32.u64 %0, t; }"
        : "=r"(a) : "l"(p));
    return a;
}
__device__ __forceinline__ void ldsm_x4(uint32_t* a, uint32_t addr) {
    asm volatile("ldmatrix.sync.aligned.m8n8.x4.shared.b16 {%0,%1,%2,%3}, [%4];"
                 : "=r"(a[0]), "=r"(a[1]), "=r"(a[2]), "=r"(a[3]) : "r"(addr));
}
__device__ __forceinline__ void ldsm_x2t(uint32_t* b, uint32_t addr) {
    asm volatile("ldmatrix.sync.aligned.m8n8.x2.trans.shared.b16 {%0,%1}, [%2];"
                 : "=r"(b[0]), "=r"(b[1]) : "r"(addr));
}
__device__ __forceinline__ void mma16816(float* d, const uint32_t* a,
                                         const uint32_t* b) {
    asm volatile(
        "mma.sync.aligned.m16n8k16.row.col.f32.f16.f16.f32 "
        "{%0,%1,%2,%3}, {%4,%5,%6,%7}, {%8,%9}, {%0,%1,%2,%3};"
        : "+f"(d[0]), "+f"(d[1]), "+f"(d[2]), "+f"(d[3])
        : "r"(a[0]), "r"(a[1]), "r"(a[2]), "r"(a[3]), "r"(b[0]), "r"(b[1]));
}
// load 16 A elements (fp32 or fp16 source; opt. BN apply) -> 8 packed h2
__device__ __forceinline__ void load_conv(const float* agp32, const __half* agp16,
                                          int kbase,
                                          const float* scale, const float* shift,
                                          bool ok, int sidx, uint32_t* hp) {
    float e[16];
    if (ok) {
        if (agp16) {
            uint4 v0 = *(const uint4*)(agp16 + kbase);
            uint4 v1 = *(const uint4*)(agp16 + kbase + 8);
            uint32_t u[4] = {v0.x, v0.y, v0.z, v0.w};
            uint32_t w[4] = {v1.x, v1.y, v1.z, v1.w};
#pragma unroll
            for (int i = 0; i < 4; i++) {
                float2 f = __half22float2(*(__half2*)&u[i]);
                e[i * 2 + 0] = f.x; e[i * 2 + 1] = f.y;
                float2 g = __half22float2(*(__half2*)&w[i]);
                e[8 + i * 2 + 0] = g.x; e[8 + i * 2 + 1] = g.y;
            }
        } else {
#pragma unroll
            for (int i = 0; i < 4; i++) {
                float4 v = *(const float4*)(agp32 + kbase + i * 4);
                e[i * 4 + 0] = v.x; e[i * 4 + 1] = v.y;
                e[i * 4 + 2] = v.z; e[i * 4 + 3] = v.w;
            }
        }
        if (scale) {
#pragma unroll
            for (int i = 0; i < 16; i++)
                e[i] = e[i] * scale[sidx + i] + shift[sidx + i];
        }
    } else {
#pragma unroll
        for (int i = 0; i < 16; i++) e[i] = 0.f;
    }
#pragma unroll
    for (int p = 0; p < 8; p++) hp[p] = pack_h2(e[2 * p], e[2 * p + 1]);
}

__global__ __launch_bounds__(256, 2)
void gemm_fp16(const float* __restrict__ A, const __half* __restrict__ A16,
               __half* __restrict__ C, int M,
               const float* __restrict__ scale, const float* __restrict__ shift,
               const float* __restrict__ atts, const float* __restrict__ attd) {
    __shared__ __align__(16) char sm[2 * STG];
    const int t = threadIdx.x, lane = t & 31, w = t >> 5;
    const int wm = w & 1, wn = w >> 1;
    const int row0 = blockIdx.x * 128, col0 = blockIdx.y * 128;
    const uint32_t sb = smem_u32(sm);

    float acc[4][4][4];
#pragma unroll
    for (int i = 0; i < 4; i++)
#pragma unroll
        for (int j = 0; j < 4; j++)
#pragma unroll
            for (int k = 0; k < 4; k++) acc[i][j][k] = 0.f;

    const int ar = t >> 1, apart = t & 1;
    const bool a_ok = (row0 + ar) < M;
    const float* agp32 = A   ? A   + (size_t)(row0 + ar) * 256 + apart * 16 : NULL;
    const __half* agp16 = A16 ? A16 + (size_t)(row0 + ar) * 256 + apart * 16 : NULL;
    const int br = t >> 3, bseg = t & 7;
    const __half* bgp = g_Bp + (size_t)br * 256 + col0 + bseg * 16;

    uint32_t hp[8];

    load_conv(agp32, agp16, 0, scale, shift, a_ok, apart * 16, hp);
    {
        char* pa = sm + ar * PA + apart * 32;
        *(uint4*)pa = *(uint4*)&hp[0];
        *(uint4*)(pa + 16) = *(uint4*)&hp[4];
        uint4 lb0 = *(const uint4*)(bgp);
        uint4 lb1 = *(const uint4*)(bgp + 8);
        char* pb = sm + ABUF + br * PB + bseg * 32;
        *(uint4*)pb = lb0; *(uint4*)(pb + 16) = lb1;
    }
    __syncthreads();

    for (int s = 0; s < 8; s++) {
        const int buf = s & 1;
        const uint32_t sba = sb + buf * STG;
        const int sn = s + 1;
        uint4 lb0, lb1;
        if (s < 7) {
            lb0 = *(const uint4*)(bgp + (size_t)(sn * 32) * 256);
            lb1 = *(const uint4*)(bgp + (size_t)(sn * 32) * 256 + 8);
            load_conv(agp32, agp16, sn * 32, scale, shift, a_ok,
                      sn * 32 + apart * 16, hp);
        }
#pragma unroll
        for (int kh = 0; kh < 2; kh++) {
            uint32_t afr[4][4], bfr[4][2];
#pragma unroll
            for (int mi = 0; mi < 4; mi++) {
                uint32_t addr = sba + (uint32_t)(wm * 64 + mi * 16 + (lane & 15)) * PA
                              + kh * 32 + (lane >> 4) * 16;
                ldsm_x4(afr[mi], addr);
            }
#pragma unroll
            for (int nf = 0; nf < 4; nf++) {
                uint32_t addr = sba + ABUF + (uint32_t)(kh * 16 + (lane & 15)) * PB
                              + (wn * 32 + nf * 8) * 2;
                ldsm_x2t(bfr[nf], addr);
            }
#pragma unroll
            for (int mi = 0; mi < 4; mi++)
#pragma unroll
                for (int nf = 0; nf < 4; nf++)
                    mma16816(acc[mi][nf], afr[mi], bfr[nf]);
        }
        if (s < 7) {
            char* base = sm + (buf ^ 1) * STG;
            char* pb = base + ABUF + br * PB + bseg * 32;
            *(uint4*)pb = lb0; *(uint4*)(pb + 16) = lb1;
            char* pa = base + ar * PA + apart * 32;
            *(uint4*)pa = *(uint4*)&hp[0];
            *(uint4*)(pa + 16) = *(uint4*)&hp[4];
        }
        __syncthreads();
    }

    // ---- epilogue: store C (fp16), per-warp att partials -> smem, combine ---
    float* part = (float*)sm;
#pragma unroll
    for (int mi = 0; mi < 4; mi++) {
        int lr_lo = wm * 64 + mi * 16 + (lane >> 2);
        int lr_hi = lr_lo + 8;
        int r_lo = row0 + lr_lo, r_hi = row0 + lr_hi;
        float ds0 = 0.f, dd0 = 0.f, ds1 = 0.f, dd1 = 0.f;
#pragma unroll
        for (int nf = 0; nf < 4; nf++) {
            int c = col0 + wn * 32 + nf * 8 + (lane & 3) * 2;
            float v0 = acc[mi][nf][0], v1 = acc[mi][nf][1];
            float v2 = acc[mi][nf][2], v3 = acc[mi][nf][3];
            if (r_lo < M) *(__half2*)(C + (size_t)r_lo * 256 + c) = __floats2half2_rn(v0, v1);
            if (r_hi < M) *(__half2*)(C + (size_t)r_hi * 256 + c) = __floats2half2_rn(v2, v3);
            float s0 = atts[c], s1 = atts[c + 1];
            float d0 = attd[c], d1 = attd[c + 1];
            ds0 += v0 * s0 + v1 * s1; dd0 += v0 * d0 + v1 * d1;
            ds1 += v2 * s0 + v3 * s1; dd1 += v2 * d0 + v3 * d1;
        }
#pragma unroll
        for (int o = 1; o <= 2; o <<= 1) {
            ds0 += __shfl_xor_sync(0xFFFFFFFFu, ds0, o);
            dd0 += __shfl_xor_sync(0xFFFFFFFFu, dd0, o);
            ds1 += __shfl_xor_sync(0xFFFFFFFFu, ds1, o);
            dd1 += __shfl_xor_sync(0xFFFFFFFFu, dd1, o);
        }
        if ((lane & 3) == 0) {
            part[(lr_lo * 4 + wn) * 2 + 0] = ds0;
            part[(lr_lo * 4 + wn) * 2 + 1] = dd0;
            part[(lr_hi * 4 + wn) * 2 + 0] = ds1;
            part[(lr_hi * 4 + wn) * 2 + 1] = dd1;
        }
    }
    __syncthreads();
    {
        int lr = t & 127, sd = t >> 7;
        int gr = row0 + lr;
        if (gr < M) {
            float* dst = sd ? g_adst : g_asrc;
#pragma unroll
            for (int hl = 0; hl < 2; hl++) {
                float v = part[(lr * 4 + 2 * hl) * 2 + sd]
                        + part[(lr * 4 + 2 * hl + 1) * 2 + sd];
                dst[gr * HH + (col0 >> 6) + hl] = v;
            }
        }
    }
}

// ------------------------------ CSR build -----------------------------------
__global__ void csr_zero() {
    int i = blockIdx.x * blockDim.x + threadIdx.x;
    if (i < NN) g_cnt_n[i] = 0;
    if (i < F)  { g_sum[i] = 0.f; g_sumsq[i] = 0.f; }
    if (i < GG * F) g_pool[i] = 0.f;
    if (i < GG) g_cnt[i] = 0.f;
}
__global__ void csr_hist(const int* __restrict__ ei) {
    int e = blockIdx.x * blockDim.x + threadIdx.x;
    if (e >= ET) return;
    int d = (e < EE) ? ei[EE + e] : e - EE;
    atomicAdd(&g_cnt_n[d], 1);
}
__global__ void cnt_hist(const int* __restrict__ bt) {
    __shared__ int hcnt[GG];
    int t = threadIdx.x;
    if (t < GG) hcnt[t] = 0;
    __syncthreads();
    int i = blockIdx.x * blockDim.x + t;
    if (i < NN) atomicAdd(&hcnt[bt[i]], 1);
    __syncthreads();
    if (t < GG && hcnt[t]) atomicAdd(&g_cnt[t], (float)hcnt[t]);
}
__global__ void scan_p1() {
    __shared__ int ps[256];
    int t = threadIdx.x, i = blockIdx.x * 256 + t;
    int v = (i < NN) ? g_cnt_n[i] : 0;
    ps[t] = v;
    __syncthreads();
#pragma unroll
    for (int off = 128; off; off >>= 1) {
        if (t < off) ps[t] += ps[t + off];
        __syncthreads();
    }
    if (t == 0) g_blk[blockIdx.x] = ps[0];
}
__global__ void scan_p2() {
    __shared__ int ps[256];
    int t = threadIdx.x;
    ps[t] = (t < SCAN_NB) ? g_blk[t] : 0;
    __syncthreads();
#pragma unroll
    for (int off = 1; off < 256; off <<= 1) {
        int v = (t >= off) ? ps[t - off] : 0;
        __syncthreads();
        ps[t] += v;
        __syncthreads();
    }
    g_blk[t] = ps[t];
}
__global__ void scan_p3() {
    __shared__ int ps[256];
    int t = threadIdx.x, b = blockIdx.x, i = b * 256 + t;
    int v = (i < NN) ? g_cnt_n[i] : 0;
    ps[t] = v;
    __syncthreads();
#pragma unroll
    for (int off = 1; off < 256; off <<= 1) {
        int u = (t >= off) ? ps[t - off] : 0;
        __syncthreads();
        ps[t] += u;
        __syncthreads();
    }
    int base = b ? g_blk[b - 1] : 0;
    int excl = base + ps[t] - v;
    if (i < NN) {
        g_rp[i] = excl;
        g_cnt_n[i] = excl;
        if (i == NN - 1) g_rp[NN] = excl + v;
    }
}
__global__ void csr_scatter(const int* __restrict__ ei) {
    int e = blockIdx.x * blockDim.x + threadIdx.x;
    if (e >= ET) return;
    int s, d;
    if (e < EE) { s = ei[e]; d = ei[EE + e]; }
    else        { s = d = e - EE; }
    int pos = atomicAdd(&g_cnt_n[d], 1);
    g_col[pos] = s;
}

// ----- fused GAT aggregate + bias + ELU + residual(+BN) + BN stats -----------
// Warp per (dst, 128-col half); edge loop 8/4/1 pipelined.
// y16: layer-1 output (fp16). do_pool: per-graph sums instead of y write.
#define RPW 4
__global__ __launch_bounds__(256)
void gat_agg(const float* __restrict__ b,
             const float* __restrict__ xin32,
             const __half* __restrict__ xin16,
             const float* __restrict__ rscale,
             const float* __restrict__ rshift,
             __half* __restrict__ y16,
             const int* __restrict__ bat, int do_pool) {
    __shared__ float bsum[F], bsq[F];
    int t = threadIdx.x;
    bsum[t] = 0.f; bsq[t] = 0.f;
    __syncthreads();

    int lane = t & 31;
    int gwarp = blockIdx.x * 8 + (t >> 5);
    int hf = gwarp & 1;
    int d0 = (gwarp >> 1) * RPW;
    int c = hf * 128 + (lane << 2);
    int h = hf * 2 + (lane >> 4);

    float4 bias = *(const float4*)(b + c);
    float scv = rscale ? rscale[c] : 1.f,     shv = rshift ? rshift[c] : 0.f;
    float scy = rscale ? rscale[c + 1] : 1.f, shy = rshift ? rshift[c + 1] : 0.f;
    float scz = rscale ? rscale[c + 2] : 1.f, shz = rshift ? rshift[c + 2] : 0.f;
    float scw = rscale ? rscale[c + 3] : 1.f, shw = rshift ? rshift[c + 3] : 0.f;

    float ss[4] = {0, 0, 0, 0};
    float sq[4] = {0, 0, 0, 0};
    float pa[4] = {0, 0, 0, 0};
    int curg = -1;

#pragma unroll
    for (int rr = 0; rr < RPW; rr++) {
        int d = d0 + rr;
        if (d >= NN) break;
        float ad = g_adst[d * HH + h];
        float ax = 0.f, ay = 0.f, az = 0.f, aw = 0.f;
        float den = 0.f;
        int e0 = g_rp[d], e1 = g_rp[d + 1];
        int e = e0;
        // 8-wide pipelined leg (MLP ~16)
        for (; e + 8 <= e1; e += 8) {
            int sid[8];
#pragma unroll
            for (int j = 0; j < 8; j++) sid[j] = g_col[e + j];
            float av[8];
            uint2 uv[8];
#pragma unroll
            for (int j = 0; j < 8; j++) av[j] = g_asrc[sid[j] * HH + h];
#pragma unroll
            for (int j = 0; j < 8; j++)
                uv[j] = *(const uint2*)(g_hh + (size_t)sid[j] * F + c);
#pragma unroll
            for (int j = 0; j < 8; j++) {
                float v = av[j] + ad;
                v = v > 0.f ? v : 0.2f * v;
                float ex = __expf(v);
                den += ex;
                float2 f0 = __half22float2(*(__half2*)&uv[j].x);
                float2 f1 = __half22float2(*(__half2*)&uv[j].y);
                ax += ex * f0.x; ay += ex * f0.y;
                az += ex * f1.x; aw += ex * f1.y;
            }
        }
        // 4-wide leg
        for (; e + 4 <= e1; e += 4) {
            int s0 = g_col[e], s1 = g_col[e + 1];
            int s2 = g_col[e + 2], s3 = g_col[e + 3];
            float a0 = g_asrc[s0 * HH + h], a1 = g_asrc[s1 * HH + h];
            float a2 = g_asrc[s2 * HH + h], a3 = g_asrc[s3 * HH + h];
            uint2 u0 = *(const uint2*)(g_hh + (size_t)s0 * F + c);
            uint2 u1 = *(const uint2*)(g_hh + (size_t)s1 * F + c);
            uint2 u2 = *(const uint2*)(g_hh + (size_t)s2 * F + c);
            uint2 u3 = *(const uint2*)(g_hh + (size_t)s3 * F + c);
            float v0 = a0 + ad, v1 = a1 + ad, v2 = a2 + ad, v3 = a3 + ad;
            v0 = v0 > 0.f ? v0 : 0.2f * v0;
            v1 = v1 > 0.f ? v1 : 0.2f * v1;
            v2 = v2 > 0.f ? v2 : 0.2f * v2;
            v3 = v3 > 0.f ? v3 : 0.2f * v3;
            float x0 = __expf(v0), x1 = __expf(v1);
            float x2 = __expf(v2), x3 = __expf(v3);
            den += (x0 + x1) + (x2 + x3);
            float2 p0 = __half22float2(*(__half2*)&u0.x);
            float2 q0 = __half22float2(*(__half2*)&u0.y);
            float2 p1 = __half22float2(*(__half2*)&u1.x);
            float2 q1 = __half22float2(*(__half2*)&u1.y);
            float2 p2 = __half22float2(*(__half2*)&u2.x);
            float2 q2 = __half22float2(*(__half2*)&u2.y);
            float2 p3 = __half22float2(*(__half2*)&u3.x);
            float2 q3 = __half22float2(*(__half2*)&u3.y);
            ax += x0 * p0.x + x1 * p1.x + x2 * p2.x + x3 * p3.x;
            ay += x0 * p0.y + x1 * p1.y + x2 * p2.y + x3 * p3.y;
            az += x0 * q0.x + x1 * q1.x + x2 * q2.x + x3 * q3.x;
            aw += x0 * q0.y + x1 * q1.y + x2 * q2.y + x3 * q3.y;
        }
        for (; e < e1; e++) {
            int s = g_col[e];
            float v = g_asrc[s * HH + h] + ad;
            v = v > 0.f ? v : 0.2f * v;
            float ex = __expf(v);
            den += ex;
            uint2 u = *(const uint2*)(g_hh + (size_t)s * F + c);
            float2 f0 = __half22float2(*(__half2*)&u.x);
            float2 f1 = __half22float2(*(__half2*)&u.y);
            ax += ex * f0.x; ay += ex * f0.y;
            az += ex * f1.x; aw += ex * f1.y;
        }
        float inv = __fdividef(1.f, den);
        float xv[4];
        if (xin16) {
            uint2 u = *(const uint2*)(xin16 + (size_t)d * F + c);
            float2 f0 = __half22float2(*(__half2*)&u.x);
            float2 f1 = __half22float2(*(__half2*)&u.y);
            xv[0] = f0.x; xv[1] = f0.y; xv[2] = f1.x; xv[3] = f1.y;
        } else {
            float4 xr = *(const float4*)(xin32 + (size_t)d * F + c);
            xv[0] = xr.x; xv[1] = xr.y; xv[2] = xr.z; xv[3] = xr.w;
        }
        float o[4];
        o[0] = ax * inv + bias.x; o[1] = ay * inv + bias.y;
        o[2] = az * inv + bias.z; o[3] = aw * inv + bias.w;
#pragma unroll
        for (int j = 0; j < 4; j++) o[j] = o[j] > 0.f ? o[j] : expm1f(o[j]);
        o[0] += xv[0] * scv + shv; o[1] += xv[1] * scy + shy;
        o[2] += xv[2] * scz + shz; o[3] += xv[3] * scw + shw;
        if (do_pool) {
            int gb = bat[d];
            if (gb != curg) {
                if (curg >= 0)
                    red4(&g_pool[curg * F + c], pa[0], pa[1], pa[2], pa[3]);
                curg = gb;
                pa[0] = pa[1] = pa[2] = pa[3] = 0.f;
            }
#pragma unroll
            for (int j = 0; j < 4; j++) pa[j] += o[j];
        } else {
            __half2 h0 = __floats2half2_rn(o[0], o[1]);
            __half2 h1 = __floats2half2_rn(o[2], o[3]);
            uint2 uo;
            uo.x = *(uint32_t*)&h0; uo.y = *(uint32_t*)&h1;
            *(uint2*)(y16 + (size_t)d * F + c) = uo;
        }
#pragma unroll
        for (int j = 0; j < 4; j++) { ss[j] += o[j]; sq[j] += o[j] * o[j]; }
    }
    if (do_pool && curg >= 0)
        red4(&g_pool[curg * F + c], pa[0], pa[1], pa[2], pa[3]);
#pragma unroll
    for (int j = 0; j < 4; j++) {
        atomicAdd(&bsum[c + j], ss[j]);
        atomicAdd(&bsq[c + j],  sq[j]);
    }
    __syncthreads();
    atomicAdd(&g_sum[t],   bsum[t]);
    atomicAdd(&g_sumsq[t], bsq[t]);
}

__global__ void bn_final(const float* __restrict__ gm, const float* __restrict__ bt,
                         float* __restrict__ sc_out, float* __restrict__ sh_out) {
    int f = threadIdx.x;
    float mu  = g_sum[f] / (float)NN;
    float var = g_sumsq[f] / (float)NN - mu * mu;
    float sc  = gm[f] * rsqrtf(var + 1e-5f);
    sc_out[f] = sc;
    sh_out[f] = bt[f] - mu * sc;
    g_sum[f] = 0.f; g_sumsq[f] = 0.f;
}

// ---------- MLP head: BN2 affine on pooled raw sums + log softmax ------------
__global__ void mlp_head(const float* __restrict__ fc1w, const float* __restrict__ fc1b,
                         const float* __restrict__ fc2w, const float* __restrict__ fc2b,
                         float* __restrict__ out) {
    __shared__ float p[F];
    __shared__ float z[CC];
    __shared__ float l[NCLS];
    __shared__ float red[2];
    int g = blockIdx.x;
    int t = threadIdx.x;
    float cnt = fmaxf(g_cnt[g], 1.f);
    float inv = 1.f / cnt;
    for (int k = t; k < F; k += 64)
        p[k] = (g_sc2[k] * g_pool[g * F + k] + g_sh2[k] * cnt) * inv;
    __syncthreads();
    float acc = fc1b[t];
    for (int k = 0; k < F; k++) acc += p[k] * fc1w[k * CC + t];
    z[t] = fmaxf(acc, 0.f);
    __syncthreads();
    if (t < NCLS) {
        float a = fc2b[t];
        for (int k = 0; k < CC; k++) a += z[k] * fc2w[k * NCLS + t];
        l[t] = a;
    }
    __syncthreads();
    if (t == 0) {
        float m = l[0];
        for (int i = 1; i < NCLS; i++) m = fmaxf(m, l[i]);
        float s = 0.f;
        for (int i = 0; i < NCLS; i++) s += expf(l[i] - m);
        red[0] = m; red[1] = logf(s);
    }
    __syncthreads();
    if (t < NCLS) out[g * NCLS + t] = l[t] - red[0] - red[1];
}

// ---------------------------------- launch ----------------------------------
extern "C" void kernel_launch(void* const* d_in, const int* in_sizes, int n_in,
                              void* d_out, int out_size) {
    const float* x    = (const float*)d_in[0];
    const int*   ei   = (const int*)  d_in[1];
    const int*   bat  = (const int*)  d_in[2];
    const float* W1   = (const float*)d_in[3];
    const float* as1  = (const float*)d_in[4];
    const float* ad1  = (const float*)d_in[5];
    const float* b1   = (const float*)d_in[6];
    const float* gm1  = (const float*)d_in[7];
    const float* be1  = (const float*)d_in[8];
    const float* W2   = (const float*)d_in[9];
    const float* as2  = (const float*)d_in[10];
    const float* ad2  = (const float*)d_in[11];
    const float* b2   = (const float*)d_in[12];
    const float* gm2  = (const float*)d_in[13];
    const float* be2  = (const float*)d_in[14];
    const float* fc1w = (const float*)d_in[15];
    const float* fc1b = (const float*)d_in[16];
    const float* fc2w = (const float*)d_in[17];
    const float* fc2b = (const float*)d_in[18];
    float* out = (float*)d_out;

    __half *phh, *py1h;
    float *psc1, *psh1, *psc2, *psh2;
    cudaGetSymbolAddress((void**)&phh,  g_hh);
    cudaGetSymbolAddress((void**)&py1h, g_y1h);
    cudaGetSymbolAddress((void**)&psc1, g_sc1);
    cudaGetSymbolAddress((void**)&psh1, g_sh1);
    cudaGetSymbolAddress((void**)&psc2, g_sc2);
    cudaGetSymbolAddress((void**)&psh2, g_sh2);

    static cudaStream_t s2 = nullptr;
    static cudaEvent_t evFork = nullptr, evCsr = nullptr,
                       evGemm1 = nullptr, evConvB2 = nullptr;
    if (!s2) {
        cudaStreamCreateWithFlags(&s2, cudaStreamNonBlocking);
        cudaEventCreateWithFlags(&evFork,   cudaEventDisableTiming);
        cudaEventCreateWithFlags(&evCsr,    cudaEventDisableTiming);
        cudaEventCreateWithFlags(&evGemm1,  cudaEventDisableTiming);
        cudaEventCreateWithFlags(&evConvB2, cudaEventDisableTiming);
    }

    const int TPB = 256;
    const int nET = (ET + TPB - 1) / TPB;
    const int nNN = (NN + TPB - 1) / TPB;
    dim3 mmGrid((NN + 127) / 128, 2);
    const int nAGG  = (2 * NN + 8 * RPW - 1) / (8 * RPW);
    const int nZERO = (GG * F + TPB - 1) / TPB > nNN
                      ? (GG * F + TPB - 1) / TPB : nNN;

    // ---- fork: CSR build chain on side stream, GEMM path on main -----------
    cudaEventRecord(evFork, 0);
    cudaStreamWaitEvent(s2, evFork, 0);

    csr_zero<<<nZERO, TPB, 0, s2>>>();
    csr_hist<<<nET, TPB, 0, s2>>>(ei);
    cnt_hist<<<nNN, TPB, 0, s2>>>(bat);
    scan_p1<<<SCAN_NB, 256, 0, s2>>>();
    scan_p2<<<1, 256, 0, s2>>>();
    scan_p3<<<SCAN_NB, 256, 0, s2>>>();
    csr_scatter<<<nET, TPB, 0, s2>>>(ei);
    cudaEventRecord(evCsr, s2);

    // main: layer-1 GEMM (independent of CSR)
    conv_B<<<256, 256>>>(W1);
    gemm_fp16<<<mmGrid, 256>>>(x, NULL, phh, NN, NULL, NULL, as1, ad1);
    cudaEventRecord(evGemm1, 0);

    // side: conv_B(W2) after gemm1 released g_Bp, overlapping gat_agg1
    cudaStreamWaitEvent(s2, evGemm1, 0);
    conv_B<<<256, 256, 0, s2>>>(W2);
    cudaEventRecord(evConvB2, s2);

    // main: join CSR, run layer-1 aggregation (writes y1 fp16)
    cudaStreamWaitEvent(0, evCsr, 0);
    gat_agg<<<nAGG, 256>>>(b1, x, NULL, NULL, NULL, py1h, bat, 0);
    bn_final<<<1, F>>>(gm1, be1, psc1, psh1);

    // main: join conv_B(W2), layer 2 (A from fp16 y1, pooling fused)
    cudaStreamWaitEvent(0, evConvB2, 0);
    gemm_fp16<<<mmGrid, 256>>>(NULL, py1h, phh, NN, psc1, psh1, as2, ad2);
    gat_agg<<<nAGG, 256>>>(b2, NULL, py1h, psc1, psh1, NULL, bat, 1);
    bn_final<<<1, F>>>(gm2, be2, psc2, psh2);

    // ---- head ----
    mlp_head<<<GG, 64>>>(fc1w, fc1b, fc2w, fc2b, out);
}